// round 8
// baseline (speedup 1.0000x reference)
#include <cuda_runtime.h>
#include <cuda_bf16.h>
#include <math.h>

// ---------------- problem constants ----------------
#define BS   8
#define SEQ  1024
#define DM   768
#define NH   4
#define DH   192
#define ROWS (BS*SEQ)          // 8192
#define D3   (3*DM)            // 2304
#define D4   (4*DM)            // 3072

#define XOUT_ELEMS   ((size_t)ROWS*DM)
#define PRES_ELEMS   ((size_t)BS*2*NH*SEQ*DH)

// ---------------- scratch (device globals) ---------------------------------
__device__ __align__(256) float g_x1 [ROWS*DM];

__device__ __align__(256) __nv_bfloat16 g_qkvh[(size_t)ROWS*D3], g_qkvl[(size_t)ROWS*D3];
__device__ __align__(256) __nv_bfloat16 g_xnh [ROWS*DM],  g_xnl [ROWS*DM];
__device__ __align__(256) __nv_bfloat16 g_atth[ROWS*DM],  g_attl[ROWS*DM];
__device__ __align__(256) __nv_bfloat16 g_xn2h[ROWS*DM],  g_xn2l[ROWS*DM];
__device__ __align__(256) __nv_bfloat16 g_hh[(size_t)ROWS*D4], g_hl[(size_t)ROWS*D4];

// transposed split weights: [N][K]
__device__ __align__(256) __nv_bfloat16 g_w1h[(size_t)D3*DM], g_w1l[(size_t)D3*DM];
__device__ __align__(256) __nv_bfloat16 g_w3h[(size_t)DM*DM], g_w3l[(size_t)DM*DM];
__device__ __align__(256) __nv_bfloat16 g_w2h[(size_t)D4*DM], g_w2l[(size_t)D4*DM];
__device__ __align__(256) __nv_bfloat16 g_w4h[(size_t)DM*D4], g_w4l[(size_t)DM*D4];

// ---------------- helpers ---------------------------------------------------
__device__ __forceinline__ void split2(float x0, float x1, unsigned &hi, unsigned &lo) {
    __nv_bfloat16 h0 = __float2bfloat16_rn(x0);
    __nv_bfloat16 h1 = __float2bfloat16_rn(x1);
    __nv_bfloat16 l0 = __float2bfloat16_rn(x0 - __bfloat162float(h0));
    __nv_bfloat16 l1 = __float2bfloat16_rn(x1 - __bfloat162float(h1));
    hi = ((unsigned)__bfloat16_as_ushort(h1) << 16) | (unsigned)__bfloat16_as_ushort(h0);
    lo = ((unsigned)__bfloat16_as_ushort(l1) << 16) | (unsigned)__bfloat16_as_ushort(l0);
}

__device__ __forceinline__ void mma_bf16(float c[4], const unsigned a[4], const unsigned b[2]) {
    asm volatile(
        "mma.sync.aligned.m16n8k16.row.col.f32.bf16.bf16.f32 "
        "{%0,%1,%2,%3}, {%4,%5,%6,%7}, {%8,%9}, {%0,%1,%2,%3};\n"
        : "+f"(c[0]), "+f"(c[1]), "+f"(c[2]), "+f"(c[3])
        : "r"(a[0]), "r"(a[1]), "r"(a[2]), "r"(a[3]), "r"(b[0]), "r"(b[1]));
}

__device__ __forceinline__ void ldsm_x4(unsigned r[4], unsigned addr) {
    asm volatile("ldmatrix.sync.aligned.m8n8.x4.shared.b16 {%0,%1,%2,%3}, [%4];"
        : "=r"(r[0]), "=r"(r[1]), "=r"(r[2]), "=r"(r[3]) : "r"(addr));
}

__device__ __forceinline__ void ldsm_x4_t(unsigned &r0, unsigned &r1, unsigned &r2, unsigned &r3, unsigned saddr) {
    asm volatile("ldmatrix.sync.aligned.m8n8.x4.trans.shared.b16 {%0,%1,%2,%3}, [%4];"
        : "=r"(r0), "=r"(r1), "=r"(r2), "=r"(r3) : "r"(saddr));
}

#define CP16(dst, src) asm volatile("cp.async.cg.shared.global [%0], [%1], 16;\n" :: "r"(dst), "l"(src))
#define CP_COMMIT() asm volatile("cp.async.commit_group;\n" ::)
#define CP_WAIT0()  asm volatile("cp.async.wait_group 0;\n" ::)
#define CP_WAIT1()  asm volatile("cp.async.wait_group 1;\n" ::)
#define CP_WAIT2()  asm volatile("cp.async.wait_group 2;\n" ::)

__device__ __forceinline__ float gelu_tanh_f(float x) {
    float x3 = x * x * x;
    float t  = tanhf(0.7978845608028654f * (x + 0.044715f * x3));
    return 0.5f * x * (1.0f + t);
}

// ---------------- weight transpose + split: W[K][N] -> Wt_hi/lo[N][K] ------
__global__ __launch_bounds__(256) void wsplit_kernel(
    const float* __restrict__ W, __nv_bfloat16* __restrict__ Th,
    __nv_bfloat16* __restrict__ Tl, int K, int N)
{
    __shared__ float t[32][33];
    int n0 = blockIdx.x * 32, k0 = blockIdx.y * 32;
    int tx = threadIdx.x & 31, ty = threadIdx.x >> 5;
    #pragma unroll
    for (int j = 0; j < 4; j++)
        t[ty + 8 * j][tx] = W[(size_t)(k0 + ty + 8 * j) * N + n0 + tx];
    __syncthreads();
    #pragma unroll
    for (int j = 0; j < 4; j++) {
        float v = t[tx][ty + 8 * j];
        __nv_bfloat16 hi = __float2bfloat16_rn(v);
        size_t o = (size_t)(n0 + ty + 8 * j) * K + k0 + tx;
        Th[o] = hi;
        Tl[o] = __float2bfloat16_rn(v - __bfloat162float(hi));
    }
}

// ---------------- LayerNorm, writes split bf16 hi/lo ------------------------
__global__ __launch_bounds__(256) void ln_kernel(
    const float* __restrict__ x, const float* __restrict__ gamma,
    const float* __restrict__ beta,
    __nv_bfloat16* __restrict__ oh, __nv_bfloat16* __restrict__ ol)
{
    int row = blockIdx.x;
    int tid = threadIdx.x;
    const float* xr = x + (size_t)row * DM;
    float v0 = xr[tid], v1 = xr[tid + 256], v2 = xr[tid + 512];
    float s  = v0 + v1 + v2;
    float sq = v0*v0 + v1*v1 + v2*v2;
    #pragma unroll
    for (int o = 16; o > 0; o >>= 1) {
        s  += __shfl_xor_sync(0xffffffffu, s,  o);
        sq += __shfl_xor_sync(0xffffffffu, sq, o);
    }
    __shared__ float ss[8], ssq[8];
    __shared__ float mu_s, rs_s;
    int w = tid >> 5, l = tid & 31;
    if (l == 0) { ss[w] = s; ssq[w] = sq; }
    __syncthreads();
    if (tid == 0) {
        float S = 0.f, SQ = 0.f;
        #pragma unroll
        for (int i = 0; i < 8; i++) { S += ss[i]; SQ += ssq[i]; }
        float mu = S * (1.0f / DM);
        float var = SQ * (1.0f / DM) - mu * mu;
        mu_s = mu;
        rs_s = rsqrtf(var + 1e-3f);
    }
    __syncthreads();
    float mu = mu_s, rs = rs_s;
    size_t ro = (size_t)row * DM;
    #pragma unroll
    for (int q = 0; q < 3; q++) {
        int c = tid + q * 256;
        float v = (q == 0 ? v0 : (q == 1 ? v1 : v2));
        float y = (v - mu) * rs * gamma[c] + beta[c];
        __nv_bfloat16 hi = __float2bfloat16_rn(y);
        oh[ro + c] = hi;
        ol[ro + c] = __float2bfloat16_rn(y - __bfloat162float(hi));
    }
}

// ---------------- split-bf16 GEMM v4: BK=16, 4-stage, single sync -----------
// A_hi/lo [M][K], B_hi/lo [N][K] bf16 K-major. Block 128x128, warp 64x32.
#define SROW4 48                     // bytes per smem row (16 bf16 + 16B pad)
#define MAT4  (128*SROW4)            // 6144 B
#define STG4  (4*MAT4)               // 24576 B per stage (Ah,Al,Bh,Bl)
#define GEMM4_SMEM (4*STG4)          // 98304 B, 2 CTA/SM

template<bool GELU, int OMODE>
__global__ __launch_bounds__(256, 2) void bgemm4_kernel(
    const __nv_bfloat16* __restrict__ Ah, const __nv_bfloat16* __restrict__ Al,
    const __nv_bfloat16* __restrict__ Bh, const __nv_bfloat16* __restrict__ Bl,
    const float* __restrict__ bias, const float* __restrict__ res,
    float* __restrict__ C, __nv_bfloat16* __restrict__ Ch, __nv_bfloat16* __restrict__ Cl,
    float* __restrict__ pres, int M, int N, int K)
{
    extern __shared__ unsigned char sm4[];
    const int tid = threadIdx.x;
    const int w = tid >> 5, l = tid & 31;
    const int wm = w & 1, wn = w >> 1;
    const int gid = l >> 2, tig = l & 3;
    const int bx = blockIdx.x, by = blockIdx.y;
    const int T = K >> 4;                       // k-tiles of 16

    const unsigned smem_base = (unsigned)__cvta_generic_to_shared(sm4);

    const __nv_bfloat16* A0 = Ah + (size_t)(by * 128) * K;
    const __nv_bfloat16* A1 = Al + (size_t)(by * 128) * K;
    const __nv_bfloat16* B0 = Bh + (size_t)(bx * 128) * K;
    const __nv_bfloat16* B1 = Bl + (size_t)(bx * 128) * K;

    const int rl = l & 7, sel = l >> 3;
    const unsigned a_off = (unsigned)((rl + 8 * (sel & 1)) * SROW4 + 16 * (sel >> 1));
    const unsigned b_off = (unsigned)((rl + 8 * (sel >> 1)) * SROW4 + 16 * (sel & 1));

    float acc[4][4][4];
    #pragma unroll
    for (int i = 0; i < 4; i++)
        #pragma unroll
        for (int j = 0; j < 4; j++)
            #pragma unroll
            for (int c = 0; c < 4; c++) acc[i][j][c] = 0.f;

    // per thread: one 16B chunk per matrix per stage (512 chunks / 2 per row)
    const int cr = tid >> 1, cc = tid & 1;
    const unsigned cdoff = (unsigned)(cr * SROW4 + cc * 16);
    auto issue = [&](int t) {
        unsigned sb = smem_base + (t & 3) * STG4;
        size_t goff = (size_t)cr * K + (t << 4) + cc * 8;
        CP16(sb + cdoff,            (const void*)(A0 + goff));
        CP16(sb + MAT4 + cdoff,     (const void*)(A1 + goff));
        CP16(sb + 2 * MAT4 + cdoff, (const void*)(B0 + goff));
        CP16(sb + 3 * MAT4 + cdoff, (const void*)(B1 + goff));
        CP_COMMIT();
    };

    issue(0); issue(1); issue(2);

    for (int t = 0; t < T; t++) {
        if (t + 2 < T)      CP_WAIT2();
        else if (t + 1 < T) CP_WAIT1();
        else                CP_WAIT0();
        __syncthreads();
        if (t + 3 < T) issue(t + 3);

        unsigned sb = smem_base + (t & 3) * STG4;
        unsigned bh[2][4], bl4[2][4];
        #pragma unroll
        for (int p = 0; p < 2; p++) {
            unsigned bd = sb + 2 * MAT4 + (unsigned)((wn * 32 + p * 16) * SROW4) + b_off;
            ldsm_x4(bh[p], bd);
            ldsm_x4(bl4[p], bd + MAT4);
        }
        #pragma unroll
        for (int am = 0; am < 4; am++) {
            unsigned ah[4], al4[4];
            unsigned ad = sb + (unsigned)((wm * 64 + am * 16) * SROW4) + a_off;
            ldsm_x4(ah, ad);
            ldsm_x4(al4, ad + MAT4);
            #pragma unroll
            for (int an = 0; an < 4; an++) {
                const int p = an >> 1, q = (an & 1) * 2;
                unsigned bfh[2] = { bh[p][q], bh[p][q + 1] };
                unsigned bfl[2] = { bl4[p][q], bl4[p][q + 1] };
                mma_bf16(acc[am][an], ah, bfh);
                mma_bf16(acc[am][an], al4, bfh);
                mma_bf16(acc[am][an], ah, bfl);
            }
        }
    }

    // ---- epilogue ----
    #pragma unroll
    for (int am = 0; am < 4; am++) {
        int r0 = by * 128 + wm * 64 + am * 16 + gid;
        int r1 = r0 + 8;
        #pragma unroll
        for (int an = 0; an < 4; an++) {
            int n0 = bx * 128 + wn * 32 + an * 8 + 2 * tig;
            float bv0 = bias[n0], bv1 = bias[n0 + 1];
            size_t o0 = (size_t)r0 * N + n0;
            size_t o1 = (size_t)r1 * N + n0;
            float v0 = acc[am][an][0] + bv0;
            float v1 = acc[am][an][1] + bv1;
            float v2 = acc[am][an][2] + bv0;
            float v3 = acc[am][an][3] + bv1;
            if (res) {
                v0 += res[o0]; v1 += res[o0 + 1];
                v2 += res[o1]; v3 += res[o1 + 1];
            }
            if (GELU) {
                v0 = gelu_tanh_f(v0); v1 = gelu_tanh_f(v1);
                v2 = gelu_tanh_f(v2); v3 = gelu_tanh_f(v3);
            }
            if (OMODE == 0) {
                *reinterpret_cast<float2*>(C + o0) = make_float2(v0, v1);
                *reinterpret_cast<float2*>(C + o1) = make_float2(v2, v3);
            } else {
                unsigned hw, lw;
                split2(v0, v1, hw, lw);
                *reinterpret_cast<unsigned*>(Ch + o0) = hw;
                *reinterpret_cast<unsigned*>(Cl + o0) = lw;
                split2(v2, v3, hw, lw);
                *reinterpret_cast<unsigned*>(Ch + o1) = hw;
                *reinterpret_cast<unsigned*>(Cl + o1) = lw;
                if (OMODE == 2 && n0 >= DM) {
                    int kvsel = (n0 >= 2 * DM) ? 1 : 0;
                    int local = n0 - DM - kvsel * DM;
                    int hh = local / DH, dd = local % DH;
                    int b0 = r0 >> 10, s0 = r0 & 1023;
                    int b1 = r1 >> 10, s1 = r1 & 1023;
                    size_t p0 = (((size_t)(b0 * 2 + kvsel) * NH + hh) * SEQ + s0) * DH + dd;
                    size_t p1 = (((size_t)(b1 * 2 + kvsel) * NH + hh) * SEQ + s1) * DH + dd;
                    *reinterpret_cast<float2*>(pres + p0) = make_float2(v0, v1);
                    *reinterpret_cast<float2*>(pres + p1) = make_float2(v2, v3);
                }
            }
        }
    }
}

// ---------------- FA2-style attention v4: pipelined K/V loads ---------------
// q-tile 128 rows/block, 8 warps x 16 rows, KV tiles of 64.
#define A3_ST 100
#define A3_QH 0
#define A3_QL 12800
#define A3_KH 25600
#define A3_KL 32000
#define A3_VH 38400
#define A3_VL 44800
#define ATT3_SMEM_BYTES (51200*4)

__global__ __launch_bounds__(256, 1) void attn_v4_kernel(
    const __nv_bfloat16* __restrict__ qkvh, const __nv_bfloat16* __restrict__ qkvl,
    __nv_bfloat16* __restrict__ atth, __nv_bfloat16* __restrict__ attl)
{
    extern __shared__ unsigned smu[];
    const int bi = (int)gridDim.x - 1 - (int)blockIdx.x;   // biggest first
    const int h  = blockIdx.y;
    const int b  = blockIdx.z;
    const int tid = threadIdx.x;
    const int w = tid >> 5, l = tid & 31;
    const int gid = l >> 2, tig = l & 3;

    const float scale = 13.856406460551018f;   // sqrt(192) (faithful bug)
    const unsigned sbase = (unsigned)__cvta_generic_to_shared(smu);

    // per-thread K/V chunk coords (1536 chunks of 16B per 64x192 tile)
    // 6 chunks/thread; r = chunk/24, cc = chunk%24
    const int kcol = DM + h * DH;

    auto issue_k = [&](int j) {
        const size_t row0 = (size_t)(b * SEQ + j * 64);
        #pragma unroll
        for (int i = 0; i < 6; i++) {
            int c = tid + (i << 8);
            int r = c / 24, cc2 = c % 24;
            unsigned doff = (unsigned)((r * A3_ST + cc2 * 4) * 4);
            size_t gk = (row0 + r) * D3 + kcol + cc2 * 8;
            CP16(sbase + A3_KH * 4 + doff, (const void*)(qkvh + gk));
            CP16(sbase + A3_KL * 4 + doff, (const void*)(qkvl + gk));
        }
        CP_COMMIT();
    };
    auto issue_v = [&](int j) {
        const size_t row0 = (size_t)(b * SEQ + j * 64);
        #pragma unroll
        for (int i = 0; i < 6; i++) {
            int c = tid + (i << 8);
            int r = c / 24, cc2 = c % 24;
            unsigned doff = (unsigned)((r * A3_ST + cc2 * 4) * 4);
            size_t gv = (row0 + r) * D3 + kcol + DM + cc2 * 8;
            CP16(sbase + A3_VH * 4 + doff, (const void*)(qkvh + gv));
            CP16(sbase + A3_VL * 4 + doff, (const void*)(qkvl + gv));
        }
        CP_COMMIT();
    };

    // ---- preload Q (group), K(0) (group), V(0) (group) ----
    {
        const size_t row0 = (size_t)(b * SEQ + bi * 128);
        const int qcol = h * DH;
        #pragma unroll
        for (int i = 0; i < 12; i++) {
            int c = tid + (i << 8);          // 3072 chunks
            int r = c / 24, cc2 = c % 24;
            unsigned doff = (unsigned)((r * A3_ST + cc2 * 4) * 4);
            size_t goff = (row0 + r) * D3 + qcol + cc2 * 8;
            CP16(sbase + A3_QH * 4 + doff, (const void*)(qkvh + goff));
            CP16(sbase + A3_QL * 4 + doff, (const void*)(qkvl + goff));
        }
        CP_COMMIT();
    }
    issue_k(0);
    issue_v(0);

    float m0 = -1e30f, m1 = -1e30f, l0 = 0.f, l1 = 0.f;
    float accO[24][4];
    #pragma unroll
    for (int i = 0; i < 24; i++)
        #pragma unroll
        for (int c = 0; c < 4; c++) accO[i][c] = 0.f;

    const int lm_rwi  = (l & 7) + ((l >> 3) & 1) * 8;
    const int lm_ncol = (l >> 4) * 8;
    const unsigned vh_base = sbase + A3_VH * 4;
    const unsigned vl_base = sbase + A3_VL * 4;

    const int qg0 = bi * 128 + w * 16 + gid;
    const int qg1 = qg0 + 8;
    const int nkv = 2 * bi + 2;

    for (int j = 0; j < nkv; j++) {
        // K(j) ready (V(j) may still be in flight)
        CP_WAIT1();
        __syncthreads();

        const unsigned* Qh = smu + A3_QH;
        const unsigned* Ql = smu + A3_QL;
        const unsigned* Kh = smu + A3_KH;
        const unsigned* Kl = smu + A3_KL;

        // ---- scores: warp computes 16 x 64 (8 n-tiles) ----
        float accS[8][4];
        #pragma unroll
        for (int i = 0; i < 8; i++)
            #pragma unroll
            for (int c = 0; c < 4; c++) accS[i][c] = 0.f;

        #pragma unroll
        for (int ks = 0; ks < 12; ks++) {
            int kp = ks * 8;
            unsigned ah[4], al[4];
            int a0 = (w * 16 + gid) * A3_ST + kp + tig;
            int a1 = a0 + 8 * A3_ST;
            ah[0] = Qh[a0]; ah[1] = Qh[a1]; ah[2] = Qh[a0 + 4]; ah[3] = Qh[a1 + 4];
            al[0] = Ql[a0]; al[1] = Ql[a1]; al[2] = Ql[a0 + 4]; al[3] = Ql[a1 + 4];
            #pragma unroll
            for (int nt = 0; nt < 8; nt++) {
                int bb = (nt * 8 + gid) * A3_ST + kp + tig;
                unsigned bh[2], bl2[2];
                bh[0]  = Kh[bb]; bh[1]  = Kh[bb + 4];
                bl2[0] = Kl[bb]; bl2[1] = Kl[bb + 4];
                mma_bf16(accS[nt], ah, bh);
                mma_bf16(accS[nt], al, bh);
                mma_bf16(accS[nt], ah, bl2);
            }
        }

        // ---- scale + causal mask + register online softmax ----
        const bool diag = (j >= 2 * bi);
        float mx0 = -1e30f, mx1 = -1e30f;
        #pragma unroll
        for (int nt = 0; nt < 8; nt++) {
            int kg = j * 64 + nt * 8 + 2 * tig;
            float v0 = accS[nt][0] * scale;
            float v1 = accS[nt][1] * scale;
            float v2 = accS[nt][2] * scale;
            float v3 = accS[nt][3] * scale;
            if (diag) {
                if (kg     > qg0) v0 = -1e30f;
                if (kg + 1 > qg0) v1 = -1e30f;
                if (kg     > qg1) v2 = -1e30f;
                if (kg + 1 > qg1) v3 = -1e30f;
            }
            accS[nt][0] = v0; accS[nt][1] = v1;
            accS[nt][2] = v2; accS[nt][3] = v3;
            mx0 = fmaxf(mx0, fmaxf(v0, v1));
            mx1 = fmaxf(mx1, fmaxf(v2, v3));
        }
        mx0 = fmaxf(mx0, __shfl_xor_sync(0xffffffffu, mx0, 1));
        mx0 = fmaxf(mx0, __shfl_xor_sync(0xffffffffu, mx0, 2));
        mx1 = fmaxf(mx1, __shfl_xor_sync(0xffffffffu, mx1, 1));
        mx1 = fmaxf(mx1, __shfl_xor_sync(0xffffffffu, mx1, 2));
        float mn0 = fmaxf(m0, mx0), mn1 = fmaxf(m1, mx1);
        float corr0 = __expf(m0 - mn0), corr1 = __expf(m1 - mn1);

        unsigned pha[4][4], pla[4][4];
        float sum0 = 0.f, sum1 = 0.f;
        #pragma unroll
        for (int nt = 0; nt < 8; nt++) {
            float p0 = __expf(accS[nt][0] - mn0);
            float p1 = __expf(accS[nt][1] - mn0);
            float p2 = __expf(accS[nt][2] - mn1);
            float p3 = __expf(accS[nt][3] - mn1);
            sum0 += p0 + p1;
            sum1 += p2 + p3;
            const int ks = nt >> 1;
            const int s0 = (nt & 1) * 2;
            split2(p0, p1, pha[ks][s0],     pla[ks][s0]);
            split2(p2, p3, pha[ks][s0 + 1], pla[ks][s0 + 1]);
        }
        sum0 += __shfl_xor_sync(0xffffffffu, sum0, 1);
        sum0 += __shfl_xor_sync(0xffffffffu, sum0, 2);
        sum1 += __shfl_xor_sync(0xffffffffu, sum1, 1);
        sum1 += __shfl_xor_sync(0xffffffffu, sum1, 2);
        l0 = l0 * corr0 + sum0;  m0 = mn0;
        l1 = l1 * corr1 + sum1;  m1 = mn1;

        // V(j) ready; all warps past scores -> K buffer free for prefetch
        CP_WAIT0();
        __syncthreads();
        if (j + 1 < nkv) issue_k(j + 1);     // lands under PV(j)

        // ---- O = O*corr + P V ----
        #pragma unroll
        for (int nt = 0; nt < 24; nt++) {
            accO[nt][0] *= corr0; accO[nt][1] *= corr0;
            accO[nt][2] *= corr1; accO[nt][3] *= corr1;
        }
        #pragma unroll
        for (int ks = 0; ks < 4; ks++) {
            unsigned rowoff = (unsigned)((ks * 16 + lm_rwi) * A3_ST) * 4u;
            #pragma unroll
            for (int g = 0; g < 12; g++) {
                unsigned coloff = (unsigned)(g * 8 + lm_ncol / 2) * 4u;
                unsigned bh0, bh1, bh2, bh3, bl0, bl1, bl2, bl3;
                ldsm_x4_t(bh0, bh1, bh2, bh3, vh_base + rowoff + coloff);
                ldsm_x4_t(bl0, bl1, bl2, bl3, vl_base + rowoff + coloff);
                unsigned bfh[2], bfl[2];
                bfh[0] = bh0; bfh[1] = bh1; bfl[0] = bl0; bfl[1] = bl1;
                mma_bf16(accO[2 * g],     pha[ks], bfh);
                mma_bf16(accO[2 * g],     pla[ks], bfh);
                mma_bf16(accO[2 * g],     pha[ks], bfl);
                bfh[0] = bh2; bfh[1] = bh3; bfl[0] = bl2; bfl[1] = bl3;
                mma_bf16(accO[2 * g + 1], pha[ks], bfh);
                mma_bf16(accO[2 * g + 1], pla[ks], bfh);
                mma_bf16(accO[2 * g + 1], pha[ks], bfl);
            }
        }

        // all warps done reading V(j) -> V buffer free for prefetch
        __syncthreads();
        if (j + 1 < nkv) issue_v(j + 1);     // lands under scores(j+1)
    }

    // ---- final normalize + split write ----
    float li0 = 1.0f / l0, li1 = 1.0f / l1;
    int row0 = b * SEQ + bi * 128 + w * 16 + gid;
    #pragma unroll
    for (int nt = 0; nt < 24; nt++) {
        int col = h * DH + nt * 8 + 2 * tig;
        size_t o0 = (size_t)row0 * DM + col;
        size_t o1 = (size_t)(row0 + 8) * DM + col;
        unsigned hw, lw;
        split2(accO[nt][0] * li0, accO[nt][1] * li0, hw, lw);
        *reinterpret_cast<unsigned*>(atth + o0) = hw;
        *reinterpret_cast<unsigned*>(attl + o0) = lw;
        split2(accO[nt][2] * li1, accO[nt][3] * li1, hw, lw);
        *reinterpret_cast<unsigned*>(atth + o1) = hw;
        *reinterpret_cast<unsigned*>(attl + o1) = lw;
    }
}

// ---------------- launch -----------------------------------------------
extern "C" void kernel_launch(void* const* d_in, const int* in_sizes, int n_in,
                              void* d_out, int out_size)
{
    const float* x   = (const float*)d_in[0];
    const float* W1  = (const float*)d_in[2];
    const float* b1  = (const float*)d_in[3];
    const float* W3  = (const float*)d_in[4];
    const float* b3  = (const float*)d_in[5];
    const float* W2  = (const float*)d_in[6];
    const float* b2  = (const float*)d_in[7];
    const float* W4  = (const float*)d_in[8];
    const float* b4  = (const float*)d_in[9];
    const float* g1  = (const float*)d_in[10];
    const float* be1 = (const float*)d_in[11];
    const float* g2  = (const float*)d_in[12];
    const float* be2 = (const float*)d_in[13];
    float* out = (float*)d_out;

    float *x1;
    cudaGetSymbolAddress((void**)&x1, g_x1);
    __nv_bfloat16 *qkvh, *qkvl, *xnh, *xnl, *atth, *attl, *xn2h, *xn2l, *hh, *hl;
    __nv_bfloat16 *w1h, *w1l, *w3h, *w3l, *w2h, *w2l, *w4h, *w4l;
    cudaGetSymbolAddress((void**)&qkvh, g_qkvh); cudaGetSymbolAddress((void**)&qkvl, g_qkvl);
    cudaGetSymbolAddress((void**)&xnh,  g_xnh);  cudaGetSymbolAddress((void**)&xnl,  g_xnl);
    cudaGetSymbolAddress((void**)&atth, g_atth); cudaGetSymbolAddress((void**)&attl, g_attl);
    cudaGetSymbolAddress((void**)&xn2h, g_xn2h); cudaGetSymbolAddress((void**)&xn2l, g_xn2l);
    cudaGetSymbolAddress((void**)&hh,   g_hh);   cudaGetSymbolAddress((void**)&hl,   g_hl);
    cudaGetSymbolAddress((void**)&w1h,  g_w1h);  cudaGetSymbolAddress((void**)&w1l,  g_w1l);
    cudaGetSymbolAddress((void**)&w3h,  g_w3h);  cudaGetSymbolAddress((void**)&w3l,  g_w3l);
    cudaGetSymbolAddress((void**)&w2h,  g_w2h);  cudaGetSymbolAddress((void**)&w2l,  g_w2l);
    cudaGetSymbolAddress((void**)&w4h,  g_w4h);  cudaGetSymbolAddress((void**)&w4l,  g_w4l);

    cudaFuncSetAttribute(attn_v4_kernel,
                         cudaFuncAttributeMaxDynamicSharedMemorySize, ATT3_SMEM_BYTES);
    cudaFuncSetAttribute(bgemm4_kernel<false,0>,
                         cudaFuncAttributeMaxDynamicSharedMemorySize, GEMM4_SMEM);
    cudaFuncSetAttribute(bgemm4_kernel<false,1>,
                         cudaFuncAttributeMaxDynamicSharedMemorySize, GEMM4_SMEM);
    cudaFuncSetAttribute(bgemm4_kernel<false,2>,
                         cudaFuncAttributeMaxDynamicSharedMemorySize, GEMM4_SMEM);
    cudaFuncSetAttribute(bgemm4_kernel<true,1>,
                         cudaFuncAttributeMaxDynamicSharedMemorySize, GEMM4_SMEM);

    float* pres = out + XOUT_ELEMS;
    bool has_present = ((size_t)out_size >= XOUT_ELEMS + PRES_ELEMS);

    // 0) weight transpose+split (constant per call)
    wsplit_kernel<<<dim3(D3/32, DM/32), 256>>>(W1, w1h, w1l, DM, D3);
    wsplit_kernel<<<dim3(DM/32, DM/32), 256>>>(W3, w3h, w3l, DM, DM);
    wsplit_kernel<<<dim3(D4/32, DM/32), 256>>>(W2, w2h, w2l, DM, D4);
    wsplit_kernel<<<dim3(DM/32, D4/32), 256>>>(W4, w4h, w4l, D4, DM);

    // 1) LN1 -> split
    ln_kernel<<<ROWS, 256>>>(x, g1, be1, xnh, xnl);

    // 2) qkv = xn @ W1 + b1 -> split qkv (+ fused present fp32 write)
    if (has_present) {
        bgemm4_kernel<false,2><<<dim3(D3/128, ROWS/128), 256, GEMM4_SMEM>>>(
            xnh, xnl, w1h, w1l, b1, nullptr, nullptr, qkvh, qkvl, pres, ROWS, D3, DM);
    } else {
        bgemm4_kernel<false,1><<<dim3(D3/128, ROWS/128), 256, GEMM4_SMEM>>>(
            xnh, xnl, w1h, w1l, b1, nullptr, nullptr, qkvh, qkvl, nullptr, ROWS, D3, DM);
    }

    // 3) attention (pipelined K/V loads)
    attn_v4_kernel<<<dim3(SEQ/128, NH, BS), 256, ATT3_SMEM_BYTES>>>(qkvh, qkvl, atth, attl);

    // 4) x1 = att @ W3 + b3 + x (float out)
    bgemm4_kernel<false,0><<<dim3(DM/128, ROWS/128), 256, GEMM4_SMEM>>>(
        atth, attl, w3h, w3l, b3, x, x1, nullptr, nullptr, nullptr, ROWS, DM, DM);

    // 5) LN2 -> split
    ln_kernel<<<ROWS, 256>>>(x1, g2, be2, xn2h, xn2l);

    // 6) h = gelu(xn2 @ W2 + b2) -> split out
    bgemm4_kernel<true,1><<<dim3(D4/128, ROWS/128), 256, GEMM4_SMEM>>>(
        xn2h, xn2l, w2h, w2l, b2, nullptr, nullptr, hh, hl, nullptr, ROWS, D4, DM);

    // 7) out = h @ W4 + b4 + x1 (float out)
    bgemm4_kernel<false,0><<<dim3(DM/128, ROWS/128), 256, GEMM4_SMEM>>>(
        hh, hl, w4h, w4l, b4, x1, out, nullptr, nullptr, nullptr, ROWS, DM, D4);
}

// round 9
// speedup vs baseline: 1.1331x; 1.1331x over previous
#include <cuda_runtime.h>
#include <cuda_bf16.h>
#include <math.h>

// ---------------- problem constants ----------------
#define BS   8
#define SEQ  1024
#define DM   768
#define NH   4
#define DH   192
#define ROWS (BS*SEQ)          // 8192
#define D3   (3*DM)            // 2304
#define D4   (4*DM)            // 3072

#define XOUT_ELEMS   ((size_t)ROWS*DM)
#define PRES_ELEMS   ((size_t)BS*2*NH*SEQ*DH)

// ---------------- scratch (device globals) ---------------------------------
__device__ __align__(256) float g_x1 [ROWS*DM];

__device__ __align__(256) __nv_bfloat16 g_qkvh[(size_t)ROWS*D3], g_qkvl[(size_t)ROWS*D3];
__device__ __align__(256) __nv_bfloat16 g_xnh [ROWS*DM],  g_xnl [ROWS*DM];
__device__ __align__(256) __nv_bfloat16 g_atth[ROWS*DM],  g_attl[ROWS*DM];
__device__ __align__(256) __nv_bfloat16 g_xn2h[ROWS*DM],  g_xn2l[ROWS*DM];
__device__ __align__(256) __nv_bfloat16 g_hh[(size_t)ROWS*D4], g_hl[(size_t)ROWS*D4];

// transposed split weights: [N][K]
__device__ __align__(256) __nv_bfloat16 g_w1h[(size_t)D3*DM], g_w1l[(size_t)D3*DM];
__device__ __align__(256) __nv_bfloat16 g_w3h[(size_t)DM*DM], g_w3l[(size_t)DM*DM];
__device__ __align__(256) __nv_bfloat16 g_w2h[(size_t)D4*DM], g_w2l[(size_t)D4*DM];
__device__ __align__(256) __nv_bfloat16 g_w4h[(size_t)DM*D4], g_w4l[(size_t)DM*D4];

// ---------------- helpers ---------------------------------------------------
__device__ __forceinline__ void split2(float x0, float x1, unsigned &hi, unsigned &lo) {
    __nv_bfloat16 h0 = __float2bfloat16_rn(x0);
    __nv_bfloat16 h1 = __float2bfloat16_rn(x1);
    __nv_bfloat16 l0 = __float2bfloat16_rn(x0 - __bfloat162float(h0));
    __nv_bfloat16 l1 = __float2bfloat16_rn(x1 - __bfloat162float(h1));
    hi = ((unsigned)__bfloat16_as_ushort(h1) << 16) | (unsigned)__bfloat16_as_ushort(h0);
    lo = ((unsigned)__bfloat16_as_ushort(l1) << 16) | (unsigned)__bfloat16_as_ushort(l0);
}

__device__ __forceinline__ void mma_bf16(float c[4], const unsigned a[4], const unsigned b[2]) {
    asm volatile(
        "mma.sync.aligned.m16n8k16.row.col.f32.bf16.bf16.f32 "
        "{%0,%1,%2,%3}, {%4,%5,%6,%7}, {%8,%9}, {%0,%1,%2,%3};\n"
        : "+f"(c[0]), "+f"(c[1]), "+f"(c[2]), "+f"(c[3])
        : "r"(a[0]), "r"(a[1]), "r"(a[2]), "r"(a[3]), "r"(b[0]), "r"(b[1]));
}

__device__ __forceinline__ void ldsm_x4(unsigned r[4], unsigned addr) {
    asm volatile("ldmatrix.sync.aligned.m8n8.x4.shared.b16 {%0,%1,%2,%3}, [%4];"
        : "=r"(r[0]), "=r"(r[1]), "=r"(r[2]), "=r"(r[3]) : "r"(addr));
}

__device__ __forceinline__ void ldsm_x4_t(unsigned &r0, unsigned &r1, unsigned &r2, unsigned &r3, unsigned saddr) {
    asm volatile("ldmatrix.sync.aligned.m8n8.x4.trans.shared.b16 {%0,%1,%2,%3}, [%4];"
        : "=r"(r0), "=r"(r1), "=r"(r2), "=r"(r3) : "r"(saddr));
}

#define CP16(dst, src) asm volatile("cp.async.cg.shared.global [%0], [%1], 16;\n" :: "r"(dst), "l"(src))
#define CP_COMMIT() asm volatile("cp.async.commit_group;\n" ::)
#define CP_WAIT0()  asm volatile("cp.async.wait_group 0;\n" ::)
#define CP_WAIT1()  asm volatile("cp.async.wait_group 1;\n" ::)

__device__ __forceinline__ float gelu_tanh_f(float x) {
    float x3 = x * x * x;
    float t  = tanhf(0.7978845608028654f * (x + 0.044715f * x3));
    return 0.5f * x * (1.0f + t);
}

// ---------------- weight transpose + split: W[K][N] -> Wt_hi/lo[N][K] ------
__global__ __launch_bounds__(256) void wsplit_kernel(
    const float* __restrict__ W, __nv_bfloat16* __restrict__ Th,
    __nv_bfloat16* __restrict__ Tl, int K, int N)
{
    __shared__ float t[32][33];
    int n0 = blockIdx.x * 32, k0 = blockIdx.y * 32;
    int tx = threadIdx.x & 31, ty = threadIdx.x >> 5;
    #pragma unroll
    for (int j = 0; j < 4; j++)
        t[ty + 8 * j][tx] = W[(size_t)(k0 + ty + 8 * j) * N + n0 + tx];
    __syncthreads();
    #pragma unroll
    for (int j = 0; j < 4; j++) {
        float v = t[tx][ty + 8 * j];
        __nv_bfloat16 hi = __float2bfloat16_rn(v);
        size_t o = (size_t)(n0 + ty + 8 * j) * K + k0 + tx;
        Th[o] = hi;
        Tl[o] = __float2bfloat16_rn(v - __bfloat162float(hi));
    }
}

// ---------------- LayerNorm, writes split bf16 hi/lo ------------------------
__global__ __launch_bounds__(256) void ln_kernel(
    const float* __restrict__ x, const float* __restrict__ gamma,
    const float* __restrict__ beta,
    __nv_bfloat16* __restrict__ oh, __nv_bfloat16* __restrict__ ol)
{
    int row = blockIdx.x;
    int tid = threadIdx.x;
    const float* xr = x + (size_t)row * DM;
    float v0 = xr[tid], v1 = xr[tid + 256], v2 = xr[tid + 512];
    float s  = v0 + v1 + v2;
    float sq = v0*v0 + v1*v1 + v2*v2;
    #pragma unroll
    for (int o = 16; o > 0; o >>= 1) {
        s  += __shfl_xor_sync(0xffffffffu, s,  o);
        sq += __shfl_xor_sync(0xffffffffu, sq, o);
    }
    __shared__ float ss[8], ssq[8];
    __shared__ float mu_s, rs_s;
    int w = tid >> 5, l = tid & 31;
    if (l == 0) { ss[w] = s; ssq[w] = sq; }
    __syncthreads();
    if (tid == 0) {
        float S = 0.f, SQ = 0.f;
        #pragma unroll
        for (int i = 0; i < 8; i++) { S += ss[i]; SQ += ssq[i]; }
        float mu = S * (1.0f / DM);
        float var = SQ * (1.0f / DM) - mu * mu;
        mu_s = mu;
        rs_s = rsqrtf(var + 1e-3f);
    }
    __syncthreads();
    float mu = mu_s, rs = rs_s;
    size_t ro = (size_t)row * DM;
    #pragma unroll
    for (int q = 0; q < 3; q++) {
        int c = tid + q * 256;
        float v = (q == 0 ? v0 : (q == 1 ? v1 : v2));
        float y = (v - mu) * rs * gamma[c] + beta[c];
        __nv_bfloat16 hi = __float2bfloat16_rn(y);
        oh[ro + c] = hi;
        ol[ro + c] = __float2bfloat16_rn(y - __bfloat162float(hi));
    }
}

// ---------------- split-bf16 GEMM v3: BK=32, 2-stage, 2 CTA/SM --------------
#define SROW3 80
#define MAT3  (128*SROW3)
#define STG3  (4*MAT3)
#define GEMM3_SMEM (2*STG3)

template<bool GELU, int OMODE>
__global__ __launch_bounds__(256, 2) void bgemm3_kernel(
    const __nv_bfloat16* __restrict__ Ah, const __nv_bfloat16* __restrict__ Al,
    const __nv_bfloat16* __restrict__ Bh, const __nv_bfloat16* __restrict__ Bl,
    const float* __restrict__ bias, const float* __restrict__ res,
    float* __restrict__ C, __nv_bfloat16* __restrict__ Ch, __nv_bfloat16* __restrict__ Cl,
    float* __restrict__ pres, int M, int N, int K)
{
    extern __shared__ unsigned char sm3[];
    const int tid = threadIdx.x;
    const int w = tid >> 5, l = tid & 31;
    const int wm = w & 1, wn = w >> 1;
    const int gid = l >> 2, tig = l & 3;
    const int bx = blockIdx.x, by = blockIdx.y;
    const int T = K >> 5;

    const unsigned smem_base = (unsigned)__cvta_generic_to_shared(sm3);

    const __nv_bfloat16* A0 = Ah + (size_t)(by * 128) * K;
    const __nv_bfloat16* A1 = Al + (size_t)(by * 128) * K;
    const __nv_bfloat16* B0 = Bh + (size_t)(bx * 128) * K;
    const __nv_bfloat16* B1 = Bl + (size_t)(bx * 128) * K;

    const int rl = l & 7, sel = l >> 3;
    const unsigned a_off = (unsigned)((rl + 8 * (sel & 1)) * SROW3 + 16 * (sel >> 1));
    const unsigned b_off = (unsigned)((rl + 8 * (sel >> 1)) * SROW3 + 16 * (sel & 1));

    float acc[4][4][4];
    #pragma unroll
    for (int i = 0; i < 4; i++)
        #pragma unroll
        for (int j = 0; j < 4; j++)
            #pragma unroll
            for (int c = 0; c < 4; c++) acc[i][j][c] = 0.f;

    auto issue = [&](int t) {
        unsigned sb = smem_base + (t & 1) * STG3;
        int k0 = t << 5;
        #pragma unroll
        for (int i = 0; i < 2; i++) {
            int chunk = tid + (i << 8);
            int r = chunk >> 2, c = chunk & 3;
            unsigned doff = (unsigned)(r * SROW3 + c * 16);
            size_t goff = (size_t)r * K + k0 + c * 8;
            CP16(sb + doff,            (const void*)(A0 + goff));
            CP16(sb + MAT3 + doff,     (const void*)(A1 + goff));
            CP16(sb + 2 * MAT3 + doff, (const void*)(B0 + goff));
            CP16(sb + 3 * MAT3 + doff, (const void*)(B1 + goff));
        }
        CP_COMMIT();
    };

    issue(0);
    if (T > 1) issue(1);

    for (int t = 0; t < T; t++) {
        if (t + 1 < T) CP_WAIT1(); else CP_WAIT0();
        __syncthreads();

        unsigned sb = smem_base + (t & 1) * STG3;
        #pragma unroll
        for (int ks = 0; ks < 2; ks++) {
            unsigned bh[2][4], bl4[2][4];
            #pragma unroll
            for (int p = 0; p < 2; p++) {
                unsigned bd = sb + 2 * MAT3 + (unsigned)((wn * 32 + p * 16) * SROW3 + ks * 32) + b_off;
                ldsm_x4(bh[p], bd);
                ldsm_x4(bl4[p], bd + MAT3);
            }
            #pragma unroll
            for (int am = 0; am < 4; am++) {
                unsigned ah[4], al4[4];
                unsigned ad = sb + (unsigned)((wm * 64 + am * 16) * SROW3 + ks * 32) + a_off;
                ldsm_x4(ah, ad);
                ldsm_x4(al4, ad + MAT3);
                #pragma unroll
                for (int an = 0; an < 4; an++) {
                    const int p = an >> 1, q = (an & 1) * 2;
                    unsigned bfh[2] = { bh[p][q], bh[p][q + 1] };
                    unsigned bfl[2] = { bl4[p][q], bl4[p][q + 1] };
                    mma_bf16(acc[am][an], ah, bfh);
                    mma_bf16(acc[am][an], al4, bfh);
                    mma_bf16(acc[am][an], ah, bfl);
                }
            }
        }
        __syncthreads();
        if (t + 2 < T) issue(t + 2);
    }

    #pragma unroll
    for (int am = 0; am < 4; am++) {
        int r0 = by * 128 + wm * 64 + am * 16 + gid;
        int r1 = r0 + 8;
        #pragma unroll
        for (int an = 0; an < 4; an++) {
            int n0 = bx * 128 + wn * 32 + an * 8 + 2 * tig;
            float bv0 = bias[n0], bv1 = bias[n0 + 1];
            size_t o0 = (size_t)r0 * N + n0;
            size_t o1 = (size_t)r1 * N + n0;
            float v0 = acc[am][an][0] + bv0;
            float v1 = acc[am][an][1] + bv1;
            float v2 = acc[am][an][2] + bv0;
            float v3 = acc[am][an][3] + bv1;
            if (res) {
                v0 += res[o0]; v1 += res[o0 + 1];
                v2 += res[o1]; v3 += res[o1 + 1];
            }
            if (GELU) {
                v0 = gelu_tanh_f(v0); v1 = gelu_tanh_f(v1);
                v2 = gelu_tanh_f(v2); v3 = gelu_tanh_f(v3);
            }
            if (OMODE == 0) {
                *reinterpret_cast<float2*>(C + o0) = make_float2(v0, v1);
                *reinterpret_cast<float2*>(C + o1) = make_float2(v2, v3);
            } else {
                unsigned hw, lw;
                split2(v0, v1, hw, lw);
                *reinterpret_cast<unsigned*>(Ch + o0) = hw;
                *reinterpret_cast<unsigned*>(Cl + o0) = lw;
                split2(v2, v3, hw, lw);
                *reinterpret_cast<unsigned*>(Ch + o1) = hw;
                *reinterpret_cast<unsigned*>(Cl + o1) = lw;
                if (OMODE == 2 && n0 >= DM) {
                    int kvsel = (n0 >= 2 * DM) ? 1 : 0;
                    int local = n0 - DM - kvsel * DM;
                    int hh = local / DH, dd = local % DH;
                    int b0 = r0 >> 10, s0 = r0 & 1023;
                    int b1 = r1 >> 10, s1 = r1 & 1023;
                    size_t p0 = (((size_t)(b0 * 2 + kvsel) * NH + hh) * SEQ + s0) * DH + dd;
                    size_t p1 = (((size_t)(b1 * 2 + kvsel) * NH + hh) * SEQ + s1) * DH + dd;
                    *reinterpret_cast<float2*>(pres + p0) = make_float2(v0, v1);
                    *reinterpret_cast<float2*>(pres + p1) = make_float2(v2, v3);
                }
            }
        }
    }
}

// ---------------- FA2-style attention v4: pipelined K/V loads ---------------
#define A3_ST 100
#define A3_QH 0
#define A3_QL 12800
#define A3_KH 25600
#define A3_KL 32000
#define A3_VH 38400
#define A3_VL 44800
#define ATT3_SMEM_BYTES (51200*4)

__global__ __launch_bounds__(256, 1) void attn_v4_kernel(
    const __nv_bfloat16* __restrict__ qkvh, const __nv_bfloat16* __restrict__ qkvl,
    __nv_bfloat16* __restrict__ atth, __nv_bfloat16* __restrict__ attl)
{
    extern __shared__ unsigned smu[];
    const int bi = (int)gridDim.x - 1 - (int)blockIdx.x;   // biggest first
    const int h  = blockIdx.y;
    const int b  = blockIdx.z;
    const int tid = threadIdx.x;
    const int w = tid >> 5, l = tid & 31;
    const int gid = l >> 2, tig = l & 3;

    const float scale = 13.856406460551018f;   // sqrt(192) (faithful bug)
    const unsigned sbase = (unsigned)__cvta_generic_to_shared(smu);

    const int kcol = DM + h * DH;

    auto issue_k = [&](int j) {
        const size_t row0 = (size_t)(b * SEQ + j * 64);
        #pragma unroll
        for (int i = 0; i < 6; i++) {
            int c = tid + (i << 8);
            int r = c / 24, cc2 = c % 24;
            unsigned doff = (unsigned)((r * A3_ST + cc2 * 4) * 4);
            size_t gk = (row0 + r) * D3 + kcol + cc2 * 8;
            CP16(sbase + A3_KH * 4 + doff, (const void*)(qkvh + gk));
            CP16(sbase + A3_KL * 4 + doff, (const void*)(qkvl + gk));
        }
        CP_COMMIT();
    };
    auto issue_v = [&](int j) {
        const size_t row0 = (size_t)(b * SEQ + j * 64);
        #pragma unroll
        for (int i = 0; i < 6; i++) {
            int c = tid + (i << 8);
            int r = c / 24, cc2 = c % 24;
            unsigned doff = (unsigned)((r * A3_ST + cc2 * 4) * 4);
            size_t gv = (row0 + r) * D3 + kcol + DM + cc2 * 8;
            CP16(sbase + A3_VH * 4 + doff, (const void*)(qkvh + gv));
            CP16(sbase + A3_VL * 4 + doff, (const void*)(qkvl + gv));
        }
        CP_COMMIT();
    };

    // preload Q, K(0), V(0)
    {
        const size_t row0 = (size_t)(b * SEQ + bi * 128);
        const int qcol = h * DH;
        #pragma unroll
        for (int i = 0; i < 12; i++) {
            int c = tid + (i << 8);
            int r = c / 24, cc2 = c % 24;
            unsigned doff = (unsigned)((r * A3_ST + cc2 * 4) * 4);
            size_t goff = (row0 + r) * D3 + qcol + cc2 * 8;
            CP16(sbase + A3_QH * 4 + doff, (const void*)(qkvh + goff));
            CP16(sbase + A3_QL * 4 + doff, (const void*)(qkvl + goff));
        }
        CP_COMMIT();
    }
    issue_k(0);
    issue_v(0);

    float m0 = -1e30f, m1 = -1e30f, l0 = 0.f, l1 = 0.f;
    float accO[24][4];
    #pragma unroll
    for (int i = 0; i < 24; i++)
        #pragma unroll
        for (int c = 0; c < 4; c++) accO[i][c] = 0.f;

    const int lm_rwi  = (l & 7) + ((l >> 3) & 1) * 8;
    const int lm_ncol = (l >> 4) * 8;
    const unsigned vh_base = sbase + A3_VH * 4;
    const unsigned vl_base = sbase + A3_VL * 4;

    const int qg0 = bi * 128 + w * 16 + gid;
    const int qg1 = qg0 + 8;
    const int nkv = 2 * bi + 2;

    for (int j = 0; j < nkv; j++) {
        CP_WAIT1();             // K(j) ready
        __syncthreads();

        const unsigned* Qh = smu + A3_QH;
        const unsigned* Ql = smu + A3_QL;
        const unsigned* Kh = smu + A3_KH;
        const unsigned* Kl = smu + A3_KL;

        float accS[8][4];
        #pragma unroll
        for (int i = 0; i < 8; i++)
            #pragma unroll
            for (int c = 0; c < 4; c++) accS[i][c] = 0.f;

        #pragma unroll
        for (int ks = 0; ks < 12; ks++) {
            int kp = ks * 8;
            unsigned ah[4], al[4];
            int a0 = (w * 16 + gid) * A3_ST + kp + tig;
            int a1 = a0 + 8 * A3_ST;
            ah[0] = Qh[a0]; ah[1] = Qh[a1]; ah[2] = Qh[a0 + 4]; ah[3] = Qh[a1 + 4];
            al[0] = Ql[a0]; al[1] = Ql[a1]; al[2] = Ql[a0 + 4]; al[3] = Ql[a1 + 4];
            #pragma unroll
            for (int nt = 0; nt < 8; nt++) {
                int bb = (nt * 8 + gid) * A3_ST + kp + tig;
                unsigned bh[2], bl2[2];
                bh[0]  = Kh[bb]; bh[1]  = Kh[bb + 4];
                bl2[0] = Kl[bb]; bl2[1] = Kl[bb + 4];
                mma_bf16(accS[nt], ah, bh);
                mma_bf16(accS[nt], al, bh);
                mma_bf16(accS[nt], ah, bl2);
            }
        }

        const bool diag = (j >= 2 * bi);
        float mx0 = -1e30f, mx1 = -1e30f;
        #pragma unroll
        for (int nt = 0; nt < 8; nt++) {
            int kg = j * 64 + nt * 8 + 2 * tig;
            float v0 = accS[nt][0] * scale;
            float v1 = accS[nt][1] * scale;
            float v2 = accS[nt][2] * scale;
            float v3 = accS[nt][3] * scale;
            if (diag) {
                if (kg     > qg0) v0 = -1e30f;
                if (kg + 1 > qg0) v1 = -1e30f;
                if (kg     > qg1) v2 = -1e30f;
                if (kg + 1 > qg1) v3 = -1e30f;
            }
            accS[nt][0] = v0; accS[nt][1] = v1;
            accS[nt][2] = v2; accS[nt][3] = v3;
            mx0 = fmaxf(mx0, fmaxf(v0, v1));
            mx1 = fmaxf(mx1, fmaxf(v2, v3));
        }
        mx0 = fmaxf(mx0, __shfl_xor_sync(0xffffffffu, mx0, 1));
        mx0 = fmaxf(mx0, __shfl_xor_sync(0xffffffffu, mx0, 2));
        mx1 = fmaxf(mx1, __shfl_xor_sync(0xffffffffu, mx1, 1));
        mx1 = fmaxf(mx1, __shfl_xor_sync(0xffffffffu, mx1, 2));
        float mn0 = fmaxf(m0, mx0), mn1 = fmaxf(m1, mx1);
        float corr0 = __expf(m0 - mn0), corr1 = __expf(m1 - mn1);

        unsigned pha[4][4], pla[4][4];
        float sum0 = 0.f, sum1 = 0.f;
        #pragma unroll
        for (int nt = 0; nt < 8; nt++) {
            float p0 = __expf(accS[nt][0] - mn0);
            float p1 = __expf(accS[nt][1] - mn0);
            float p2 = __expf(accS[nt][2] - mn1);
            float p3 = __expf(accS[nt][3] - mn1);
            sum0 += p0 + p1;
            sum1 += p2 + p3;
            const int ks = nt >> 1;
            const int s0 = (nt & 1) * 2;
            split2(p0, p1, pha[ks][s0],     pla[ks][s0]);
            split2(p2, p3, pha[ks][s0 + 1], pla[ks][s0 + 1]);
        }
        sum0 += __shfl_xor_sync(0xffffffffu, sum0, 1);
        sum0 += __shfl_xor_sync(0xffffffffu, sum0, 2);
        sum1 += __shfl_xor_sync(0xffffffffu, sum1, 1);
        sum1 += __shfl_xor_sync(0xffffffffu, sum1, 2);
        l0 = l0 * corr0 + sum0;  m0 = mn0;
        l1 = l1 * corr1 + sum1;  m1 = mn1;

        CP_WAIT0();             // V(j) ready
        __syncthreads();        // all warps past scores -> K buffer free
        if (j + 1 < nkv) issue_k(j + 1);   // lands under PV(j)

        #pragma unroll
        for (int nt = 0; nt < 24; nt++) {
            accO[nt][0] *= corr0; accO[nt][1] *= corr0;
            accO[nt][2] *= corr1; accO[nt][3] *= corr1;
        }
        #pragma unroll
        for (int ks = 0; ks < 4; ks++) {
            unsigned rowoff = (unsigned)((ks * 16 + lm_rwi) * A3_ST) * 4u;
            #pragma unroll
            for (int g = 0; g < 12; g++) {
                unsigned coloff = (unsigned)(g * 8 + lm_ncol / 2) * 4u;
                unsigned bh0, bh1, bh2, bh3, bl0, bl1, bl2, bl3;
                ldsm_x4_t(bh0, bh1, bh2, bh3, vh_base + rowoff + coloff);
                ldsm_x4_t(bl0, bl1, bl2, bl3, vl_base + rowoff + coloff);
                unsigned bfh[2], bfl[2];
                bfh[0] = bh0; bfh[1] = bh1; bfl[0] = bl0; bfl[1] = bl1;
                mma_bf16(accO[2 * g],     pha[ks], bfh);
                mma_bf16(accO[2 * g],     pla[ks], bfh);
                mma_bf16(accO[2 * g],     pha[ks], bfl);
                bfh[0] = bh2; bfh[1] = bh3; bfl[0] = bl2; bfl[1] = bl3;
                mma_bf16(accO[2 * g + 1], pha[ks], bfh);
                mma_bf16(accO[2 * g + 1], pla[ks], bfh);
                mma_bf16(accO[2 * g + 1], pha[ks], bfl);
            }
        }

        __syncthreads();        // all warps done reading V(j)
        if (j + 1 < nkv) issue_v(j + 1);   // lands under scores(j+1)
    }

    float li0 = 1.0f / l0, li1 = 1.0f / l1;
    int row0 = b * SEQ + bi * 128 + w * 16 + gid;
    #pragma unroll
    for (int nt = 0; nt < 24; nt++) {
        int col = h * DH + nt * 8 + 2 * tig;
        size_t o0 = (size_t)row0 * DM + col;
        size_t o1 = (size_t)(row0 + 8) * DM + col;
        unsigned hw, lw;
        split2(accO[nt][0] * li0, accO[nt][1] * li0, hw, lw);
        *reinterpret_cast<unsigned*>(atth + o0) = hw;
        *reinterpret_cast<unsigned*>(attl + o0) = lw;
        split2(accO[nt][2] * li1, accO[nt][3] * li1, hw, lw);
        *reinterpret_cast<unsigned*>(atth + o1) = hw;
        *reinterpret_cast<unsigned*>(attl + o1) = lw;
    }
}

// ---------------- launch -----------------------------------------------
extern "C" void kernel_launch(void* const* d_in, const int* in_sizes, int n_in,
                              void* d_out, int out_size)
{
    const float* x   = (const float*)d_in[0];
    const float* W1  = (const float*)d_in[2];
    const float* b1  = (const float*)d_in[3];
    const float* W3  = (const float*)d_in[4];
    const float* b3  = (const float*)d_in[5];
    const float* W2  = (const float*)d_in[6];
    const float* b2  = (const float*)d_in[7];
    const float* W4  = (const float*)d_in[8];
    const float* b4  = (const float*)d_in[9];
    const float* g1  = (const float*)d_in[10];
    const float* be1 = (const float*)d_in[11];
    const float* g2  = (const float*)d_in[12];
    const float* be2 = (const float*)d_in[13];
    float* out = (float*)d_out;

    float *x1;
    cudaGetSymbolAddress((void**)&x1, g_x1);
    __nv_bfloat16 *qkvh, *qkvl, *xnh, *xnl, *atth, *attl, *xn2h, *xn2l, *hh, *hl;
    __nv_bfloat16 *w1h, *w1l, *w3h, *w3l, *w2h, *w2l, *w4h, *w4l;
    cudaGetSymbolAddress((void**)&qkvh, g_qkvh); cudaGetSymbolAddress((void**)&qkvl, g_qkvl);
    cudaGetSymbolAddress((void**)&xnh,  g_xnh);  cudaGetSymbolAddress((void**)&xnl,  g_xnl);
    cudaGetSymbolAddress((void**)&atth, g_atth); cudaGetSymbolAddress((void**)&attl, g_attl);
    cudaGetSymbolAddress((void**)&xn2h, g_xn2h); cudaGetSymbolAddress((void**)&xn2l, g_xn2l);
    cudaGetSymbolAddress((void**)&hh,   g_hh);   cudaGetSymbolAddress((void**)&hl,   g_hl);
    cudaGetSymbolAddress((void**)&w1h,  g_w1h);  cudaGetSymbolAddress((void**)&w1l,  g_w1l);
    cudaGetSymbolAddress((void**)&w3h,  g_w3h);  cudaGetSymbolAddress((void**)&w3l,  g_w3l);
    cudaGetSymbolAddress((void**)&w2h,  g_w2h);  cudaGetSymbolAddress((void**)&w2l,  g_w2l);
    cudaGetSymbolAddress((void**)&w4h,  g_w4h);  cudaGetSymbolAddress((void**)&w4l,  g_w4l);

    cudaFuncSetAttribute(attn_v4_kernel,
                         cudaFuncAttributeMaxDynamicSharedMemorySize, ATT3_SMEM_BYTES);
    cudaFuncSetAttribute(bgemm3_kernel<false,0>,
                         cudaFuncAttributeMaxDynamicSharedMemorySize, GEMM3_SMEM);
    cudaFuncSetAttribute(bgemm3_kernel<false,1>,
                         cudaFuncAttributeMaxDynamicSharedMemorySize, GEMM3_SMEM);
    cudaFuncSetAttribute(bgemm3_kernel<false,2>,
                         cudaFuncAttributeMaxDynamicSharedMemorySize, GEMM3_SMEM);
    cudaFuncSetAttribute(bgemm3_kernel<true,1>,
                         cudaFuncAttributeMaxDynamicSharedMemorySize, GEMM3_SMEM);

    float* pres = out + XOUT_ELEMS;
    bool has_present = ((size_t)out_size >= XOUT_ELEMS + PRES_ELEMS);

    // 0) weight transpose+split
    wsplit_kernel<<<dim3(D3/32, DM/32), 256>>>(W1, w1h, w1l, DM, D3);
    wsplit_kernel<<<dim3(DM/32, DM/32), 256>>>(W3, w3h, w3l, DM, DM);
    wsplit_kernel<<<dim3(D4/32, DM/32), 256>>>(W2, w2h, w2l, DM, D4);
    wsplit_kernel<<<dim3(DM/32, D4/32), 256>>>(W4, w4h, w4l, D4, DM);

    // 1) LN1 -> split
    ln_kernel<<<ROWS, 256>>>(x, g1, be1, xnh, xnl);

    // 2) qkv = xn @ W1 + b1 -> split qkv (+ fused present fp32 write)
    if (has_present) {
        bgemm3_kernel<false,2><<<dim3(D3/128, ROWS/128), 256, GEMM3_SMEM>>>(
            xnh, xnl, w1h, w1l, b1, nullptr, nullptr, qkvh, qkvl, pres, ROWS, D3, DM);
    } else {
        bgemm3_kernel<false,1><<<dim3(D3/128, ROWS/128), 256, GEMM3_SMEM>>>(
            xnh, xnl, w1h, w1l, b1, nullptr, nullptr, qkvh, qkvl, nullptr, ROWS, D3, DM);
    }

    // 3) attention (pipelined K/V loads)
    attn_v4_kernel<<<dim3(SEQ/128, NH, BS), 256, ATT3_SMEM_BYTES>>>(qkvh, qkvl, atth, attl);

    // 4) x1 = att @ W3 + b3 + x
    bgemm3_kernel<false,0><<<dim3(DM/128, ROWS/128), 256, GEMM3_SMEM>>>(
        atth, attl, w3h, w3l, b3, x, x1, nullptr, nullptr, nullptr, ROWS, DM, DM);

    // 5) LN2 -> split
    ln_kernel<<<ROWS, 256>>>(x1, g2, be2, xn2h, xn2l);

    // 6) h = gelu(xn2 @ W2 + b2) -> split out
    bgemm3_kernel<true,1><<<dim3(D4/128, ROWS/128), 256, GEMM3_SMEM>>>(
        xn2h, xn2l, w2h, w2l, b2, nullptr, nullptr, hh, hl, nullptr, ROWS, D4, DM);

    // 7) out = h @ W4 + b4 + x1
    bgemm3_kernel<false,0><<<dim3(DM/128, ROWS/128), 256, GEMM3_SMEM>>>(
        hh, hl, w4h, w4l, b4, x1, out, nullptr, nullptr, nullptr, ROWS, DM, D4);
}

// round 10
// speedup vs baseline: 1.1386x; 1.0048x over previous
#include <cuda_runtime.h>
#include <cuda_bf16.h>
#include <math.h>

// ---------------- problem constants ----------------
#define BS   8
#define SEQ  1024
#define DM   768
#define NH   4
#define DH   192
#define ROWS (BS*SEQ)          // 8192
#define D3   (3*DM)            // 2304
#define D4   (4*DM)            // 3072

#define XOUT_ELEMS   ((size_t)ROWS*DM)
#define PRES_ELEMS   ((size_t)BS*2*NH*SEQ*DH)

// ---------------- scratch (device globals) ---------------------------------
__device__ __align__(256) float g_x1 [ROWS*DM];

__device__ __align__(256) __nv_bfloat16 g_qkvh[(size_t)ROWS*D3], g_qkvl[(size_t)ROWS*D3];
__device__ __align__(256) __nv_bfloat16 g_xnh [ROWS*DM],  g_xnl [ROWS*DM];
__device__ __align__(256) __nv_bfloat16 g_atth[ROWS*DM],  g_attl[ROWS*DM];
__device__ __align__(256) __nv_bfloat16 g_xn2h[ROWS*DM],  g_xn2l[ROWS*DM];
__device__ __align__(256) __nv_bfloat16 g_hh[(size_t)ROWS*D4], g_hl[(size_t)ROWS*D4];

// transposed split weights: [N][K]
__device__ __align__(256) __nv_bfloat16 g_w1h[(size_t)D3*DM], g_w1l[(size_t)D3*DM];
__device__ __align__(256) __nv_bfloat16 g_w3h[(size_t)DM*DM], g_w3l[(size_t)DM*DM];
__device__ __align__(256) __nv_bfloat16 g_w2h[(size_t)D4*DM], g_w2l[(size_t)D4*DM];
__device__ __align__(256) __nv_bfloat16 g_w4h[(size_t)DM*D4], g_w4l[(size_t)DM*D4];

// split-KV partials: [chunk][pidx(b,h,bi-4)][row 0..127][col 0..191] fp32
__device__ __align__(256) float g_po[(size_t)2*128*128*192];
__device__ __align__(256) float g_pm[2*128*128];
__device__ __align__(256) float g_pl[2*128*128];

// work table: (bi, chunk) per blockIdx.x type; chunk -1 = full (single block)
__device__ const int c_bi[12] = {7,6,3,5,7,2,4,6,5,1,4,0};
__device__ const int c_ch[12] = {1,1,-1,1,0,-1,1,0,0,-1,0,-1};

// ---------------- helpers ---------------------------------------------------
__device__ __forceinline__ void split2(float x0, float x1, unsigned &hi, unsigned &lo) {
    __nv_bfloat16 h0 = __float2bfloat16_rn(x0);
    __nv_bfloat16 h1 = __float2bfloat16_rn(x1);
    __nv_bfloat16 l0 = __float2bfloat16_rn(x0 - __bfloat162float(h0));
    __nv_bfloat16 l1 = __float2bfloat16_rn(x1 - __bfloat162float(h1));
    hi = ((unsigned)__bfloat16_as_ushort(h1) << 16) | (unsigned)__bfloat16_as_ushort(h0);
    lo = ((unsigned)__bfloat16_as_ushort(l1) << 16) | (unsigned)__bfloat16_as_ushort(l0);
}

__device__ __forceinline__ void mma_bf16(float c[4], const unsigned a[4], const unsigned b[2]) {
    asm volatile(
        "mma.sync.aligned.m16n8k16.row.col.f32.bf16.bf16.f32 "
        "{%0,%1,%2,%3}, {%4,%5,%6,%7}, {%8,%9}, {%0,%1,%2,%3};\n"
        : "+f"(c[0]), "+f"(c[1]), "+f"(c[2]), "+f"(c[3])
        : "r"(a[0]), "r"(a[1]), "r"(a[2]), "r"(a[3]), "r"(b[0]), "r"(b[1]));
}

__device__ __forceinline__ void ldsm_x4(unsigned r[4], unsigned addr) {
    asm volatile("ldmatrix.sync.aligned.m8n8.x4.shared.b16 {%0,%1,%2,%3}, [%4];"
        : "=r"(r[0]), "=r"(r[1]), "=r"(r[2]), "=r"(r[3]) : "r"(addr));
}

__device__ __forceinline__ void ldsm_x4_t(unsigned &r0, unsigned &r1, unsigned &r2, unsigned &r3, unsigned saddr) {
    asm volatile("ldmatrix.sync.aligned.m8n8.x4.trans.shared.b16 {%0,%1,%2,%3}, [%4];"
        : "=r"(r0), "=r"(r1), "=r"(r2), "=r"(r3) : "r"(saddr));
}

#define CP16(dst, src) asm volatile("cp.async.cg.shared.global [%0], [%1], 16;\n" :: "r"(dst), "l"(src))
#define CP_COMMIT() asm volatile("cp.async.commit_group;\n" ::)
#define CP_WAIT0()  asm volatile("cp.async.wait_group 0;\n" ::)
#define CP_WAIT1()  asm volatile("cp.async.wait_group 1;\n" ::)

__device__ __forceinline__ float gelu_tanh_f(float x) {
    float x3 = x * x * x;
    float t  = tanhf(0.7978845608028654f * (x + 0.044715f * x3));
    return 0.5f * x * (1.0f + t);
}

// ---------------- weight transpose + split: W[K][N] -> Wt_hi/lo[N][K] ------
__global__ __launch_bounds__(256) void wsplit_kernel(
    const float* __restrict__ W, __nv_bfloat16* __restrict__ Th,
    __nv_bfloat16* __restrict__ Tl, int K, int N)
{
    __shared__ float t[32][33];
    int n0 = blockIdx.x * 32, k0 = blockIdx.y * 32;
    int tx = threadIdx.x & 31, ty = threadIdx.x >> 5;
    #pragma unroll
    for (int j = 0; j < 4; j++)
        t[ty + 8 * j][tx] = W[(size_t)(k0 + ty + 8 * j) * N + n0 + tx];
    __syncthreads();
    #pragma unroll
    for (int j = 0; j < 4; j++) {
        float v = t[tx][ty + 8 * j];
        __nv_bfloat16 hi = __float2bfloat16_rn(v);
        size_t o = (size_t)(n0 + ty + 8 * j) * K + k0 + tx;
        Th[o] = hi;
        Tl[o] = __float2bfloat16_rn(v - __bfloat162float(hi));
    }
}

// ---------------- LayerNorm, writes split bf16 hi/lo ------------------------
__global__ __launch_bounds__(256) void ln_kernel(
    const float* __restrict__ x, const float* __restrict__ gamma,
    const float* __restrict__ beta,
    __nv_bfloat16* __restrict__ oh, __nv_bfloat16* __restrict__ ol)
{
    int row = blockIdx.x;
    int tid = threadIdx.x;
    const float* xr = x + (size_t)row * DM;
    float v0 = xr[tid], v1 = xr[tid + 256], v2 = xr[tid + 512];
    float s  = v0 + v1 + v2;
    float sq = v0*v0 + v1*v1 + v2*v2;
    #pragma unroll
    for (int o = 16; o > 0; o >>= 1) {
        s  += __shfl_xor_sync(0xffffffffu, s,  o);
        sq += __shfl_xor_sync(0xffffffffu, sq, o);
    }
    __shared__ float ss[8], ssq[8];
    __shared__ float mu_s, rs_s;
    int w = tid >> 5, l = tid & 31;
    if (l == 0) { ss[w] = s; ssq[w] = sq; }
    __syncthreads();
    if (tid == 0) {
        float S = 0.f, SQ = 0.f;
        #pragma unroll
        for (int i = 0; i < 8; i++) { S += ss[i]; SQ += ssq[i]; }
        float mu = S * (1.0f / DM);
        float var = SQ * (1.0f / DM) - mu * mu;
        mu_s = mu;
        rs_s = rsqrtf(var + 1e-3f);
    }
    __syncthreads();
    float mu = mu_s, rs = rs_s;
    size_t ro = (size_t)row * DM;
    #pragma unroll
    for (int q = 0; q < 3; q++) {
        int c = tid + q * 256;
        float v = (q == 0 ? v0 : (q == 1 ? v1 : v2));
        float y = (v - mu) * rs * gamma[c] + beta[c];
        __nv_bfloat16 hi = __float2bfloat16_rn(y);
        oh[ro + c] = hi;
        ol[ro + c] = __float2bfloat16_rn(y - __bfloat162float(hi));
    }
}

// ---------------- split-bf16 GEMM v3: BK=32, 2-stage, 2 CTA/SM --------------
#define SROW3 80
#define MAT3  (128*SROW3)
#define STG3  (4*MAT3)
#define GEMM3_SMEM (2*STG3)

template<bool GELU, int OMODE>
__global__ __launch_bounds__(256, 2) void bgemm3_kernel(
    const __nv_bfloat16* __restrict__ Ah, const __nv_bfloat16* __restrict__ Al,
    const __nv_bfloat16* __restrict__ Bh, const __nv_bfloat16* __restrict__ Bl,
    const float* __restrict__ bias, const float* __restrict__ res,
    float* __restrict__ C, __nv_bfloat16* __restrict__ Ch, __nv_bfloat16* __restrict__ Cl,
    float* __restrict__ pres, int M, int N, int K)
{
    extern __shared__ unsigned char sm3[];
    const int tid = threadIdx.x;
    const int w = tid >> 5, l = tid & 31;
    const int wm = w & 1, wn = w >> 1;
    const int gid = l >> 2, tig = l & 3;
    const int bx = blockIdx.x, by = blockIdx.y;
    const int T = K >> 5;

    const unsigned smem_base = (unsigned)__cvta_generic_to_shared(sm3);

    const __nv_bfloat16* A0 = Ah + (size_t)(by * 128) * K;
    const __nv_bfloat16* A1 = Al + (size_t)(by * 128) * K;
    const __nv_bfloat16* B0 = Bh + (size_t)(bx * 128) * K;
    const __nv_bfloat16* B1 = Bl + (size_t)(bx * 128) * K;

    const int rl = l & 7, sel = l >> 3;
    const unsigned a_off = (unsigned)((rl + 8 * (sel & 1)) * SROW3 + 16 * (sel >> 1));
    const unsigned b_off = (unsigned)((rl + 8 * (sel >> 1)) * SROW3 + 16 * (sel & 1));

    float acc[4][4][4];
    #pragma unroll
    for (int i = 0; i < 4; i++)
        #pragma unroll
        for (int j = 0; j < 4; j++)
            #pragma unroll
            for (int c = 0; c < 4; c++) acc[i][j][c] = 0.f;

    auto issue = [&](int t) {
        unsigned sb = smem_base + (t & 1) * STG3;
        int k0 = t << 5;
        #pragma unroll
        for (int i = 0; i < 2; i++) {
            int chunk = tid + (i << 8);
            int r = chunk >> 2, c = chunk & 3;
            unsigned doff = (unsigned)(r * SROW3 + c * 16);
            size_t goff = (size_t)r * K + k0 + c * 8;
            CP16(sb + doff,            (const void*)(A0 + goff));
            CP16(sb + MAT3 + doff,     (const void*)(A1 + goff));
            CP16(sb + 2 * MAT3 + doff, (const void*)(B0 + goff));
            CP16(sb + 3 * MAT3 + doff, (const void*)(B1 + goff));
        }
        CP_COMMIT();
    };

    issue(0);
    if (T > 1) issue(1);

    for (int t = 0; t < T; t++) {
        if (t + 1 < T) CP_WAIT1(); else CP_WAIT0();
        __syncthreads();

        unsigned sb = smem_base + (t & 1) * STG3;
        #pragma unroll
        for (int ks = 0; ks < 2; ks++) {
            unsigned bh[2][4], bl4[2][4];
            #pragma unroll
            for (int p = 0; p < 2; p++) {
                unsigned bd = sb + 2 * MAT3 + (unsigned)((wn * 32 + p * 16) * SROW3 + ks * 32) + b_off;
                ldsm_x4(bh[p], bd);
                ldsm_x4(bl4[p], bd + MAT3);
            }
            #pragma unroll
            for (int am = 0; am < 4; am++) {
                unsigned ah[4], al4[4];
                unsigned ad = sb + (unsigned)((wm * 64 + am * 16) * SROW3 + ks * 32) + a_off;
                ldsm_x4(ah, ad);
                ldsm_x4(al4, ad + MAT3);
                #pragma unroll
                for (int an = 0; an < 4; an++) {
                    const int p = an >> 1, q = (an & 1) * 2;
                    unsigned bfh[2] = { bh[p][q], bh[p][q + 1] };
                    unsigned bfl[2] = { bl4[p][q], bl4[p][q + 1] };
                    mma_bf16(acc[am][an], ah, bfh);
                    mma_bf16(acc[am][an], al4, bfh);
                    mma_bf16(acc[am][an], ah, bfl);
                }
            }
        }
        __syncthreads();
        if (t + 2 < T) issue(t + 2);
    }

    #pragma unroll
    for (int am = 0; am < 4; am++) {
        int r0 = by * 128 + wm * 64 + am * 16 + gid;
        int r1 = r0 + 8;
        #pragma unroll
        for (int an = 0; an < 4; an++) {
            int n0 = bx * 128 + wn * 32 + an * 8 + 2 * tig;
            float bv0 = bias[n0], bv1 = bias[n0 + 1];
            size_t o0 = (size_t)r0 * N + n0;
            size_t o1 = (size_t)r1 * N + n0;
            float v0 = acc[am][an][0] + bv0;
            float v1 = acc[am][an][1] + bv1;
            float v2 = acc[am][an][2] + bv0;
            float v3 = acc[am][an][3] + bv1;
            if (res) {
                v0 += res[o0]; v1 += res[o0 + 1];
                v2 += res[o1]; v3 += res[o1 + 1];
            }
            if (GELU) {
                v0 = gelu_tanh_f(v0); v1 = gelu_tanh_f(v1);
                v2 = gelu_tanh_f(v2); v3 = gelu_tanh_f(v3);
            }
            if (OMODE == 0) {
                *reinterpret_cast<float2*>(C + o0) = make_float2(v0, v1);
                *reinterpret_cast<float2*>(C + o1) = make_float2(v2, v3);
            } else {
                unsigned hw, lw;
                split2(v0, v1, hw, lw);
                *reinterpret_cast<unsigned*>(Ch + o0) = hw;
                *reinterpret_cast<unsigned*>(Cl + o0) = lw;
                split2(v2, v3, hw, lw);
                *reinterpret_cast<unsigned*>(Ch + o1) = hw;
                *reinterpret_cast<unsigned*>(Cl + o1) = lw;
                if (OMODE == 2 && n0 >= DM) {
                    int kvsel = (n0 >= 2 * DM) ? 1 : 0;
                    int local = n0 - DM - kvsel * DM;
                    int hh = local / DH, dd = local % DH;
                    int b0 = r0 >> 10, s0 = r0 & 1023;
                    int b1 = r1 >> 10, s1 = r1 & 1023;
                    size_t p0 = (((size_t)(b0 * 2 + kvsel) * NH + hh) * SEQ + s0) * DH + dd;
                    size_t p1 = (((size_t)(b1 * 2 + kvsel) * NH + hh) * SEQ + s1) * DH + dd;
                    *reinterpret_cast<float2*>(pres + p0) = make_float2(v0, v1);
                    *reinterpret_cast<float2*>(pres + p1) = make_float2(v2, v3);
                }
            }
        }
    }
}

// ---------------- attention v5: split-KV + register softmax -----------------
#define A3_ST 100
#define A3_QH 0
#define A3_QL 12800
#define A3_KH 25600
#define A3_KL 32000
#define A3_VH 38400
#define A3_VL 44800
#define ATT3_SMEM_BYTES (51200*4)

__global__ __launch_bounds__(256, 1) void attn_v5_kernel(
    const __nv_bfloat16* __restrict__ qkvh, const __nv_bfloat16* __restrict__ qkvl,
    __nv_bfloat16* __restrict__ atth, __nv_bfloat16* __restrict__ attl)
{
    extern __shared__ unsigned smu[];
    const int type = blockIdx.x;     // 0..11
    const int bi = c_bi[type];
    const int ch = c_ch[type];       // -1 single, 0/1 chunk
    const int h  = blockIdx.y;
    const int b  = blockIdx.z;
    const int tid = threadIdx.x;
    const int w = tid >> 5, l = tid & 31;
    const int gid = l >> 2, tig = l & 3;

    const int j0 = (ch == 1) ? bi : 0;
    const int j1 = (ch == 0) ? bi : 2 * bi + 2;

    const float scale = 13.856406460551018f;   // sqrt(192) (faithful bug)
    const unsigned sbase = (unsigned)__cvta_generic_to_shared(smu);

    const int kcol = DM + h * DH;

    auto issue_k = [&](int j) {
        const size_t row0 = (size_t)(b * SEQ + j * 64);
        #pragma unroll
        for (int i = 0; i < 6; i++) {
            int c = tid + (i << 8);
            int r = c / 24, cc2 = c % 24;
            unsigned doff = (unsigned)((r * A3_ST + cc2 * 4) * 4);
            size_t gk = (row0 + r) * D3 + kcol + cc2 * 8;
            CP16(sbase + A3_KH * 4 + doff, (const void*)(qkvh + gk));
            CP16(sbase + A3_KL * 4 + doff, (const void*)(qkvl + gk));
        }
        CP_COMMIT();
    };
    auto issue_v = [&](int j) {
        const size_t row0 = (size_t)(b * SEQ + j * 64);
        #pragma unroll
        for (int i = 0; i < 6; i++) {
            int c = tid + (i << 8);
            int r = c / 24, cc2 = c % 24;
            unsigned doff = (unsigned)((r * A3_ST + cc2 * 4) * 4);
            size_t gv = (row0 + r) * D3 + kcol + DM + cc2 * 8;
            CP16(sbase + A3_VH * 4 + doff, (const void*)(qkvh + gv));
            CP16(sbase + A3_VL * 4 + doff, (const void*)(qkvl + gv));
        }
        CP_COMMIT();
    };

    // preload Q, K(j0), V(j0)
    {
        const size_t row0 = (size_t)(b * SEQ + bi * 128);
        const int qcol = h * DH;
        #pragma unroll
        for (int i = 0; i < 12; i++) {
            int c = tid + (i << 8);
            int r = c / 24, cc2 = c % 24;
            unsigned doff = (unsigned)((r * A3_ST + cc2 * 4) * 4);
            size_t goff = (row0 + r) * D3 + qcol + cc2 * 8;
            CP16(sbase + A3_QH * 4 + doff, (const void*)(qkvh + goff));
            CP16(sbase + A3_QL * 4 + doff, (const void*)(qkvl + goff));
        }
        CP_COMMIT();
    }
    issue_k(j0);
    issue_v(j0);

    float m0 = -1e30f, m1 = -1e30f, l0 = 0.f, l1 = 0.f;
    float accO[24][4];
    #pragma unroll
    for (int i = 0; i < 24; i++)
        #pragma unroll
        for (int c = 0; c < 4; c++) accO[i][c] = 0.f;

    const int lm_rwi  = (l & 7) + ((l >> 3) & 1) * 8;
    const int lm_ncol = (l >> 4) * 8;
    const unsigned vh_base = sbase + A3_VH * 4;
    const unsigned vl_base = sbase + A3_VL * 4;

    const int qg0 = bi * 128 + w * 16 + gid;
    const int qg1 = qg0 + 8;

    for (int j = j0; j < j1; j++) {
        CP_WAIT1();             // K(j) ready
        __syncthreads();

        const bool diag = (j >= 2 * bi);
        // warp fully masked in this tile? (all 16 rows < all 64 cols)
        const bool wskip = diag && (64 * j >= bi * 128 + w * 16 + 16);

        const unsigned* Qh = smu + A3_QH;
        const unsigned* Ql = smu + A3_QL;
        const unsigned* Kh = smu + A3_KH;
        const unsigned* Kl = smu + A3_KL;

        unsigned pha[4][4], pla[4][4];
        float corr0 = 1.f, corr1 = 1.f;

        if (!wskip) {
            float accS[8][4];
            #pragma unroll
            for (int i = 0; i < 8; i++)
                #pragma unroll
                for (int c = 0; c < 4; c++) accS[i][c] = 0.f;

            #pragma unroll
            for (int ks = 0; ks < 12; ks++) {
                int kp = ks * 8;
                unsigned ah[4], al[4];
                int a0 = (w * 16 + gid) * A3_ST + kp + tig;
                int a1 = a0 + 8 * A3_ST;
                ah[0] = Qh[a0]; ah[1] = Qh[a1]; ah[2] = Qh[a0 + 4]; ah[3] = Qh[a1 + 4];
                al[0] = Ql[a0]; al[1] = Ql[a1]; al[2] = Ql[a0 + 4]; al[3] = Ql[a1 + 4];
                #pragma unroll
                for (int nt = 0; nt < 8; nt++) {
                    int bb = (nt * 8 + gid) * A3_ST + kp + tig;
                    unsigned bh[2], bl2[2];
                    bh[0]  = Kh[bb]; bh[1]  = Kh[bb + 4];
                    bl2[0] = Kl[bb]; bl2[1] = Kl[bb + 4];
                    mma_bf16(accS[nt], ah, bh);
                    mma_bf16(accS[nt], al, bh);
                    mma_bf16(accS[nt], ah, bl2);
                }
            }

            float mx0 = -1e30f, mx1 = -1e30f;
            #pragma unroll
            for (int nt = 0; nt < 8; nt++) {
                int kg = j * 64 + nt * 8 + 2 * tig;
                float v0 = accS[nt][0] * scale;
                float v1 = accS[nt][1] * scale;
                float v2 = accS[nt][2] * scale;
                float v3 = accS[nt][3] * scale;
                if (diag) {
                    if (kg     > qg0) v0 = -1e30f;
                    if (kg + 1 > qg0) v1 = -1e30f;
                    if (kg     > qg1) v2 = -1e30f;
                    if (kg + 1 > qg1) v3 = -1e30f;
                }
                accS[nt][0] = v0; accS[nt][1] = v1;
                accS[nt][2] = v2; accS[nt][3] = v3;
                mx0 = fmaxf(mx0, fmaxf(v0, v1));
                mx1 = fmaxf(mx1, fmaxf(v2, v3));
            }
            mx0 = fmaxf(mx0, __shfl_xor_sync(0xffffffffu, mx0, 1));
            mx0 = fmaxf(mx0, __shfl_xor_sync(0xffffffffu, mx0, 2));
            mx1 = fmaxf(mx1, __shfl_xor_sync(0xffffffffu, mx1, 1));
            mx1 = fmaxf(mx1, __shfl_xor_sync(0xffffffffu, mx1, 2));
            float mn0 = fmaxf(m0, mx0), mn1 = fmaxf(m1, mx1);
            corr0 = __expf(m0 - mn0); corr1 = __expf(m1 - mn1);

            float sum0 = 0.f, sum1 = 0.f;
            #pragma unroll
            for (int nt = 0; nt < 8; nt++) {
                float p0 = __expf(accS[nt][0] - mn0);
                float p1 = __expf(accS[nt][1] - mn0);
                float p2 = __expf(accS[nt][2] - mn1);
                float p3 = __expf(accS[nt][3] - mn1);
                sum0 += p0 + p1;
                sum1 += p2 + p3;
                const int ks = nt >> 1;
                const int s0 = (nt & 1) * 2;
                split2(p0, p1, pha[ks][s0],     pla[ks][s0]);
                split2(p2, p3, pha[ks][s0 + 1], pla[ks][s0 + 1]);
            }
            sum0 += __shfl_xor_sync(0xffffffffu, sum0, 1);
            sum0 += __shfl_xor_sync(0xffffffffu, sum0, 2);
            sum1 += __shfl_xor_sync(0xffffffffu, sum1, 1);
            sum1 += __shfl_xor_sync(0xffffffffu, sum1, 2);
            l0 = l0 * corr0 + sum0;  m0 = mn0;
            l1 = l1 * corr1 + sum1;  m1 = mn1;
        }

        CP_WAIT0();             // V(j) ready
        __syncthreads();        // K buffer free
        if (j + 1 < j1) issue_k(j + 1);    // lands under PV(j)

        if (!wskip) {
            #pragma unroll
            for (int nt = 0; nt < 24; nt++) {
                accO[nt][0] *= corr0; accO[nt][1] *= corr0;
                accO[nt][2] *= corr1; accO[nt][3] *= corr1;
            }
            #pragma unroll
            for (int ks = 0; ks < 4; ks++) {
                unsigned rowoff = (unsigned)((ks * 16 + lm_rwi) * A3_ST) * 4u;
                #pragma unroll
                for (int g = 0; g < 12; g++) {
                    unsigned coloff = (unsigned)(g * 8 + lm_ncol / 2) * 4u;
                    unsigned bh0, bh1, bh2, bh3, bl0, bl1, bl2, bl3;
                    ldsm_x4_t(bh0, bh1, bh2, bh3, vh_base + rowoff + coloff);
                    ldsm_x4_t(bl0, bl1, bl2, bl3, vl_base + rowoff + coloff);
                    unsigned bfh[2], bfl[2];
                    bfh[0] = bh0; bfh[1] = bh1; bfl[0] = bl0; bfl[1] = bl1;
                    mma_bf16(accO[2 * g],     pha[ks], bfh);
                    mma_bf16(accO[2 * g],     pla[ks], bfh);
                    mma_bf16(accO[2 * g],     pha[ks], bfl);
                    bfh[0] = bh2; bfh[1] = bh3; bfl[0] = bl2; bfl[1] = bl3;
                    mma_bf16(accO[2 * g + 1], pha[ks], bfh);
                    mma_bf16(accO[2 * g + 1], pla[ks], bfh);
                    mma_bf16(accO[2 * g + 1], pha[ks], bfl);
                }
            }
        }

        __syncthreads();        // V buffer free
        if (j + 1 < j1) issue_v(j + 1);    // lands under scores(j+1)
    }

    if (ch < 0) {
        // single block: normalize + split write
        float li0 = 1.0f / l0, li1 = 1.0f / l1;
        int row0 = b * SEQ + bi * 128 + w * 16 + gid;
        #pragma unroll
        for (int nt = 0; nt < 24; nt++) {
            int col = h * DH + nt * 8 + 2 * tig;
            size_t o0 = (size_t)row0 * DM + col;
            size_t o1 = (size_t)(row0 + 8) * DM + col;
            unsigned hw, lw;
            split2(accO[nt][0] * li0, accO[nt][1] * li0, hw, lw);
            *reinterpret_cast<unsigned*>(atth + o0) = hw;
            *reinterpret_cast<unsigned*>(attl + o0) = lw;
            split2(accO[nt][2] * li1, accO[nt][3] * li1, hw, lw);
            *reinterpret_cast<unsigned*>(atth + o1) = hw;
            *reinterpret_cast<unsigned*>(attl + o1) = lw;
        }
    } else {
        // partial: write unnormalized O + m/l
        const int pidx = ((b * NH + h) << 2) + (bi - 4);
        float* po = g_po + ((size_t)ch * 128 + pidx) * (128 * 192);
        const int r0 = w * 16 + gid, r1 = r0 + 8;
        #pragma unroll
        for (int nt = 0; nt < 24; nt++) {
            int col = nt * 8 + 2 * tig;
            *reinterpret_cast<float2*>(po + r0 * 192 + col) = make_float2(accO[nt][0], accO[nt][1]);
            *reinterpret_cast<float2*>(po + r1 * 192 + col) = make_float2(accO[nt][2], accO[nt][3]);
        }
        if (tig == 0) {
            int mlb = (ch * 128 + pidx) * 128;
            g_pm[mlb + r0] = m0; g_pl[mlb + r0] = l0;
            g_pm[mlb + r1] = m1; g_pl[mlb + r1] = l1;
        }
    }
}

// ---------------- split-KV combine ------------------------------------------
__global__ __launch_bounds__(256) void attn_combine_kernel(
    __nv_bfloat16* __restrict__ atth, __nv_bfloat16* __restrict__ attl)
{
    const int pidx = blockIdx.x;           // 0..127
    const int b  = pidx >> 4;
    const int h  = (pidx >> 2) & 3;
    const int bi = 4 + (pidx & 3);
    const int r  = threadIdx.x >> 1;
    const int c0 = (threadIdx.x & 1) * 96;

    const float* po0 = g_po + ((size_t)0 * 128 + pidx) * (128 * 192) + r * 192 + c0;
    const float* po1 = g_po + ((size_t)1 * 128 + pidx) * (128 * 192) + r * 192 + c0;
    const int mlb0 = (0 * 128 + pidx) * 128 + r;
    const int mlb1 = (1 * 128 + pidx) * 128 + r;
    float m0 = g_pm[mlb0], l0 = g_pl[mlb0];
    float m1 = g_pm[mlb1], l1 = g_pl[mlb1];
    float m = fmaxf(m0, m1);
    float e0 = __expf(m0 - m), e1 = __expf(m1 - m);
    float linv = 1.0f / (e0 * l0 + e1 * l1);

    size_t go = (size_t)(b * SEQ + bi * 128 + r) * DM + h * DH + c0;
    #pragma unroll
    for (int c = 0; c < 96; c += 2) {
        float v0 = (e0 * po0[c]     + e1 * po1[c])     * linv;
        float v1 = (e0 * po0[c + 1] + e1 * po1[c + 1]) * linv;
        unsigned hw, lw;
        split2(v0, v1, hw, lw);
        *reinterpret_cast<unsigned*>(atth + go + c) = hw;
        *reinterpret_cast<unsigned*>(attl + go + c) = lw;
    }
}

// ---------------- launch -----------------------------------------------
extern "C" void kernel_launch(void* const* d_in, const int* in_sizes, int n_in,
                              void* d_out, int out_size)
{
    const float* x   = (const float*)d_in[0];
    const float* W1  = (const float*)d_in[2];
    const float* b1  = (const float*)d_in[3];
    const float* W3  = (const float*)d_in[4];
    const float* b3  = (const float*)d_in[5];
    const float* W2  = (const float*)d_in[6];
    const float* b2  = (const float*)d_in[7];
    const float* W4  = (const float*)d_in[8];
    const float* b4  = (const float*)d_in[9];
    const float* g1  = (const float*)d_in[10];
    const float* be1 = (const float*)d_in[11];
    const float* g2  = (const float*)d_in[12];
    const float* be2 = (const float*)d_in[13];
    float* out = (float*)d_out;

    float *x1;
    cudaGetSymbolAddress((void**)&x1, g_x1);
    __nv_bfloat16 *qkvh, *qkvl, *xnh, *xnl, *atth, *attl, *xn2h, *xn2l, *hh, *hl;
    __nv_bfloat16 *w1h, *w1l, *w3h, *w3l, *w2h, *w2l, *w4h, *w4l;
    cudaGetSymbolAddress((void**)&qkvh, g_qkvh); cudaGetSymbolAddress((void**)&qkvl, g_qkvl);
    cudaGetSymbolAddress((void**)&xnh,  g_xnh);  cudaGetSymbolAddress((void**)&xnl,  g_xnl);
    cudaGetSymbolAddress((void**)&atth, g_atth); cudaGetSymbolAddress((void**)&attl, g_attl);
    cudaGetSymbolAddress((void**)&xn2h, g_xn2h); cudaGetSymbolAddress((void**)&xn2l, g_xn2l);
    cudaGetSymbolAddress((void**)&hh,   g_hh);   cudaGetSymbolAddress((void**)&hl,   g_hl);
    cudaGetSymbolAddress((void**)&w1h,  g_w1h);  cudaGetSymbolAddress((void**)&w1l,  g_w1l);
    cudaGetSymbolAddress((void**)&w3h,  g_w3h);  cudaGetSymbolAddress((void**)&w3l,  g_w3l);
    cudaGetSymbolAddress((void**)&w2h,  g_w2h);  cudaGetSymbolAddress((void**)&w2l,  g_w2l);
    cudaGetSymbolAddress((void**)&w4h,  g_w4h);  cudaGetSymbolAddress((void**)&w4l,  g_w4l);

    cudaFuncSetAttribute(attn_v5_kernel,
                         cudaFuncAttributeMaxDynamicSharedMemorySize, ATT3_SMEM_BYTES);
    cudaFuncSetAttribute(bgemm3_kernel<false,0>,
                         cudaFuncAttributeMaxDynamicSharedMemorySize, GEMM3_SMEM);
    cudaFuncSetAttribute(bgemm3_kernel<false,1>,
                         cudaFuncAttributeMaxDynamicSharedMemorySize, GEMM3_SMEM);
    cudaFuncSetAttribute(bgemm3_kernel<false,2>,
                         cudaFuncAttributeMaxDynamicSharedMemorySize, GEMM3_SMEM);
    cudaFuncSetAttribute(bgemm3_kernel<true,1>,
                         cudaFuncAttributeMaxDynamicSharedMemorySize, GEMM3_SMEM);

    float* pres = out + XOUT_ELEMS;
    bool has_present = ((size_t)out_size >= XOUT_ELEMS + PRES_ELEMS);

    // 0) weight transpose+split
    wsplit_kernel<<<dim3(D3/32, DM/32), 256>>>(W1, w1h, w1l, DM, D3);
    wsplit_kernel<<<dim3(DM/32, DM/32), 256>>>(W3, w3h, w3l, DM, DM);
    wsplit_kernel<<<dim3(D4/32, DM/32), 256>>>(W2, w2h, w2l, DM, D4);
    wsplit_kernel<<<dim3(DM/32, D4/32), 256>>>(W4, w4h, w4l, D4, DM);

    // 1) LN1 -> split
    ln_kernel<<<ROWS, 256>>>(x, g1, be1, xnh, xnl);

    // 2) qkv = xn @ W1 + b1 -> split qkv (+ fused present fp32 write)
    if (has_present) {
        bgemm3_kernel<false,2><<<dim3(D3/128, ROWS/128), 256, GEMM3_SMEM>>>(
            xnh, xnl, w1h, w1l, b1, nullptr, nullptr, qkvh, qkvl, pres, ROWS, D3, DM);
    } else {
        bgemm3_kernel<false,1><<<dim3(D3/128, ROWS/128), 256, GEMM3_SMEM>>>(
            xnh, xnl, w1h, w1l, b1, nullptr, nullptr, qkvh, qkvl, nullptr, ROWS, D3, DM);
    }

    // 3) attention: split-KV main + combine
    attn_v5_kernel<<<dim3(12, NH, BS), 256, ATT3_SMEM_BYTES>>>(qkvh, qkvl, atth, attl);
    attn_combine_kernel<<<128, 256>>>(atth, attl);

    // 4) x1 = att @ W3 + b3 + x
    bgemm3_kernel<false,0><<<dim3(DM/128, ROWS/128), 256, GEMM3_SMEM>>>(
        atth, attl, w3h, w3l, b3, x, x1, nullptr, nullptr, nullptr, ROWS, DM, DM);

    // 5) LN2 -> split
    ln_kernel<<<ROWS, 256>>>(x1, g2, be2, xn2h, xn2l);

    // 6) h = gelu(xn2 @ W2 + b2) -> split out
    bgemm3_kernel<true,1><<<dim3(D4/128, ROWS/128), 256, GEMM3_SMEM>>>(
        xn2h, xn2l, w2h, w2l, b2, nullptr, nullptr, hh, hl, nullptr, ROWS, D4, DM);

    // 7) out = h @ W4 + b4 + x1
    bgemm3_kernel<false,0><<<dim3(DM/128, ROWS/128), 256, GEMM3_SMEM>>>(
        hh, hl, w4h, w4l, b4, x1, out, nullptr, nullptr, nullptr, ROWS, DM, D4);
}

// round 11
// speedup vs baseline: 1.3761x; 1.2086x over previous
#include <cuda_runtime.h>
#include <cuda_bf16.h>
#include <cuda_fp16.h>
#include <math.h>

// ---------------- problem constants ----------------
#define BS   8
#define SEQ  1024
#define DM   768
#define NH   4
#define DH   192
#define ROWS (BS*SEQ)          // 8192
#define D3   (3*DM)            // 2304
#define D4   (4*DM)            // 3072

#define XOUT_ELEMS   ((size_t)ROWS*DM)
#define PRES_ELEMS   ((size_t)BS*2*NH*SEQ*DH)

// ---------------- scratch (device globals) ---------------------------------
__device__ __align__(256) float g_x1 [ROWS*DM];

__device__ __align__(256) __nv_bfloat16 g_qkvh[(size_t)ROWS*D3], g_qkvl[(size_t)ROWS*D3];
__device__ __align__(256) __nv_bfloat16 g_xnh [ROWS*DM],  g_xnl [ROWS*DM];
__device__ __align__(256) __half g_atth[ROWS*DM],  g_attl[ROWS*DM];
__device__ __align__(256) __half g_xn2h[ROWS*DM],  g_xn2l[ROWS*DM];
__device__ __align__(256) __half g_hh[(size_t)ROWS*D4], g_hl[(size_t)ROWS*D4];

// transposed weights: [N][K]
__device__ __align__(256) __nv_bfloat16 g_w1h[(size_t)D3*DM], g_w1l[(size_t)D3*DM];  // bf16 split
__device__ __align__(256) __half g_w3h[(size_t)DM*DM];                                // fp16 single
__device__ __align__(256) __half g_w2h[(size_t)D4*DM];
__device__ __align__(256) __half g_w4h[(size_t)DM*D4];

// split-KV partials
__device__ __align__(256) float g_po[(size_t)2*128*128*192];
__device__ __align__(256) float g_pm[2*128*128];
__device__ __align__(256) float g_pl[2*128*128];

__device__ const int c_bi[12] = {7,6,3,5,7,2,4,6,5,1,4,0};
__device__ const int c_ch[12] = {1,1,-1,1,0,-1,1,0,0,-1,0,-1};

// ---------------- helpers ---------------------------------------------------
__device__ __forceinline__ void split2(float x0, float x1, unsigned &hi, unsigned &lo) {
    __nv_bfloat16 h0 = __float2bfloat16_rn(x0);
    __nv_bfloat16 h1 = __float2bfloat16_rn(x1);
    __nv_bfloat16 l0 = __float2bfloat16_rn(x0 - __bfloat162float(h0));
    __nv_bfloat16 l1 = __float2bfloat16_rn(x1 - __bfloat162float(h1));
    hi = ((unsigned)__bfloat16_as_ushort(h1) << 16) | (unsigned)__bfloat16_as_ushort(h0);
    lo = ((unsigned)__bfloat16_as_ushort(l1) << 16) | (unsigned)__bfloat16_as_ushort(l0);
}

__device__ __forceinline__ void split2h(float x0, float x1, unsigned &hi, unsigned &lo) {
    __half h0 = __float2half_rn(x0);
    __half h1 = __float2half_rn(x1);
    __half l0 = __float2half_rn(x0 - __half2float(h0));
    __half l1 = __float2half_rn(x1 - __half2float(h1));
    hi = ((unsigned)__half_as_ushort(h1) << 16) | (unsigned)__half_as_ushort(h0);
    lo = ((unsigned)__half_as_ushort(l1) << 16) | (unsigned)__half_as_ushort(l0);
}

__device__ __forceinline__ void mma_bf16(float c[4], const unsigned a[4], const unsigned b[2]) {
    asm volatile(
        "mma.sync.aligned.m16n8k16.row.col.f32.bf16.bf16.f32 "
        "{%0,%1,%2,%3}, {%4,%5,%6,%7}, {%8,%9}, {%0,%1,%2,%3};\n"
        : "+f"(c[0]), "+f"(c[1]), "+f"(c[2]), "+f"(c[3])
        : "r"(a[0]), "r"(a[1]), "r"(a[2]), "r"(a[3]), "r"(b[0]), "r"(b[1]));
}

__device__ __forceinline__ void mma_f16(float c[4], const unsigned a[4], const unsigned b[2]) {
    asm volatile(
        "mma.sync.aligned.m16n8k16.row.col.f32.f16.f16.f32 "
        "{%0,%1,%2,%3}, {%4,%5,%6,%7}, {%8,%9}, {%0,%1,%2,%3};\n"
        : "+f"(c[0]), "+f"(c[1]), "+f"(c[2]), "+f"(c[3])
        : "r"(a[0]), "r"(a[1]), "r"(a[2]), "r"(a[3]), "r"(b[0]), "r"(b[1]));
}

__device__ __forceinline__ void ldsm_x4(unsigned r[4], unsigned addr) {
    asm volatile("ldmatrix.sync.aligned.m8n8.x4.shared.b16 {%0,%1,%2,%3}, [%4];"
        : "=r"(r[0]), "=r"(r[1]), "=r"(r[2]), "=r"(r[3]) : "r"(addr));
}

__device__ __forceinline__ void ldsm_x4_t(unsigned &r0, unsigned &r1, unsigned &r2, unsigned &r3, unsigned saddr) {
    asm volatile("ldmatrix.sync.aligned.m8n8.x4.trans.shared.b16 {%0,%1,%2,%3}, [%4];"
        : "=r"(r0), "=r"(r1), "=r"(r2), "=r"(r3) : "r"(saddr));
}

#define CP16(dst, src) asm volatile("cp.async.cg.shared.global [%0], [%1], 16;\n" :: "r"(dst), "l"(src))
#define CP_COMMIT() asm volatile("cp.async.commit_group;\n" ::)
#define CP_WAIT0()  asm volatile("cp.async.wait_group 0;\n" ::)
#define CP_WAIT1()  asm volatile("cp.async.wait_group 1;\n" ::)

__device__ __forceinline__ float gelu_tanh_f(float x) {
    float x3 = x * x * x;
    float t  = tanhf(0.7978845608028654f * (x + 0.044715f * x3));
    return 0.5f * x * (1.0f + t);
}

// ---------------- weight transpose + split (bf16 hi/lo) ---------------------
__global__ __launch_bounds__(256) void wsplit_kernel(
    const float* __restrict__ W, __nv_bfloat16* __restrict__ Th,
    __nv_bfloat16* __restrict__ Tl, int K, int N)
{
    __shared__ float t[32][33];
    int n0 = blockIdx.x * 32, k0 = blockIdx.y * 32;
    int tx = threadIdx.x & 31, ty = threadIdx.x >> 5;
    #pragma unroll
    for (int j = 0; j < 4; j++)
        t[ty + 8 * j][tx] = W[(size_t)(k0 + ty + 8 * j) * N + n0 + tx];
    __syncthreads();
    #pragma unroll
    for (int j = 0; j < 4; j++) {
        float v = t[tx][ty + 8 * j];
        __nv_bfloat16 hi = __float2bfloat16_rn(v);
        size_t o = (size_t)(n0 + ty + 8 * j) * K + k0 + tx;
        Th[o] = hi;
        Tl[o] = __float2bfloat16_rn(v - __bfloat162float(hi));
    }
}

// ---------------- weight transpose (fp16 single) ----------------------------
__global__ __launch_bounds__(256) void wsplit_h_kernel(
    const float* __restrict__ W, __half* __restrict__ Th, int K, int N)
{
    __shared__ float t[32][33];
    int n0 = blockIdx.x * 32, k0 = blockIdx.y * 32;
    int tx = threadIdx.x & 31, ty = threadIdx.x >> 5;
    #pragma unroll
    for (int j = 0; j < 4; j++)
        t[ty + 8 * j][tx] = W[(size_t)(k0 + ty + 8 * j) * N + n0 + tx];
    __syncthreads();
    #pragma unroll
    for (int j = 0; j < 4; j++) {
        size_t o = (size_t)(n0 + ty + 8 * j) * K + k0 + tx;
        Th[o] = __float2half_rn(t[tx][ty + 8 * j]);
    }
}

// ---------------- LayerNorm: templated split output -------------------------
template<bool F16>
__global__ __launch_bounds__(256) void ln_kernel(
    const float* __restrict__ x, const float* __restrict__ gamma,
    const float* __restrict__ beta, void* __restrict__ ohv, void* __restrict__ olv)
{
    int row = blockIdx.x;
    int tid = threadIdx.x;
    const float* xr = x + (size_t)row * DM;
    float v0 = xr[tid], v1 = xr[tid + 256], v2 = xr[tid + 512];
    float s  = v0 + v1 + v2;
    float sq = v0*v0 + v1*v1 + v2*v2;
    #pragma unroll
    for (int o = 16; o > 0; o >>= 1) {
        s  += __shfl_xor_sync(0xffffffffu, s,  o);
        sq += __shfl_xor_sync(0xffffffffu, sq, o);
    }
    __shared__ float ss[8], ssq[8];
    __shared__ float mu_s, rs_s;
    int w = tid >> 5, l = tid & 31;
    if (l == 0) { ss[w] = s; ssq[w] = sq; }
    __syncthreads();
    if (tid == 0) {
        float S = 0.f, SQ = 0.f;
        #pragma unroll
        for (int i = 0; i < 8; i++) { S += ss[i]; SQ += ssq[i]; }
        float mu = S * (1.0f / DM);
        float var = SQ * (1.0f / DM) - mu * mu;
        mu_s = mu;
        rs_s = rsqrtf(var + 1e-3f);
    }
    __syncthreads();
    float mu = mu_s, rs = rs_s;
    size_t ro = (size_t)row * DM;
    #pragma unroll
    for (int q = 0; q < 3; q++) {
        int c = tid + q * 256;
        float v = (q == 0 ? v0 : (q == 1 ? v1 : v2));
        float y = (v - mu) * rs * gamma[c] + beta[c];
        if (F16) {
            __half* oh = (__half*)ohv; __half* ol = (__half*)olv;
            __half hi = __float2half_rn(y);
            oh[ro + c] = hi;
            ol[ro + c] = __float2half_rn(y - __half2float(hi));
        } else {
            __nv_bfloat16* oh = (__nv_bfloat16*)ohv; __nv_bfloat16* ol = (__nv_bfloat16*)olv;
            __nv_bfloat16 hi = __float2bfloat16_rn(y);
            oh[ro + c] = hi;
            ol[ro + c] = __float2bfloat16_rn(y - __bfloat162float(hi));
        }
    }
}

// ---------------- GEMM v3 (bf16 3-pass) for QKV ------------------------------
#define SROW3 80
#define MAT3  (128*SROW3)
#define STG3  (4*MAT3)
#define GEMM3_SMEM (2*STG3)

template<int OMODE>   // 1 = split bf16 out, 2 = split bf16 out + present
__global__ __launch_bounds__(256, 2) void bgemm3_kernel(
    const __nv_bfloat16* __restrict__ Ah, const __nv_bfloat16* __restrict__ Al,
    const __nv_bfloat16* __restrict__ Bh, const __nv_bfloat16* __restrict__ Bl,
    const float* __restrict__ bias,
    __nv_bfloat16* __restrict__ Ch, __nv_bfloat16* __restrict__ Cl,
    float* __restrict__ pres, int M, int N, int K)
{
    extern __shared__ unsigned char sm3[];
    const int tid = threadIdx.x;
    const int w = tid >> 5, l = tid & 31;
    const int wm = w & 1, wn = w >> 1;
    const int gid = l >> 2, tig = l & 3;
    const int bx = blockIdx.x, by = blockIdx.y;
    const int T = K >> 5;

    const unsigned smem_base = (unsigned)__cvta_generic_to_shared(sm3);

    const __nv_bfloat16* A0 = Ah + (size_t)(by * 128) * K;
    const __nv_bfloat16* A1 = Al + (size_t)(by * 128) * K;
    const __nv_bfloat16* B0 = Bh + (size_t)(bx * 128) * K;
    const __nv_bfloat16* B1 = Bl + (size_t)(bx * 128) * K;

    const int rl = l & 7, sel = l >> 3;
    const unsigned a_off = (unsigned)((rl + 8 * (sel & 1)) * SROW3 + 16 * (sel >> 1));
    const unsigned b_off = (unsigned)((rl + 8 * (sel >> 1)) * SROW3 + 16 * (sel & 1));

    float acc[4][4][4];
    #pragma unroll
    for (int i = 0; i < 4; i++)
        #pragma unroll
        for (int j = 0; j < 4; j++)
            #pragma unroll
            for (int c = 0; c < 4; c++) acc[i][j][c] = 0.f;

    auto issue = [&](int t) {
        unsigned sb = smem_base + (t & 1) * STG3;
        int k0 = t << 5;
        #pragma unroll
        for (int i = 0; i < 2; i++) {
            int chunk = tid + (i << 8);
            int r = chunk >> 2, c = chunk & 3;
            unsigned doff = (unsigned)(r * SROW3 + c * 16);
            size_t goff = (size_t)r * K + k0 + c * 8;
            CP16(sb + doff,            (const void*)(A0 + goff));
            CP16(sb + MAT3 + doff,     (const void*)(A1 + goff));
            CP16(sb + 2 * MAT3 + doff, (const void*)(B0 + goff));
            CP16(sb + 3 * MAT3 + doff, (const void*)(B1 + goff));
        }
        CP_COMMIT();
    };

    issue(0);
    if (T > 1) issue(1);

    for (int t = 0; t < T; t++) {
        if (t + 1 < T) CP_WAIT1(); else CP_WAIT0();
        __syncthreads();

        unsigned sb = smem_base + (t & 1) * STG3;
        #pragma unroll
        for (int ks = 0; ks < 2; ks++) {
            unsigned bh[2][4], bl4[2][4];
            #pragma unroll
            for (int p = 0; p < 2; p++) {
                unsigned bd = sb + 2 * MAT3 + (unsigned)((wn * 32 + p * 16) * SROW3 + ks * 32) + b_off;
                ldsm_x4(bh[p], bd);
                ldsm_x4(bl4[p], bd + MAT3);
            }
            #pragma unroll
            for (int am = 0; am < 4; am++) {
                unsigned ah[4], al4[4];
                unsigned ad = sb + (unsigned)((wm * 64 + am * 16) * SROW3 + ks * 32) + a_off;
                ldsm_x4(ah, ad);
                ldsm_x4(al4, ad + MAT3);
                #pragma unroll
                for (int an = 0; an < 4; an++) {
                    const int p = an >> 1, q = (an & 1) * 2;
                    unsigned bfh[2] = { bh[p][q], bh[p][q + 1] };
                    unsigned bfl[2] = { bl4[p][q], bl4[p][q + 1] };
                    mma_bf16(acc[am][an], ah, bfh);
                    mma_bf16(acc[am][an], al4, bfh);
                    mma_bf16(acc[am][an], ah, bfl);
                }
            }
        }
        __syncthreads();
        if (t + 2 < T) issue(t + 2);
    }

    #pragma unroll
    for (int am = 0; am < 4; am++) {
        int r0 = by * 128 + wm * 64 + am * 16 + gid;
        int r1 = r0 + 8;
        #pragma unroll
        for (int an = 0; an < 4; an++) {
            int n0 = bx * 128 + wn * 32 + an * 8 + 2 * tig;
            float bv0 = bias[n0], bv1 = bias[n0 + 1];
            size_t o0 = (size_t)r0 * N + n0;
            size_t o1 = (size_t)r1 * N + n0;
            float v0 = acc[am][an][0] + bv0;
            float v1 = acc[am][an][1] + bv1;
            float v2 = acc[am][an][2] + bv0;
            float v3 = acc[am][an][3] + bv1;
            unsigned hw, lw;
            split2(v0, v1, hw, lw);
            *reinterpret_cast<unsigned*>(Ch + o0) = hw;
            *reinterpret_cast<unsigned*>(Cl + o0) = lw;
            split2(v2, v3, hw, lw);
            *reinterpret_cast<unsigned*>(Ch + o1) = hw;
            *reinterpret_cast<unsigned*>(Cl + o1) = lw;
            if (OMODE == 2 && n0 >= DM) {
                int kvsel = (n0 >= 2 * DM) ? 1 : 0;
                int local = n0 - DM - kvsel * DM;
                int hh = local / DH, dd = local % DH;
                int b0 = r0 >> 10, s0 = r0 & 1023;
                int b1 = r1 >> 10, s1 = r1 & 1023;
                size_t p0 = (((size_t)(b0 * 2 + kvsel) * NH + hh) * SEQ + s0) * DH + dd;
                size_t p1 = (((size_t)(b1 * 2 + kvsel) * NH + hh) * SEQ + s1) * DH + dd;
                *reinterpret_cast<float2*>(pres + p0) = make_float2(v0, v1);
                *reinterpret_cast<float2*>(pres + p1) = make_float2(v2, v3);
            }
        }
    }
}

// ---------------- GEMM v5: fp16 2-pass (A split hi/lo, B single) ------------
#define STG5  (3*MAT3)
#define GEMM5_SMEM (2*STG5)

template<bool GELU, int OMODE>  // OMODE: 0 = float out (+res), 1 = split fp16 out
__global__ __launch_bounds__(256, 2) void bgemm5_kernel(
    const __half* __restrict__ Ah, const __half* __restrict__ Al,
    const __half* __restrict__ Bh,
    const float* __restrict__ bias, const float* __restrict__ res,
    float* __restrict__ C, __half* __restrict__ Ch, __half* __restrict__ Cl,
    int M, int N, int K)
{
    extern __shared__ unsigned char sm5[];
    const int tid = threadIdx.x;
    const int w = tid >> 5, l = tid & 31;
    const int wm = w & 1, wn = w >> 1;
    const int gid = l >> 2, tig = l & 3;
    const int bx = blockIdx.x, by = blockIdx.y;
    const int T = K >> 5;

    const unsigned smem_base = (unsigned)__cvta_generic_to_shared(sm5);

    const __half* A0 = Ah + (size_t)(by * 128) * K;
    const __half* A1 = Al + (size_t)(by * 128) * K;
    const __half* B0 = Bh + (size_t)(bx * 128) * K;

    const int rl = l & 7, sel = l >> 3;
    const unsigned a_off = (unsigned)((rl + 8 * (sel & 1)) * SROW3 + 16 * (sel >> 1));
    const unsigned b_off = (unsigned)((rl + 8 * (sel >> 1)) * SROW3 + 16 * (sel & 1));

    float acc[4][4][4];
    #pragma unroll
    for (int i = 0; i < 4; i++)
        #pragma unroll
        for (int j = 0; j < 4; j++)
            #pragma unroll
            for (int c = 0; c < 4; c++) acc[i][j][c] = 0.f;

    auto issue = [&](int t) {
        unsigned sb = smem_base + (t & 1) * STG5;
        int k0 = t << 5;
        #pragma unroll
        for (int i = 0; i < 2; i++) {
            int chunk = tid + (i << 8);
            int r = chunk >> 2, c = chunk & 3;
            unsigned doff = (unsigned)(r * SROW3 + c * 16);
            size_t goff = (size_t)r * K + k0 + c * 8;
            CP16(sb + doff,            (const void*)(A0 + goff));
            CP16(sb + MAT3 + doff,     (const void*)(A1 + goff));
            CP16(sb + 2 * MAT3 + doff, (const void*)(B0 + goff));
        }
        CP_COMMIT();
    };

    issue(0);
    if (T > 1) issue(1);

    for (int t = 0; t < T; t++) {
        if (t + 1 < T) CP_WAIT1(); else CP_WAIT0();
        __syncthreads();

        unsigned sb = smem_base + (t & 1) * STG5;
        #pragma unroll
        for (int ks = 0; ks < 2; ks++) {
            unsigned bh[2][4];
            #pragma unroll
            for (int p = 0; p < 2; p++) {
                unsigned bd = sb + 2 * MAT3 + (unsigned)((wn * 32 + p * 16) * SROW3 + ks * 32) + b_off;
                ldsm_x4(bh[p], bd);
            }
            #pragma unroll
            for (int am = 0; am < 4; am++) {
                unsigned ah[4], al4[4];
                unsigned ad = sb + (unsigned)((wm * 64 + am * 16) * SROW3 + ks * 32) + a_off;
                ldsm_x4(ah, ad);
                ldsm_x4(al4, ad + MAT3);
                #pragma unroll
                for (int an = 0; an < 4; an++) {
                    const int p = an >> 1, q = (an & 1) * 2;
                    unsigned bfh[2] = { bh[p][q], bh[p][q + 1] };
                    mma_f16(acc[am][an], ah, bfh);
                    mma_f16(acc[am][an], al4, bfh);
                }
            }
        }
        __syncthreads();
        if (t + 2 < T) issue(t + 2);
    }

    #pragma unroll
    for (int am = 0; am < 4; am++) {
        int r0 = by * 128 + wm * 64 + am * 16 + gid;
        int r1 = r0 + 8;
        #pragma unroll
        for (int an = 0; an < 4; an++) {
            int n0 = bx * 128 + wn * 32 + an * 8 + 2 * tig;
            float bv0 = bias[n0], bv1 = bias[n0 + 1];
            size_t o0 = (size_t)r0 * N + n0;
            size_t o1 = (size_t)r1 * N + n0;
            float v0 = acc[am][an][0] + bv0;
            float v1 = acc[am][an][1] + bv1;
            float v2 = acc[am][an][2] + bv0;
            float v3 = acc[am][an][3] + bv1;
            if (res) {
                v0 += res[o0]; v1 += res[o0 + 1];
                v2 += res[o1]; v3 += res[o1 + 1];
            }
            if (GELU) {
                v0 = gelu_tanh_f(v0); v1 = gelu_tanh_f(v1);
                v2 = gelu_tanh_f(v2); v3 = gelu_tanh_f(v3);
            }
            if (OMODE == 0) {
                *reinterpret_cast<float2*>(C + o0) = make_float2(v0, v1);
                *reinterpret_cast<float2*>(C + o1) = make_float2(v2, v3);
            } else {
                unsigned hw, lw;
                split2h(v0, v1, hw, lw);
                *reinterpret_cast<unsigned*>(Ch + o0) = hw;
                *reinterpret_cast<unsigned*>(Cl + o0) = lw;
                split2h(v2, v3, hw, lw);
                *reinterpret_cast<unsigned*>(Ch + o1) = hw;
                *reinterpret_cast<unsigned*>(Cl + o1) = lw;
            }
        }
    }
}

// ---------------- attention v5: split-KV + register softmax (bf16) ----------
#define A3_ST 100
#define A3_QH 0
#define A3_QL 12800
#define A3_KH 25600
#define A3_KL 32000
#define A3_VH 38400
#define A3_VL 44800
#define ATT3_SMEM_BYTES (51200*4)

__global__ __launch_bounds__(256, 1) void attn_v5_kernel(
    const __nv_bfloat16* __restrict__ qkvh, const __nv_bfloat16* __restrict__ qkvl,
    __half* __restrict__ atth, __half* __restrict__ attl)
{
    extern __shared__ unsigned smu[];
    const int type = blockIdx.x;
    const int bi = c_bi[type];
    const int ch = c_ch[type];
    const int h  = blockIdx.y;
    const int b  = blockIdx.z;
    const int tid = threadIdx.x;
    const int w = tid >> 5, l = tid & 31;
    const int gid = l >> 2, tig = l & 3;

    const int j0 = (ch == 1) ? bi : 0;
    const int j1 = (ch == 0) ? bi : 2 * bi + 2;

    const float scale = 13.856406460551018f;   // sqrt(192) (faithful bug)
    const unsigned sbase = (unsigned)__cvta_generic_to_shared(smu);

    const int kcol = DM + h * DH;

    auto issue_k = [&](int j) {
        const size_t row0 = (size_t)(b * SEQ + j * 64);
        #pragma unroll
        for (int i = 0; i < 6; i++) {
            int c = tid + (i << 8);
            int r = c / 24, cc2 = c % 24;
            unsigned doff = (unsigned)((r * A3_ST + cc2 * 4) * 4);
            size_t gk = (row0 + r) * D3 + kcol + cc2 * 8;
            CP16(sbase + A3_KH * 4 + doff, (const void*)(qkvh + gk));
            CP16(sbase + A3_KL * 4 + doff, (const void*)(qkvl + gk));
        }
        CP_COMMIT();
    };
    auto issue_v = [&](int j) {
        const size_t row0 = (size_t)(b * SEQ + j * 64);
        #pragma unroll
        for (int i = 0; i < 6; i++) {
            int c = tid + (i << 8);
            int r = c / 24, cc2 = c % 24;
            unsigned doff = (unsigned)((r * A3_ST + cc2 * 4) * 4);
            size_t gv = (row0 + r) * D3 + kcol + DM + cc2 * 8;
            CP16(sbase + A3_VH * 4 + doff, (const void*)(qkvh + gv));
            CP16(sbase + A3_VL * 4 + doff, (const void*)(qkvl + gv));
        }
        CP_COMMIT();
    };

    {
        const size_t row0 = (size_t)(b * SEQ + bi * 128);
        const int qcol = h * DH;
        #pragma unroll
        for (int i = 0; i < 12; i++) {
            int c = tid + (i << 8);
            int r = c / 24, cc2 = c % 24;
            unsigned doff = (unsigned)((r * A3_ST + cc2 * 4) * 4);
            size_t goff = (row0 + r) * D3 + qcol + cc2 * 8;
            CP16(sbase + A3_QH * 4 + doff, (const void*)(qkvh + goff));
            CP16(sbase + A3_QL * 4 + doff, (const void*)(qkvl + goff));
        }
        CP_COMMIT();
    }
    issue_k(j0);
    issue_v(j0);

    float m0 = -1e30f, m1 = -1e30f, l0 = 0.f, l1 = 0.f;
    float accO[24][4];
    #pragma unroll
    for (int i = 0; i < 24; i++)
        #pragma unroll
        for (int c = 0; c < 4; c++) accO[i][c] = 0.f;

    const int lm_rwi  = (l & 7) + ((l >> 3) & 1) * 8;
    const int lm_ncol = (l >> 4) * 8;
    const unsigned vh_base = sbase + A3_VH * 4;
    const unsigned vl_base = sbase + A3_VL * 4;

    const int qg0 = bi * 128 + w * 16 + gid;
    const int qg1 = qg0 + 8;

    for (int j = j0; j < j1; j++) {
        CP_WAIT1();
        __syncthreads();

        const bool diag = (j >= 2 * bi);
        const bool wskip = diag && (64 * j >= bi * 128 + w * 16 + 16);

        const unsigned* Qh = smu + A3_QH;
        const unsigned* Ql = smu + A3_QL;
        const unsigned* Kh = smu + A3_KH;
        const unsigned* Kl = smu + A3_KL;

        unsigned pha[4][4], pla[4][4];
        float corr0 = 1.f, corr1 = 1.f;

        if (!wskip) {
            float accS[8][4];
            #pragma unroll
            for (int i = 0; i < 8; i++)
                #pragma unroll
                for (int c = 0; c < 4; c++) accS[i][c] = 0.f;

            #pragma unroll
            for (int ks = 0; ks < 12; ks++) {
                int kp = ks * 8;
                unsigned ah[4], al[4];
                int a0 = (w * 16 + gid) * A3_ST + kp + tig;
                int a1 = a0 + 8 * A3_ST;
                ah[0] = Qh[a0]; ah[1] = Qh[a1]; ah[2] = Qh[a0 + 4]; ah[3] = Qh[a1 + 4];
                al[0] = Ql[a0]; al[1] = Ql[a1]; al[2] = Ql[a0 + 4]; al[3] = Ql[a1 + 4];
                #pragma unroll
                for (int nt = 0; nt < 8; nt++) {
                    int bb = (nt * 8 + gid) * A3_ST + kp + tig;
                    unsigned bh[2], bl2[2];
                    bh[0]  = Kh[bb]; bh[1]  = Kh[bb + 4];
                    bl2[0] = Kl[bb]; bl2[1] = Kl[bb + 4];
                    mma_bf16(accS[nt], ah, bh);
                    mma_bf16(accS[nt], al, bh);
                    mma_bf16(accS[nt], ah, bl2);
                }
            }

            float mx0 = -1e30f, mx1 = -1e30f;
            #pragma unroll
            for (int nt = 0; nt < 8; nt++) {
                int kg = j * 64 + nt * 8 + 2 * tig;
                float v0 = accS[nt][0] * scale;
                float v1 = accS[nt][1] * scale;
                float v2 = accS[nt][2] * scale;
                float v3 = accS[nt][3] * scale;
                if (diag) {
                    if (kg     > qg0) v0 = -1e30f;
                    if (kg + 1 > qg0) v1 = -1e30f;
                    if (kg     > qg1) v2 = -1e30f;
                    if (kg + 1 > qg1) v3 = -1e30f;
                }
                accS[nt][0] = v0; accS[nt][1] = v1;
                accS[nt][2] = v2; accS[nt][3] = v3;
                mx0 = fmaxf(mx0, fmaxf(v0, v1));
                mx1 = fmaxf(mx1, fmaxf(v2, v3));
            }
            mx0 = fmaxf(mx0, __shfl_xor_sync(0xffffffffu, mx0, 1));
            mx0 = fmaxf(mx0, __shfl_xor_sync(0xffffffffu, mx0, 2));
            mx1 = fmaxf(mx1, __shfl_xor_sync(0xffffffffu, mx1, 1));
            mx1 = fmaxf(mx1, __shfl_xor_sync(0xffffffffu, mx1, 2));
            float mn0 = fmaxf(m0, mx0), mn1 = fmaxf(m1, mx1);
            corr0 = __expf(m0 - mn0); corr1 = __expf(m1 - mn1);

            float sum0 = 0.f, sum1 = 0.f;
            #pragma unroll
            for (int nt = 0; nt < 8; nt++) {
                float p0 = __expf(accS[nt][0] - mn0);
                float p1 = __expf(accS[nt][1] - mn0);
                float p2 = __expf(accS[nt][2] - mn1);
                float p3 = __expf(accS[nt][3] - mn1);
                sum0 += p0 + p1;
                sum1 += p2 + p3;
                const int ks = nt >> 1;
                const int s0 = (nt & 1) * 2;
                split2(p0, p1, pha[ks][s0],     pla[ks][s0]);
                split2(p2, p3, pha[ks][s0 + 1], pla[ks][s0 + 1]);
            }
            sum0 += __shfl_xor_sync(0xffffffffu, sum0, 1);
            sum0 += __shfl_xor_sync(0xffffffffu, sum0, 2);
            sum1 += __shfl_xor_sync(0xffffffffu, sum1, 1);
            sum1 += __shfl_xor_sync(0xffffffffu, sum1, 2);
            l0 = l0 * corr0 + sum0;  m0 = mn0;
            l1 = l1 * corr1 + sum1;  m1 = mn1;
        }

        CP_WAIT0();
        __syncthreads();
        if (j + 1 < j1) issue_k(j + 1);

        if (!wskip) {
            #pragma unroll
            for (int nt = 0; nt < 24; nt++) {
                accO[nt][0] *= corr0; accO[nt][1] *= corr0;
                accO[nt][2] *= corr1; accO[nt][3] *= corr1;
            }
            #pragma unroll
            for (int ks = 0; ks < 4; ks++) {
                unsigned rowoff = (unsigned)((ks * 16 + lm_rwi) * A3_ST) * 4u;
                #pragma unroll
                for (int g = 0; g < 12; g++) {
                    unsigned coloff = (unsigned)(g * 8 + lm_ncol / 2) * 4u;
                    unsigned bh0, bh1, bh2, bh3, bl0, bl1, bl2, bl3;
                    ldsm_x4_t(bh0, bh1, bh2, bh3, vh_base + rowoff + coloff);
                    ldsm_x4_t(bl0, bl1, bl2, bl3, vl_base + rowoff + coloff);
                    unsigned bfh[2], bfl[2];
                    bfh[0] = bh0; bfh[1] = bh1; bfl[0] = bl0; bfl[1] = bl1;
                    mma_bf16(accO[2 * g],     pha[ks], bfh);
                    mma_bf16(accO[2 * g],     pla[ks], bfh);
                    mma_bf16(accO[2 * g],     pha[ks], bfl);
                    bfh[0] = bh2; bfh[1] = bh3; bfl[0] = bl2; bfl[1] = bl3;
                    mma_bf16(accO[2 * g + 1], pha[ks], bfh);
                    mma_bf16(accO[2 * g + 1], pla[ks], bfh);
                    mma_bf16(accO[2 * g + 1], pha[ks], bfl);
                }
            }
        }

        __syncthreads();
        if (j + 1 < j1) issue_v(j + 1);
    }

    if (ch < 0) {
        float li0 = 1.0f / l0, li1 = 1.0f / l1;
        int row0 = b * SEQ + bi * 128 + w * 16 + gid;
        #pragma unroll
        for (int nt = 0; nt < 24; nt++) {
            int col = h * DH + nt * 8 + 2 * tig;
            size_t o0 = (size_t)row0 * DM + col;
            size_t o1 = (size_t)(row0 + 8) * DM + col;
            unsigned hw, lw;
            split2h(accO[nt][0] * li0, accO[nt][1] * li0, hw, lw);
            *reinterpret_cast<unsigned*>(atth + o0) = hw;
            *reinterpret_cast<unsigned*>(attl + o0) = lw;
            split2h(accO[nt][2] * li1, accO[nt][3] * li1, hw, lw);
            *reinterpret_cast<unsigned*>(atth + o1) = hw;
            *reinterpret_cast<unsigned*>(attl + o1) = lw;
        }
    } else {
        const int pidx = ((b * NH + h) << 2) + (bi - 4);
        float* po = g_po + ((size_t)ch * 128 + pidx) * (128 * 192);
        const int r0 = w * 16 + gid, r1 = r0 + 8;
        #pragma unroll
        for (int nt = 0; nt < 24; nt++) {
            int col = nt * 8 + 2 * tig;
            *reinterpret_cast<float2*>(po + r0 * 192 + col) = make_float2(accO[nt][0], accO[nt][1]);
            *reinterpret_cast<float2*>(po + r1 * 192 + col) = make_float2(accO[nt][2], accO[nt][3]);
        }
        if (tig == 0) {
            int mlb = (ch * 128 + pidx) * 128;
            g_pm[mlb + r0] = m0; g_pl[mlb + r0] = l0;
            g_pm[mlb + r1] = m1; g_pl[mlb + r1] = l1;
        }
    }
}

// ---------------- split-KV combine ------------------------------------------
__global__ __launch_bounds__(256) void attn_combine_kernel(
    __half* __restrict__ atth, __half* __restrict__ attl)
{
    const int pidx = blockIdx.x;
    const int b  = pidx >> 4;
    const int h  = (pidx >> 2) & 3;
    const int bi = 4 + (pidx & 3);
    const int r  = threadIdx.x >> 1;
    const int c0 = (threadIdx.x & 1) * 96;

    const float* po0 = g_po + ((size_t)0 * 128 + pidx) * (128 * 192) + r * 192 + c0;
    const float* po1 = g_po + ((size_t)1 * 128 + pidx) * (128 * 192) + r * 192 + c0;
    const int mlb0 = (0 * 128 + pidx) * 128 + r;
    const int mlb1 = (1 * 128 + pidx) * 128 + r;
    float m0 = g_pm[mlb0], l0 = g_pl[mlb0];
    float m1 = g_pm[mlb1], l1 = g_pl[mlb1];
    float m = fmaxf(m0, m1);
    float e0 = __expf(m0 - m), e1 = __expf(m1 - m);
    float linv = 1.0f / (e0 * l0 + e1 * l1);

    size_t go = (size_t)(b * SEQ + bi * 128 + r) * DM + h * DH + c0;
    #pragma unroll
    for (int c = 0; c < 96; c += 2) {
        float v0 = (e0 * po0[c]     + e1 * po1[c])     * linv;
        float v1 = (e0 * po0[c + 1] + e1 * po1[c + 1]) * linv;
        unsigned hw, lw;
        split2h(v0, v1, hw, lw);
        *reinterpret_cast<unsigned*>(atth + go + c) = hw;
        *reinterpret_cast<unsigned*>(attl + go + c) = lw;
    }
}

// ---------------- launch -----------------------------------------------
extern "C" void kernel_launch(void* const* d_in, const int* in_sizes, int n_in,
                              void* d_out, int out_size)
{
    const float* x   = (const float*)d_in[0];
    const float* W1  = (const float*)d_in[2];
    const float* b1  = (const float*)d_in[3];
    const float* W3  = (const float*)d_in[4];
    const float* b3  = (const float*)d_in[5];
    const float* W2  = (const float*)d_in[6];
    const float* b2  = (const float*)d_in[7];
    const float* W4  = (const float*)d_in[8];
    const float* b4  = (const float*)d_in[9];
    const float* g1  = (const float*)d_in[10];
    const float* be1 = (const float*)d_in[11];
    const float* g2  = (const float*)d_in[12];
    const float* be2 = (const float*)d_in[13];
    float* out = (float*)d_out;

    float *x1;
    cudaGetSymbolAddress((void**)&x1, g_x1);
    __nv_bfloat16 *qkvh, *qkvl, *xnh, *xnl, *w1h, *w1l;
    __half *atth, *attl, *xn2h, *xn2l, *hh, *hl, *w3h, *w2h, *w4h;
    cudaGetSymbolAddress((void**)&qkvh, g_qkvh); cudaGetSymbolAddress((void**)&qkvl, g_qkvl);
    cudaGetSymbolAddress((void**)&xnh,  g_xnh);  cudaGetSymbolAddress((void**)&xnl,  g_xnl);
    cudaGetSymbolAddress((void**)&atth, g_atth); cudaGetSymbolAddress((void**)&attl, g_attl);
    cudaGetSymbolAddress((void**)&xn2h, g_xn2h); cudaGetSymbolAddress((void**)&xn2l, g_xn2l);
    cudaGetSymbolAddress((void**)&hh,   g_hh);   cudaGetSymbolAddress((void**)&hl,   g_hl);
    cudaGetSymbolAddress((void**)&w1h,  g_w1h);  cudaGetSymbolAddress((void**)&w1l,  g_w1l);
    cudaGetSymbolAddress((void**)&w3h,  g_w3h);
    cudaGetSymbolAddress((void**)&w2h,  g_w2h);
    cudaGetSymbolAddress((void**)&w4h,  g_w4h);

    cudaFuncSetAttribute(attn_v5_kernel,
                         cudaFuncAttributeMaxDynamicSharedMemorySize, ATT3_SMEM_BYTES);
    cudaFuncSetAttribute(bgemm3_kernel<1>,
                         cudaFuncAttributeMaxDynamicSharedMemorySize, GEMM3_SMEM);
    cudaFuncSetAttribute(bgemm3_kernel<2>,
                         cudaFuncAttributeMaxDynamicSharedMemorySize, GEMM3_SMEM);
    cudaFuncSetAttribute(bgemm5_kernel<false,0>,
                         cudaFuncAttributeMaxDynamicSharedMemorySize, GEMM5_SMEM);
    cudaFuncSetAttribute(bgemm5_kernel<true,1>,
                         cudaFuncAttributeMaxDynamicSharedMemorySize, GEMM5_SMEM);

    float* pres = out + XOUT_ELEMS;
    bool has_present = ((size_t)out_size >= XOUT_ELEMS + PRES_ELEMS);

    // 0) weight prep
    wsplit_kernel<<<dim3(D3/32, DM/32), 256>>>(W1, w1h, w1l, DM, D3);
    wsplit_h_kernel<<<dim3(DM/32, DM/32), 256>>>(W3, w3h, DM, DM);
    wsplit_h_kernel<<<dim3(D4/32, DM/32), 256>>>(W2, w2h, DM, D4);
    wsplit_h_kernel<<<dim3(DM/32, D4/32), 256>>>(W4, w4h, D4, DM);

    // 1) LN1 -> bf16 split
    ln_kernel<false><<<ROWS, 256>>>(x, g1, be1, xnh, xnl);

    // 2) qkv = xn @ W1 + b1 -> bf16 split (+ present)
    if (has_present) {
        bgemm3_kernel<2><<<dim3(D3/128, ROWS/128), 256, GEMM3_SMEM>>>(
            xnh, xnl, w1h, w1l, b1, qkvh, qkvl, pres, ROWS, D3, DM);
    } else {
        bgemm3_kernel<1><<<dim3(D3/128, ROWS/128), 256, GEMM3_SMEM>>>(
            xnh, xnl, w1h, w1l, b1, qkvh, qkvl, nullptr, ROWS, D3, DM);
    }

    // 3) attention: split-KV main + combine -> fp16 split att
    attn_v5_kernel<<<dim3(12, NH, BS), 256, ATT3_SMEM_BYTES>>>(qkvh, qkvl, atth, attl);
    attn_combine_kernel<<<128, 256>>>(atth, attl);

    // 4) x1 = att @ W3 + b3 + x (fp16 2-pass, float out)
    bgemm5_kernel<false,0><<<dim3(DM/128, ROWS/128), 256, GEMM5_SMEM>>>(
        atth, attl, w3h, b3, x, x1, nullptr, nullptr, ROWS, DM, DM);

    // 5) LN2 -> fp16 split
    ln_kernel<true><<<ROWS, 256>>>(x1, g2, be2, xn2h, xn2l);

    // 6) h = gelu(xn2 @ W2 + b2) -> fp16 split out
    bgemm5_kernel<true,1><<<dim3(D4/128, ROWS/128), 256, GEMM5_SMEM>>>(
        xn2h, xn2l, w2h, b2, nullptr, nullptr, hh, hl, ROWS, D4, DM);

    // 7) out = h @ W4 + b4 + x1 (fp16 2-pass, float out)
    bgemm5_kernel<false,0><<<dim3(DM/128, ROWS/128), 256, GEMM5_SMEM>>>(
        hh, hl, w4h, b4, x1, out, nullptr, nullptr, ROWS, DM, D4);
}

// round 12
// speedup vs baseline: 1.3950x; 1.0137x over previous
#include <cuda_runtime.h>
#include <cuda_bf16.h>
#include <cuda_fp16.h>
#include <math.h>

// ---------------- problem constants ----------------
#define BS   8
#define SEQ  1024
#define DM   768
#define NH   4
#define DH   192
#define ROWS (BS*SEQ)          // 8192
#define D3   (3*DM)            // 2304
#define D4   (4*DM)            // 3072
#define D2   (2*DM)            // 1536

#define XOUT_ELEMS   ((size_t)ROWS*DM)
#define PRES_ELEMS   ((size_t)BS*2*NH*SEQ*DH)

// ---------------- scratch (device globals) ---------------------------------
__device__ __align__(256) float g_x1 [ROWS*DM];

__device__ __align__(256) __half g_qkh[(size_t)ROWS*D2], g_qkl[(size_t)ROWS*D2];
__device__ __align__(256) __half g_vh [(size_t)ROWS*DM];
__device__ __align__(256) __half g_xnh [ROWS*DM],  g_xnl [ROWS*DM];
__device__ __align__(256) __half g_atth[ROWS*DM],  g_attl[ROWS*DM];
__device__ __align__(256) __half g_xn2h[ROWS*DM],  g_xn2l[ROWS*DM];
__device__ __align__(256) __half g_hh[(size_t)ROWS*D4], g_hl[(size_t)ROWS*D4];

// transposed weights: [N][K]
__device__ __align__(256) __half g_w1h[(size_t)D3*DM], g_w1l[(size_t)D3*DM];  // fp16 split
__device__ __align__(256) __half g_w3h[(size_t)DM*DM];                         // fp16 single
__device__ __align__(256) __half g_w2h[(size_t)D4*DM];
__device__ __align__(256) __half g_w4h[(size_t)DM*D4];

// split-KV partials
__device__ __align__(256) float g_po[(size_t)2*128*128*192];
__device__ __align__(256) float g_pm[2*128*128];
__device__ __align__(256) float g_pl[2*128*128];

__device__ const int c_bi[12] = {7,6,3,5,7,2,4,6,5,1,4,0};
__device__ const int c_ch[12] = {1,1,-1,1,0,-1,1,0,0,-1,0,-1};

// ---------------- helpers ---------------------------------------------------
__device__ __forceinline__ void split2h(float x0, float x1, unsigned &hi, unsigned &lo) {
    __half h0 = __float2half_rn(x0);
    __half h1 = __float2half_rn(x1);
    __half l0 = __float2half_rn(x0 - __half2float(h0));
    __half l1 = __float2half_rn(x1 - __half2float(h1));
    hi = ((unsigned)__half_as_ushort(h1) << 16) | (unsigned)__half_as_ushort(h0);
    lo = ((unsigned)__half_as_ushort(l1) << 16) | (unsigned)__half_as_ushort(l0);
}

__device__ __forceinline__ void mma_f16(float c[4], const unsigned a[4], const unsigned b[2]) {
    asm volatile(
        "mma.sync.aligned.m16n8k16.row.col.f32.f16.f16.f32 "
        "{%0,%1,%2,%3}, {%4,%5,%6,%7}, {%8,%9}, {%0,%1,%2,%3};\n"
        : "+f"(c[0]), "+f"(c[1]), "+f"(c[2]), "+f"(c[3])
        : "r"(a[0]), "r"(a[1]), "r"(a[2]), "r"(a[3]), "r"(b[0]), "r"(b[1]));
}

__device__ __forceinline__ void ldsm_x4(unsigned r[4], unsigned addr) {
    asm volatile("ldmatrix.sync.aligned.m8n8.x4.shared.b16 {%0,%1,%2,%3}, [%4];"
        : "=r"(r[0]), "=r"(r[1]), "=r"(r[2]), "=r"(r[3]) : "r"(addr));
}

__device__ __forceinline__ void ldsm_x4_t(unsigned &r0, unsigned &r1, unsigned &r2, unsigned &r3, unsigned saddr) {
    asm volatile("ldmatrix.sync.aligned.m8n8.x4.trans.shared.b16 {%0,%1,%2,%3}, [%4];"
        : "=r"(r0), "=r"(r1), "=r"(r2), "=r"(r3) : "r"(saddr));
}

#define CP16(dst, src) asm volatile("cp.async.cg.shared.global [%0], [%1], 16;\n" :: "r"(dst), "l"(src))
#define CP_COMMIT() asm volatile("cp.async.commit_group;\n" ::)
#define CP_WAIT0()  asm volatile("cp.async.wait_group 0;\n" ::)
#define CP_WAIT1()  asm volatile("cp.async.wait_group 1;\n" ::)

__device__ __forceinline__ float gelu_tanh_f(float x) {
    float x3 = x * x * x;
    float t  = tanhf(0.7978845608028654f * (x + 0.044715f * x3));
    return 0.5f * x * (1.0f + t);
}

// ---------------- weight transpose + split (fp16 hi/lo) ---------------------
__global__ __launch_bounds__(256) void wsplit_h2_kernel(
    const float* __restrict__ W, __half* __restrict__ Th,
    __half* __restrict__ Tl, int K, int N)
{
    __shared__ float t[32][33];
    int n0 = blockIdx.x * 32, k0 = blockIdx.y * 32;
    int tx = threadIdx.x & 31, ty = threadIdx.x >> 5;
    #pragma unroll
    for (int j = 0; j < 4; j++)
        t[ty + 8 * j][tx] = W[(size_t)(k0 + ty + 8 * j) * N + n0 + tx];
    __syncthreads();
    #pragma unroll
    for (int j = 0; j < 4; j++) {
        float v = t[tx][ty + 8 * j];
        __half hi = __float2half_rn(v);
        size_t o = (size_t)(n0 + ty + 8 * j) * K + k0 + tx;
        Th[o] = hi;
        Tl[o] = __float2half_rn(v - __half2float(hi));
    }
}

// ---------------- weight transpose (fp16 single) ----------------------------
__global__ __launch_bounds__(256) void wsplit_h_kernel(
    const float* __restrict__ W, __half* __restrict__ Th, int K, int N)
{
    __shared__ float t[32][33];
    int n0 = blockIdx.x * 32, k0 = blockIdx.y * 32;
    int tx = threadIdx.x & 31, ty = threadIdx.x >> 5;
    #pragma unroll
    for (int j = 0; j < 4; j++)
        t[ty + 8 * j][tx] = W[(size_t)(k0 + ty + 8 * j) * N + n0 + tx];
    __syncthreads();
    #pragma unroll
    for (int j = 0; j < 4; j++) {
        size_t o = (size_t)(n0 + ty + 8 * j) * K + k0 + tx;
        Th[o] = __float2half_rn(t[tx][ty + 8 * j]);
    }
}

// ---------------- LayerNorm -> fp16 split ------------------------------------
__global__ __launch_bounds__(256) void ln_kernel(
    const float* __restrict__ x, const float* __restrict__ gamma,
    const float* __restrict__ beta, __half* __restrict__ oh, __half* __restrict__ ol)
{
    int row = blockIdx.x;
    int tid = threadIdx.x;
    const float* xr = x + (size_t)row * DM;
    float v0 = xr[tid], v1 = xr[tid + 256], v2 = xr[tid + 512];
    float s  = v0 + v1 + v2;
    float sq = v0*v0 + v1*v1 + v2*v2;
    #pragma unroll
    for (int o = 16; o > 0; o >>= 1) {
        s  += __shfl_xor_sync(0xffffffffu, s,  o);
        sq += __shfl_xor_sync(0xffffffffu, sq, o);
    }
    __shared__ float ss[8], ssq[8];
    __shared__ float mu_s, rs_s;
    int w = tid >> 5, l = tid & 31;
    if (l == 0) { ss[w] = s; ssq[w] = sq; }
    __syncthreads();
    if (tid == 0) {
        float S = 0.f, SQ = 0.f;
        #pragma unroll
        for (int i = 0; i < 8; i++) { S += ss[i]; SQ += ssq[i]; }
        float mu = S * (1.0f / DM);
        float var = SQ * (1.0f / DM) - mu * mu;
        mu_s = mu;
        rs_s = rsqrtf(var + 1e-3f);
    }
    __syncthreads();
    float mu = mu_s, rs = rs_s;
    size_t ro = (size_t)row * DM;
    #pragma unroll
    for (int q = 0; q < 3; q++) {
        int c = tid + q * 256;
        float v = (q == 0 ? v0 : (q == 1 ? v1 : v2));
        float y = (v - mu) * rs * gamma[c] + beta[c];
        __half hi = __float2half_rn(y);
        oh[ro + c] = hi;
        ol[ro + c] = __float2half_rn(y - __half2float(hi));
    }
}

// ---------------- GEMM f3: fp16 3-pass (A split, B split) --------------------
// Used for QK: out split fp16 (+ optional K-present for n0 in [DM,2DM))
#define SROW3 80
#define MAT3  (128*SROW3)
#define STG3  (4*MAT3)
#define GEMM3_SMEM (2*STG3)

__global__ __launch_bounds__(256, 2) void bgemm3f_kernel(
    const __half* __restrict__ Ah, const __half* __restrict__ Al,
    const __half* __restrict__ Bh, const __half* __restrict__ Bl,
    const float* __restrict__ bias,
    __half* __restrict__ Ch, __half* __restrict__ Cl,
    float* __restrict__ pres, int M, int N, int K)
{
    extern __shared__ unsigned char sm3[];
    const int tid = threadIdx.x;
    const int w = tid >> 5, l = tid & 31;
    const int wm = w & 1, wn = w >> 1;
    const int gid = l >> 2, tig = l & 3;
    const int bx = blockIdx.x, by = blockIdx.y;
    const int T = K >> 5;

    const unsigned smem_base = (unsigned)__cvta_generic_to_shared(sm3);

    const __half* A0 = Ah + (size_t)(by * 128) * K;
    const __half* A1 = Al + (size_t)(by * 128) * K;
    const __half* B0 = Bh + (size_t)(bx * 128) * K;
    const __half* B1 = Bl + (size_t)(bx * 128) * K;

    const int rl = l & 7, sel = l >> 3;
    const unsigned a_off = (unsigned)((rl + 8 * (sel & 1)) * SROW3 + 16 * (sel >> 1));
    const unsigned b_off = (unsigned)((rl + 8 * (sel >> 1)) * SROW3 + 16 * (sel & 1));

    float acc[4][4][4];
    #pragma unroll
    for (int i = 0; i < 4; i++)
        #pragma unroll
        for (int j = 0; j < 4; j++)
            #pragma unroll
            for (int c = 0; c < 4; c++) acc[i][j][c] = 0.f;

    auto issue = [&](int t) {
        unsigned sb = smem_base + (t & 1) * STG3;
        int k0 = t << 5;
        #pragma unroll
        for (int i = 0; i < 2; i++) {
            int chunk = tid + (i << 8);
            int r = chunk >> 2, c = chunk & 3;
            unsigned doff = (unsigned)(r * SROW3 + c * 16);
            size_t goff = (size_t)r * K + k0 + c * 8;
            CP16(sb + doff,            (const void*)(A0 + goff));
            CP16(sb + MAT3 + doff,     (const void*)(A1 + goff));
            CP16(sb + 2 * MAT3 + doff, (const void*)(B0 + goff));
            CP16(sb + 3 * MAT3 + doff, (const void*)(B1 + goff));
        }
        CP_COMMIT();
    };

    issue(0);
    if (T > 1) issue(1);

    for (int t = 0; t < T; t++) {
        if (t + 1 < T) CP_WAIT1(); else CP_WAIT0();
        __syncthreads();

        unsigned sb = smem_base + (t & 1) * STG3;
        #pragma unroll
        for (int ks = 0; ks < 2; ks++) {
            unsigned bh[2][4], bl4[2][4];
            #pragma unroll
            for (int p = 0; p < 2; p++) {
                unsigned bd = sb + 2 * MAT3 + (unsigned)((wn * 32 + p * 16) * SROW3 + ks * 32) + b_off;
                ldsm_x4(bh[p], bd);
                ldsm_x4(bl4[p], bd + MAT3);
            }
            #pragma unroll
            for (int am = 0; am < 4; am++) {
                unsigned ah[4], al4[4];
                unsigned ad = sb + (unsigned)((wm * 64 + am * 16) * SROW3 + ks * 32) + a_off;
                ldsm_x4(ah, ad);
                ldsm_x4(al4, ad + MAT3);
                #pragma unroll
                for (int an = 0; an < 4; an++) {
                    const int p = an >> 1, q = (an & 1) * 2;
                    unsigned bfh[2] = { bh[p][q], bh[p][q + 1] };
                    unsigned bfl[2] = { bl4[p][q], bl4[p][q + 1] };
                    mma_f16(acc[am][an], ah, bfh);
                    mma_f16(acc[am][an], al4, bfh);
                    mma_f16(acc[am][an], ah, bfl);
                }
            }
        }
        __syncthreads();
        if (t + 2 < T) issue(t + 2);
    }

    #pragma unroll
    for (int am = 0; am < 4; am++) {
        int r0 = by * 128 + wm * 64 + am * 16 + gid;
        int r1 = r0 + 8;
        #pragma unroll
        for (int an = 0; an < 4; an++) {
            int n0 = bx * 128 + wn * 32 + an * 8 + 2 * tig;
            float bv0 = bias[n0], bv1 = bias[n0 + 1];
            size_t o0 = (size_t)r0 * N + n0;
            size_t o1 = (size_t)r1 * N + n0;
            float v0 = acc[am][an][0] + bv0;
            float v1 = acc[am][an][1] + bv1;
            float v2 = acc[am][an][2] + bv0;
            float v3 = acc[am][an][3] + bv1;
            unsigned hw, lw;
            split2h(v0, v1, hw, lw);
            *reinterpret_cast<unsigned*>(Ch + o0) = hw;
            *reinterpret_cast<unsigned*>(Cl + o0) = lw;
            split2h(v2, v3, hw, lw);
            *reinterpret_cast<unsigned*>(Ch + o1) = hw;
            *reinterpret_cast<unsigned*>(Cl + o1) = lw;
            if (pres && n0 >= DM) {      // K columns -> present[.,0,...]
                int local = n0 - DM;
                int hh = local / DH, dd = local % DH;
                int b0 = r0 >> 10, s0 = r0 & 1023;
                int b1 = r1 >> 10, s1 = r1 & 1023;
                size_t p0 = (((size_t)(b0 * 2) * NH + hh) * SEQ + s0) * DH + dd;
                size_t p1 = (((size_t)(b1 * 2) * NH + hh) * SEQ + s1) * DH + dd;
                *reinterpret_cast<float2*>(pres + p0) = make_float2(v0, v1);
                *reinterpret_cast<float2*>(pres + p1) = make_float2(v2, v3);
            }
        }
    }
}

// ---------------- GEMM v5: fp16 2-pass (A split, B single) ------------------
// OMODE: 0 = float out (+res), 1 = split fp16 out, 2 = single fp16 out (+V-present)
#define STG5  (3*MAT3)
#define GEMM5_SMEM (2*STG5)

template<bool GELU, int OMODE>
__global__ __launch_bounds__(256, 2) void bgemm5_kernel(
    const __half* __restrict__ Ah, const __half* __restrict__ Al,
    const __half* __restrict__ Bh,
    const float* __restrict__ bias, const float* __restrict__ res,
    float* __restrict__ C, __half* __restrict__ Ch, __half* __restrict__ Cl,
    float* __restrict__ pres, int M, int N, int K)
{
    extern __shared__ unsigned char sm5[];
    const int tid = threadIdx.x;
    const int w = tid >> 5, l = tid & 31;
    const int wm = w & 1, wn = w >> 1;
    const int gid = l >> 2, tig = l & 3;
    const int bx = blockIdx.x, by = blockIdx.y;
    const int T = K >> 5;

    const unsigned smem_base = (unsigned)__cvta_generic_to_shared(sm5);

    const __half* A0 = Ah + (size_t)(by * 128) * K;
    const __half* A1 = Al + (size_t)(by * 128) * K;
    const __half* B0 = Bh + (size_t)(bx * 128) * K;

    const int rl = l & 7, sel = l >> 3;
    const unsigned a_off = (unsigned)((rl + 8 * (sel & 1)) * SROW3 + 16 * (sel >> 1));
    const unsigned b_off = (unsigned)((rl + 8 * (sel >> 1)) * SROW3 + 16 * (sel & 1));

    float acc[4][4][4];
    #pragma unroll
    for (int i = 0; i < 4; i++)
        #pragma unroll
        for (int j = 0; j < 4; j++)
            #pragma unroll
            for (int c = 0; c < 4; c++) acc[i][j][c] = 0.f;

    auto issue = [&](int t) {
        unsigned sb = smem_base + (t & 1) * STG5;
        int k0 = t << 5;
        #pragma unroll
        for (int i = 0; i < 2; i++) {
            int chunk = tid + (i << 8);
            int r = chunk >> 2, c = chunk & 3;
            unsigned doff = (unsigned)(r * SROW3 + c * 16);
            size_t goff = (size_t)r * K + k0 + c * 8;
            CP16(sb + doff,            (const void*)(A0 + goff));
            CP16(sb + MAT3 + doff,     (const void*)(A1 + goff));
            CP16(sb + 2 * MAT3 + doff, (const void*)(B0 + goff));
        }
        CP_COMMIT();
    };

    issue(0);
    if (T > 1) issue(1);

    for (int t = 0; t < T; t++) {
        if (t + 1 < T) CP_WAIT1(); else CP_WAIT0();
        __syncthreads();

        unsigned sb = smem_base + (t & 1) * STG5;
        #pragma unroll
        for (int ks = 0; ks < 2; ks++) {
            unsigned bh[2][4];
            #pragma unroll
            for (int p = 0; p < 2; p++) {
                unsigned bd = sb + 2 * MAT3 + (unsigned)((wn * 32 + p * 16) * SROW3 + ks * 32) + b_off;
                ldsm_x4(bh[p], bd);
            }
            #pragma unroll
            for (int am = 0; am < 4; am++) {
                unsigned ah[4], al4[4];
                unsigned ad = sb + (unsigned)((wm * 64 + am * 16) * SROW3 + ks * 32) + a_off;
                ldsm_x4(ah, ad);
                ldsm_x4(al4, ad + MAT3);
                #pragma unroll
                for (int an = 0; an < 4; an++) {
                    const int p = an >> 1, q = (an & 1) * 2;
                    unsigned bfh[2] = { bh[p][q], bh[p][q + 1] };
                    mma_f16(acc[am][an], ah, bfh);
                    mma_f16(acc[am][an], al4, bfh);
                }
            }
        }
        __syncthreads();
        if (t + 2 < T) issue(t + 2);
    }

    #pragma unroll
    for (int am = 0; am < 4; am++) {
        int r0 = by * 128 + wm * 64 + am * 16 + gid;
        int r1 = r0 + 8;
        #pragma unroll
        for (int an = 0; an < 4; an++) {
            int n0 = bx * 128 + wn * 32 + an * 8 + 2 * tig;
            float bv0 = bias[n0], bv1 = bias[n0 + 1];
            size_t o0 = (size_t)r0 * N + n0;
            size_t o1 = (size_t)r1 * N + n0;
            float v0 = acc[am][an][0] + bv0;
            float v1 = acc[am][an][1] + bv1;
            float v2 = acc[am][an][2] + bv0;
            float v3 = acc[am][an][3] + bv1;
            if (res) {
                v0 += res[o0]; v1 += res[o0 + 1];
                v2 += res[o1]; v3 += res[o1 + 1];
            }
            if (GELU) {
                v0 = gelu_tanh_f(v0); v1 = gelu_tanh_f(v1);
                v2 = gelu_tanh_f(v2); v3 = gelu_tanh_f(v3);
            }
            if (OMODE == 0) {
                *reinterpret_cast<float2*>(C + o0) = make_float2(v0, v1);
                *reinterpret_cast<float2*>(C + o1) = make_float2(v2, v3);
            } else if (OMODE == 1) {
                unsigned hw, lw;
                split2h(v0, v1, hw, lw);
                *reinterpret_cast<unsigned*>(Ch + o0) = hw;
                *reinterpret_cast<unsigned*>(Cl + o0) = lw;
                split2h(v2, v3, hw, lw);
                *reinterpret_cast<unsigned*>(Ch + o1) = hw;
                *reinterpret_cast<unsigned*>(Cl + o1) = lw;
            } else {  // OMODE 2: single fp16 out + V-present
                __half h0 = __float2half_rn(v0), h1 = __float2half_rn(v1);
                __half h2 = __float2half_rn(v2), h3 = __float2half_rn(v3);
                *reinterpret_cast<unsigned*>(Ch + o0) =
                    ((unsigned)__half_as_ushort(h1) << 16) | (unsigned)__half_as_ushort(h0);
                *reinterpret_cast<unsigned*>(Ch + o1) =
                    ((unsigned)__half_as_ushort(h3) << 16) | (unsigned)__half_as_ushort(h2);
                if (pres) {
                    int hh = n0 / DH, dd = n0 % DH;
                    int b0 = r0 >> 10, s0 = r0 & 1023;
                    int b1 = r1 >> 10, s1 = r1 & 1023;
                    size_t p0 = (((size_t)(b0 * 2 + 1) * NH + hh) * SEQ + s0) * DH + dd;
                    size_t p1 = (((size_t)(b1 * 2 + 1) * NH + hh) * SEQ + s1) * DH + dd;
                    *reinterpret_cast<float2*>(pres + p0) = make_float2(v0, v1);
                    *reinterpret_cast<float2*>(pres + p1) = make_float2(v2, v3);
                }
            }
        }
    }
}

// ---------------- attention v6: fp16, split-KV, PV 2-pass -------------------
#define A6_ST 100
#define A6_QH 0
#define A6_QL 12800
#define A6_KH 25600
#define A6_KL 32000
#define A6_VH 38400
#define ATT6_SMEM_BYTES (44800*4)

__global__ __launch_bounds__(256, 1) void attn_v6_kernel(
    const __half* __restrict__ qkh, const __half* __restrict__ qkl,
    const __half* __restrict__ vbuf,
    __half* __restrict__ atth, __half* __restrict__ attl)
{
    extern __shared__ unsigned smu[];
    const int type = blockIdx.x;
    const int bi = c_bi[type];
    const int ch = c_ch[type];
    const int h  = blockIdx.y;
    const int b  = blockIdx.z;
    const int tid = threadIdx.x;
    const int w = tid >> 5, l = tid & 31;
    const int gid = l >> 2, tig = l & 3;

    const int j0 = (ch == 1) ? bi : 0;
    const int j1 = (ch == 0) ? bi : 2 * bi + 2;

    const float scale = 13.856406460551018f;   // sqrt(192) (faithful bug)
    const unsigned sbase = (unsigned)__cvta_generic_to_shared(smu);

    const int kcol = DM + h * DH;
    const int vcol = h * DH;

    auto issue_k = [&](int j) {
        const size_t row0 = (size_t)(b * SEQ + j * 64);
        #pragma unroll
        for (int i = 0; i < 6; i++) {
            int c = tid + (i << 8);
            int r = c / 24, cc2 = c % 24;
            unsigned doff = (unsigned)((r * A6_ST + cc2 * 4) * 4);
            size_t gk = (row0 + r) * D2 + kcol + cc2 * 8;
            CP16(sbase + A6_KH * 4 + doff, (const void*)(qkh + gk));
            CP16(sbase + A6_KL * 4 + doff, (const void*)(qkl + gk));
        }
        CP_COMMIT();
    };
    auto issue_v = [&](int j) {
        const size_t row0 = (size_t)(b * SEQ + j * 64);
        #pragma unroll
        for (int i = 0; i < 6; i++) {
            int c = tid + (i << 8);
            int r = c / 24, cc2 = c % 24;
            unsigned doff = (unsigned)((r * A6_ST + cc2 * 4) * 4);
            size_t gv = (row0 + r) * DM + vcol + cc2 * 8;
            CP16(sbase + A6_VH * 4 + doff, (const void*)(vbuf + gv));
        }
        CP_COMMIT();
    };

    // preload Q, K(j0), V(j0)
    {
        const size_t row0 = (size_t)(b * SEQ + bi * 128);
        const int qcol = h * DH;
        #pragma unroll
        for (int i = 0; i < 12; i++) {
            int c = tid + (i << 8);
            int r = c / 24, cc2 = c % 24;
            unsigned doff = (unsigned)((r * A6_ST + cc2 * 4) * 4);
            size_t goff = (row0 + r) * D2 + qcol + cc2 * 8;
            CP16(sbase + A6_QH * 4 + doff, (const void*)(qkh + goff));
            CP16(sbase + A6_QL * 4 + doff, (const void*)(qkl + goff));
        }
        CP_COMMIT();
    }
    issue_k(j0);
    issue_v(j0);

    float m0 = -1e30f, m1 = -1e30f, l0 = 0.f, l1 = 0.f;
    float accO[24][4];
    #pragma unroll
    for (int i = 0; i < 24; i++)
        #pragma unroll
        for (int c = 0; c < 4; c++) accO[i][c] = 0.f;

    const int lm_rwi  = (l & 7) + ((l >> 3) & 1) * 8;
    const int lm_ncol = (l >> 4) * 8;
    const unsigned vh_base = sbase + A6_VH * 4;

    const int qg0 = bi * 128 + w * 16 + gid;
    const int qg1 = qg0 + 8;

    for (int j = j0; j < j1; j++) {
        CP_WAIT1();
        __syncthreads();

        const bool diag = (j >= 2 * bi);
        const bool wskip = diag && (64 * j >= bi * 128 + w * 16 + 16);

        const unsigned* Qh = smu + A6_QH;
        const unsigned* Ql = smu + A6_QL;
        const unsigned* Kh = smu + A6_KH;
        const unsigned* Kl = smu + A6_KL;

        unsigned pha[4][4], pla[4][4];
        float corr0 = 1.f, corr1 = 1.f;

        if (!wskip) {
            float accS[8][4];
            #pragma unroll
            for (int i = 0; i < 8; i++)
                #pragma unroll
                for (int c = 0; c < 4; c++) accS[i][c] = 0.f;

            #pragma unroll
            for (int ks = 0; ks < 12; ks++) {
                int kp = ks * 8;
                unsigned ah[4], al[4];
                int a0 = (w * 16 + gid) * A6_ST + kp + tig;
                int a1 = a0 + 8 * A6_ST;
                ah[0] = Qh[a0]; ah[1] = Qh[a1]; ah[2] = Qh[a0 + 4]; ah[3] = Qh[a1 + 4];
                al[0] = Ql[a0]; al[1] = Ql[a1]; al[2] = Ql[a0 + 4]; al[3] = Ql[a1 + 4];
                #pragma unroll
                for (int nt = 0; nt < 8; nt++) {
                    int bb = (nt * 8 + gid) * A6_ST + kp + tig;
                    unsigned bh[2], bl2[2];
                    bh[0]  = Kh[bb]; bh[1]  = Kh[bb + 4];
                    bl2[0] = Kl[bb]; bl2[1] = Kl[bb + 4];
                    mma_f16(accS[nt], ah, bh);
                    mma_f16(accS[nt], al, bh);
                    mma_f16(accS[nt], ah, bl2);
                }
            }

            float mx0 = -1e30f, mx1 = -1e30f;
            #pragma unroll
            for (int nt = 0; nt < 8; nt++) {
                int kg = j * 64 + nt * 8 + 2 * tig;
                float v0 = accS[nt][0] * scale;
                float v1 = accS[nt][1] * scale;
                float v2 = accS[nt][2] * scale;
                float v3 = accS[nt][3] * scale;
                if (diag) {
                    if (kg     > qg0) v0 = -1e30f;
                    if (kg + 1 > qg0) v1 = -1e30f;
                    if (kg     > qg1) v2 = -1e30f;
                    if (kg + 1 > qg1) v3 = -1e30f;
                }
                accS[nt][0] = v0; accS[nt][1] = v1;
                accS[nt][2] = v2; accS[nt][3] = v3;
                mx0 = fmaxf(mx0, fmaxf(v0, v1));
                mx1 = fmaxf(mx1, fmaxf(v2, v3));
            }
            mx0 = fmaxf(mx0, __shfl_xor_sync(0xffffffffu, mx0, 1));
            mx0 = fmaxf(mx0, __shfl_xor_sync(0xffffffffu, mx0, 2));
            mx1 = fmaxf(mx1, __shfl_xor_sync(0xffffffffu, mx1, 1));
            mx1 = fmaxf(mx1, __shfl_xor_sync(0xffffffffu, mx1, 2));
            float mn0 = fmaxf(m0, mx0), mn1 = fmaxf(m1, mx1);
            corr0 = __expf(m0 - mn0); corr1 = __expf(m1 - mn1);

            float sum0 = 0.f, sum1 = 0.f;
            #pragma unroll
            for (int nt = 0; nt < 8; nt++) {
                float p0 = __expf(accS[nt][0] - mn0);
                float p1 = __expf(accS[nt][1] - mn0);
                float p2 = __expf(accS[nt][2] - mn1);
                float p3 = __expf(accS[nt][3] - mn1);
                sum0 += p0 + p1;
                sum1 += p2 + p3;
                const int ks = nt >> 1;
                const int s0 = (nt & 1) * 2;
                split2h(p0, p1, pha[ks][s0],     pla[ks][s0]);
                split2h(p2, p3, pha[ks][s0 + 1], pla[ks][s0 + 1]);
            }
            sum0 += __shfl_xor_sync(0xffffffffu, sum0, 1);
            sum0 += __shfl_xor_sync(0xffffffffu, sum0, 2);
            sum1 += __shfl_xor_sync(0xffffffffu, sum1, 1);
            sum1 += __shfl_xor_sync(0xffffffffu, sum1, 2);
            l0 = l0 * corr0 + sum0;  m0 = mn0;
            l1 = l1 * corr1 + sum1;  m1 = mn1;
        }

        CP_WAIT0();
        __syncthreads();
        if (j + 1 < j1) issue_k(j + 1);

        if (!wskip) {
            #pragma unroll
            for (int nt = 0; nt < 24; nt++) {
                accO[nt][0] *= corr0; accO[nt][1] *= corr0;
                accO[nt][2] *= corr1; accO[nt][3] *= corr1;
            }
            #pragma unroll
            for (int ks = 0; ks < 4; ks++) {
                unsigned rowoff = (unsigned)((ks * 16 + lm_rwi) * A6_ST) * 4u;
                #pragma unroll
                for (int g = 0; g < 12; g++) {
                    unsigned coloff = (unsigned)(g * 8 + lm_ncol / 2) * 4u;
                    unsigned bh0, bh1, bh2, bh3;
                    ldsm_x4_t(bh0, bh1, bh2, bh3, vh_base + rowoff + coloff);
                    unsigned bfh[2];
                    bfh[0] = bh0; bfh[1] = bh1;
                    mma_f16(accO[2 * g],     pha[ks], bfh);
                    mma_f16(accO[2 * g],     pla[ks], bfh);
                    bfh[0] = bh2; bfh[1] = bh3;
                    mma_f16(accO[2 * g + 1], pha[ks], bfh);
                    mma_f16(accO[2 * g + 1], pla[ks], bfh);
                }
            }
        }

        __syncthreads();
        if (j + 1 < j1) issue_v(j + 1);
    }

    if (ch < 0) {
        float li0 = 1.0f / l0, li1 = 1.0f / l1;
        int row0 = b * SEQ + bi * 128 + w * 16 + gid;
        #pragma unroll
        for (int nt = 0; nt < 24; nt++) {
            int col = h * DH + nt * 8 + 2 * tig;
            size_t o0 = (size_t)row0 * DM + col;
            size_t o1 = (size_t)(row0 + 8) * DM + col;
            unsigned hw, lw;
            split2h(accO[nt][0] * li0, accO[nt][1] * li0, hw, lw);
            *reinterpret_cast<unsigned*>(atth + o0) = hw;
            *reinterpret_cast<unsigned*>(attl + o0) = lw;
            split2h(accO[nt][2] * li1, accO[nt][3] * li1, hw, lw);
            *reinterpret_cast<unsigned*>(atth + o1) = hw;
            *reinterpret_cast<unsigned*>(attl + o1) = lw;
        }
    } else {
        const int pidx = ((b * NH + h) << 2) + (bi - 4);
        float* po = g_po + ((size_t)ch * 128 + pidx) * (128 * 192);
        const int r0 = w * 16 + gid, r1 = r0 + 8;
        #pragma unroll
        for (int nt = 0; nt < 24; nt++) {
            int col = nt * 8 + 2 * tig;
            *reinterpret_cast<float2*>(po + r0 * 192 + col) = make_float2(accO[nt][0], accO[nt][1]);
            *reinterpret_cast<float2*>(po + r1 * 192 + col) = make_float2(accO[nt][2], accO[nt][3]);
        }
        if (tig == 0) {
            int mlb = (ch * 128 + pidx) * 128;
            g_pm[mlb + r0] = m0; g_pl[mlb + r0] = l0;
            g_pm[mlb + r1] = m1; g_pl[mlb + r1] = l1;
        }
    }
}

// ---------------- split-KV combine ------------------------------------------
__global__ __launch_bounds__(256) void attn_combine_kernel(
    __half* __restrict__ atth, __half* __restrict__ attl)
{
    const int pidx = blockIdx.x;
    const int b  = pidx >> 4;
    const int h  = (pidx >> 2) & 3;
    const int bi = 4 + (pidx & 3);
    const int r  = threadIdx.x >> 1;
    const int c0 = (threadIdx.x & 1) * 96;

    const float* po0 = g_po + ((size_t)0 * 128 + pidx) * (128 * 192) + r * 192 + c0;
    const float* po1 = g_po + ((size_t)1 * 128 + pidx) * (128 * 192) + r * 192 + c0;
    const int mlb0 = (0 * 128 + pidx) * 128 + r;
    const int mlb1 = (1 * 128 + pidx) * 128 + r;
    float m0 = g_pm[mlb0], l0 = g_pl[mlb0];
    float m1 = g_pm[mlb1], l1 = g_pl[mlb1];
    float m = fmaxf(m0, m1);
    float e0 = __expf(m0 - m), e1 = __expf(m1 - m);
    float linv = 1.0f / (e0 * l0 + e1 * l1);

    size_t go = (size_t)(b * SEQ + bi * 128 + r) * DM + h * DH + c0;
    #pragma unroll
    for (int c = 0; c < 96; c += 2) {
        float v0 = (e0 * po0[c]     + e1 * po1[c])     * linv;
        float v1 = (e0 * po0[c + 1] + e1 * po1[c + 1]) * linv;
        unsigned hw, lw;
        split2h(v0, v1, hw, lw);
        *reinterpret_cast<unsigned*>(atth + go + c) = hw;
        *reinterpret_cast<unsigned*>(attl + go + c) = lw;
    }
}

// ---------------- launch -----------------------------------------------
extern "C" void kernel_launch(void* const* d_in, const int* in_sizes, int n_in,
                              void* d_out, int out_size)
{
    const float* x   = (const float*)d_in[0];
    const float* W1  = (const float*)d_in[2];
    const float* b1  = (const float*)d_in[3];
    const float* W3  = (const float*)d_in[4];
    const float* b3  = (const float*)d_in[5];
    const float* W2  = (const float*)d_in[6];
    const float* b2  = (const float*)d_in[7];
    const float* W4  = (const float*)d_in[8];
    const float* b4  = (const float*)d_in[9];
    const float* g1  = (const float*)d_in[10];
    const float* be1 = (const float*)d_in[11];
    const float* g2  = (const float*)d_in[12];
    const float* be2 = (const float*)d_in[13];
    float* out = (float*)d_out;

    float *x1;
    cudaGetSymbolAddress((void**)&x1, g_x1);
    __half *qkh, *qkl, *vh, *xnh, *xnl, *atth, *attl, *xn2h, *xn2l, *hh, *hl;
    __half *w1h, *w1l, *w3h, *w2h, *w4h;
    cudaGetSymbolAddress((void**)&qkh,  g_qkh);  cudaGetSymbolAddress((void**)&qkl,  g_qkl);
    cudaGetSymbolAddress((void**)&vh,   g_vh);
    cudaGetSymbolAddress((void**)&xnh,  g_xnh);  cudaGetSymbolAddress((void**)&xnl,  g_xnl);
    cudaGetSymbolAddress((void**)&atth, g_atth); cudaGetSymbolAddress((void**)&attl, g_attl);
    cudaGetSymbolAddress((void**)&xn2h, g_xn2h); cudaGetSymbolAddress((void**)&xn2l, g_xn2l);
    cudaGetSymbolAddress((void**)&hh,   g_hh);   cudaGetSymbolAddress((void**)&hl,   g_hl);
    cudaGetSymbolAddress((void**)&w1h,  g_w1h);  cudaGetSymbolAddress((void**)&w1l,  g_w1l);
    cudaGetSymbolAddress((void**)&w3h,  g_w3h);
    cudaGetSymbolAddress((void**)&w2h,  g_w2h);
    cudaGetSymbolAddress((void**)&w4h,  g_w4h);

    cudaFuncSetAttribute(attn_v6_kernel,
                         cudaFuncAttributeMaxDynamicSharedMemorySize, ATT6_SMEM_BYTES);
    cudaFuncSetAttribute(bgemm3f_kernel,
                         cudaFuncAttributeMaxDynamicSharedMemorySize, GEMM3_SMEM);
    cudaFuncSetAttribute(bgemm5_kernel<false,0>,
                         cudaFuncAttributeMaxDynamicSharedMemorySize, GEMM5_SMEM);
    cudaFuncSetAttribute(bgemm5_kernel<true,1>,
                         cudaFuncAttributeMaxDynamicSharedMemorySize, GEMM5_SMEM);
    cudaFuncSetAttribute(bgemm5_kernel<false,2>,
                         cudaFuncAttributeMaxDynamicSharedMemorySize, GEMM5_SMEM);

    float* pres = out + XOUT_ELEMS;
    bool has_present = ((size_t)out_size >= XOUT_ELEMS + PRES_ELEMS);
    float* presp = has_present ? pres : nullptr;

    // 0) weight prep
    wsplit_h2_kernel<<<dim3(D3/32, DM/32), 256>>>(W1, w1h, w1l, DM, D3);
    wsplit_h_kernel<<<dim3(DM/32, DM/32), 256>>>(W3, w3h, DM, DM);
    wsplit_h_kernel<<<dim3(D4/32, DM/32), 256>>>(W2, w2h, DM, D4);
    wsplit_h_kernel<<<dim3(DM/32, D4/32), 256>>>(W4, w4h, D4, DM);

    // 1) LN1 -> fp16 split
    ln_kernel<<<ROWS, 256>>>(x, g1, be1, xnh, xnl);

    // 2a) qk = xn @ W1[:, :2DM] (fp16 3-pass) -> split fp16 (+ K present)
    bgemm3f_kernel<<<dim3(D2/128, ROWS/128), 256, GEMM3_SMEM>>>(
        xnh, xnl, w1h, w1l, b1, qkh, qkl, presp, ROWS, D2, DM);

    // 2b) v = xn @ W1[:, 2DM:] (fp16 2-pass) -> single fp16 (+ V present)
    bgemm5_kernel<false,2><<<dim3(DM/128, ROWS/128), 256, GEMM5_SMEM>>>(
        xnh, xnl, w1h + (size_t)D2 * DM, b1 + D2, nullptr,
        nullptr, vh, nullptr, presp, ROWS, DM, DM);

    // 3) attention: split-KV main + combine
    attn_v6_kernel<<<dim3(12, NH, BS), 256, ATT6_SMEM_BYTES>>>(qkh, qkl, vh, atth, attl);
    attn_combine_kernel<<<128, 256>>>(atth, attl);

    // 4) x1 = att @ W3 + b3 + x (fp16 2-pass, float out)
    bgemm5_kernel<false,0><<<dim3(DM/128, ROWS/128), 256, GEMM5_SMEM>>>(
        atth, attl, w3h, b3, x, x1, nullptr, nullptr, nullptr, ROWS, DM, DM);

    // 5) LN2 -> fp16 split
    ln_kernel<<<ROWS, 256>>>(x1, g2, be2, xn2h, xn2l);

    // 6) h = gelu(xn2 @ W2 + b2) -> fp16 split out
    bgemm5_kernel<true,1><<<dim3(D4/128, ROWS/128), 256, GEMM5_SMEM>>>(
        xn2h, xn2l, w2h, b2, nullptr, nullptr, hh, hl, nullptr, ROWS, D4, DM);

    // 7) out = h @ W4 + b4 + x1 (fp16 2-pass, float out)
    bgemm5_kernel<false,0><<<dim3(DM/128, ROWS/128), 256, GEMM5_SMEM>>>(
        hh, hl, w4h, b4, x1, out, nullptr, nullptr, nullptr, ROWS, DM, D4);
}

// round 13
// speedup vs baseline: 1.9355x; 1.3875x over previous
#include <cuda_runtime.h>
#include <cuda_bf16.h>
#include <cuda_fp16.h>
#include <math.h>

// ---------------- problem constants ----------------
#define BS   8
#define SEQ  1024
#define DM   768
#define NH   4
#define DH   192
#define ROWS (BS*SEQ)          // 8192
#define D3   (3*DM)            // 2304
#define D4   (4*DM)            // 3072
#define D2   (2*DM)            // 1536

#define XOUT_ELEMS   ((size_t)ROWS*DM)
#define PRES_ELEMS   ((size_t)BS*2*NH*SEQ*DH)

// ---------------- scratch (device globals) ---------------------------------
__device__ __align__(256) float g_x1 [ROWS*DM];

__device__ __align__(256) __half g_qkh[(size_t)ROWS*D2], g_qkl[(size_t)ROWS*D2];
__device__ __align__(256) __half g_vh [(size_t)ROWS*DM];
__device__ __align__(256) __half g_xnh [ROWS*DM],  g_xnl [ROWS*DM];
__device__ __align__(256) __half g_atth[ROWS*DM];
__device__ __align__(256) __half g_xn2h[ROWS*DM];
__device__ __align__(256) __half g_hh[(size_t)ROWS*D4];

// transposed weights: [N][K]
__device__ __align__(256) __half g_w1h[(size_t)D3*DM], g_w1l[(size_t)D2*DM];  // QK split, V single
__device__ __align__(256) __half g_w3h[(size_t)DM*DM];
__device__ __align__(256) __half g_w2h[(size_t)D4*DM];
__device__ __align__(256) __half g_w4h[(size_t)DM*D4];

// split-KV partials
__device__ __align__(256) float g_po[(size_t)2*128*128*192];
__device__ __align__(256) float g_pm[2*128*128];
__device__ __align__(256) float g_pl[2*128*128];

__device__ const int c_bi[12] = {7,6,3,5,7,2,4,6,5,1,4,0};
__device__ const int c_ch[12] = {1,1,-1,1,0,-1,1,0,0,-1,0,-1};

// ---------------- helpers ---------------------------------------------------
__device__ __forceinline__ void split2h(float x0, float x1, unsigned &hi, unsigned &lo) {
    __half h0 = __float2half_rn(x0);
    __half h1 = __float2half_rn(x1);
    __half l0 = __float2half_rn(x0 - __half2float(h0));
    __half l1 = __float2half_rn(x1 - __half2float(h1));
    hi = ((unsigned)__half_as_ushort(h1) << 16) | (unsigned)__half_as_ushort(h0);
    lo = ((unsigned)__half_as_ushort(l1) << 16) | (unsigned)__half_as_ushort(l0);
}

__device__ __forceinline__ unsigned packh(float x0, float x1) {
    __half h0 = __float2half_rn(x0);
    __half h1 = __float2half_rn(x1);
    return ((unsigned)__half_as_ushort(h1) << 16) | (unsigned)__half_as_ushort(h0);
}

__device__ __forceinline__ void mma_f16(float c[4], const unsigned a[4], const unsigned b[2]) {
    asm volatile(
        "mma.sync.aligned.m16n8k16.row.col.f32.f16.f16.f32 "
        "{%0,%1,%2,%3}, {%4,%5,%6,%7}, {%8,%9}, {%0,%1,%2,%3};\n"
        : "+f"(c[0]), "+f"(c[1]), "+f"(c[2]), "+f"(c[3])
        : "r"(a[0]), "r"(a[1]), "r"(a[2]), "r"(a[3]), "r"(b[0]), "r"(b[1]));
}

__device__ __forceinline__ void ldsm_x4(unsigned r[4], unsigned addr) {
    asm volatile("ldmatrix.sync.aligned.m8n8.x4.shared.b16 {%0,%1,%2,%3}, [%4];"
        : "=r"(r[0]), "=r"(r[1]), "=r"(r[2]), "=r"(r[3]) : "r"(addr));
}

__device__ __forceinline__ void ldsm_x4_t(unsigned &r0, unsigned &r1, unsigned &r2, unsigned &r3, unsigned saddr) {
    asm volatile("ldmatrix.sync.aligned.m8n8.x4.trans.shared.b16 {%0,%1,%2,%3}, [%4];"
        : "=r"(r0), "=r"(r1), "=r"(r2), "=r"(r3) : "r"(saddr));
}

#define CP16(dst, src) asm volatile("cp.async.cg.shared.global [%0], [%1], 16;\n" :: "r"(dst), "l"(src))
#define CP_COMMIT() asm volatile("cp.async.commit_group;\n" ::)
#define CP_WAIT0()  asm volatile("cp.async.wait_group 0;\n" ::)
#define CP_WAIT1()  asm volatile("cp.async.wait_group 1;\n" ::)

__device__ __forceinline__ float gelu_tanh_f(float x) {
    float x3 = x * x * x;
    float t  = tanhf(0.7978845608028654f * (x + 0.044715f * x3));
    return 0.5f * x * (1.0f + t);
}

// ---------------- weight transpose + split (fp16 hi/lo) ---------------------
__global__ __launch_bounds__(256) void wsplit_h2_kernel(
    const float* __restrict__ W, __half* __restrict__ Th,
    __half* __restrict__ Tl, int K, int N)
{
    __shared__ float t[32][33];
    int n0 = blockIdx.x * 32, k0 = blockIdx.y * 32;
    int tx = threadIdx.x & 31, ty = threadIdx.x >> 5;
    #pragma unroll
    for (int j = 0; j < 4; j++)
        t[ty + 8 * j][tx] = W[(size_t)(k0 + ty + 8 * j) * N + n0 + tx];
    __syncthreads();
    #pragma unroll
    for (int j = 0; j < 4; j++) {
        float v = t[tx][ty + 8 * j];
        __half hi = __float2half_rn(v);
        size_t o = (size_t)(n0 + ty + 8 * j) * K + k0 + tx;
        Th[o] = hi;
        if (Tl) Tl[o] = __float2half_rn(v - __half2float(hi));
    }
}

// ---------------- LayerNorm -> fp16 (optionally split) ----------------------
template<bool SPLIT>
__global__ __launch_bounds__(256) void ln_kernel(
    const float* __restrict__ x, const float* __restrict__ gamma,
    const float* __restrict__ beta, __half* __restrict__ oh, __half* __restrict__ ol)
{
    int row = blockIdx.x;
    int tid = threadIdx.x;
    const float* xr = x + (size_t)row * DM;
    float v0 = xr[tid], v1 = xr[tid + 256], v2 = xr[tid + 512];
    float s  = v0 + v1 + v2;
    float sq = v0*v0 + v1*v1 + v2*v2;
    #pragma unroll
    for (int o = 16; o > 0; o >>= 1) {
        s  += __shfl_xor_sync(0xffffffffu, s,  o);
        sq += __shfl_xor_sync(0xffffffffu, sq, o);
    }
    __shared__ float ss[8], ssq[8];
    __shared__ float mu_s, rs_s;
    int w = tid >> 5, l = tid & 31;
    if (l == 0) { ss[w] = s; ssq[w] = sq; }
    __syncthreads();
    if (tid == 0) {
        float S = 0.f, SQ = 0.f;
        #pragma unroll
        for (int i = 0; i < 8; i++) { S += ss[i]; SQ += ssq[i]; }
        float mu = S * (1.0f / DM);
        float var = SQ * (1.0f / DM) - mu * mu;
        mu_s = mu;
        rs_s = rsqrtf(var + 1e-3f);
    }
    __syncthreads();
    float mu = mu_s, rs = rs_s;
    size_t ro = (size_t)row * DM;
    #pragma unroll
    for (int q = 0; q < 3; q++) {
        int c = tid + q * 256;
        float v = (q == 0 ? v0 : (q == 1 ? v1 : v2));
        float y = (v - mu) * rs * gamma[c] + beta[c];
        __half hi = __float2half_rn(y);
        oh[ro + c] = hi;
        if (SPLIT) ol[ro + c] = __float2half_rn(y - __half2float(hi));
    }
}

// ---------------- GEMM f3: fp16 3-pass (A split, B split) — QK only ---------
#define SROW3 80
#define MAT3  (128*SROW3)
#define STG3  (4*MAT3)
#define GEMM3_SMEM (2*STG3)

__global__ __launch_bounds__(256, 2) void bgemm3f_kernel(
    const __half* __restrict__ Ah, const __half* __restrict__ Al,
    const __half* __restrict__ Bh, const __half* __restrict__ Bl,
    const float* __restrict__ bias,
    __half* __restrict__ Ch, __half* __restrict__ Cl,
    float* __restrict__ pres, int M, int N, int K)
{
    extern __shared__ unsigned char sm3[];
    const int tid = threadIdx.x;
    const int w = tid >> 5, l = tid & 31;
    const int wm = w & 1, wn = w >> 1;
    const int gid = l >> 2, tig = l & 3;
    const int bx = blockIdx.x, by = blockIdx.y;
    const int T = K >> 5;

    const unsigned smem_base = (unsigned)__cvta_generic_to_shared(sm3);

    const __half* A0 = Ah + (size_t)(by * 128) * K;
    const __half* A1 = Al + (size_t)(by * 128) * K;
    const __half* B0 = Bh + (size_t)(bx * 128) * K;
    const __half* B1 = Bl + (size_t)(bx * 128) * K;

    const int rl = l & 7, sel = l >> 3;
    const unsigned a_off = (unsigned)((rl + 8 * (sel & 1)) * SROW3 + 16 * (sel >> 1));
    const unsigned b_off = (unsigned)((rl + 8 * (sel >> 1)) * SROW3 + 16 * (sel & 1));

    float acc[4][4][4];
    #pragma unroll
    for (int i = 0; i < 4; i++)
        #pragma unroll
        for (int j = 0; j < 4; j++)
            #pragma unroll
            for (int c = 0; c < 4; c++) acc[i][j][c] = 0.f;

    auto issue = [&](int t) {
        unsigned sb = smem_base + (t & 1) * STG3;
        int k0 = t << 5;
        #pragma unroll
        for (int i = 0; i < 2; i++) {
            int chunk = tid + (i << 8);
            int r = chunk >> 2, c = chunk & 3;
            unsigned doff = (unsigned)(r * SROW3 + c * 16);
            size_t goff = (size_t)r * K + k0 + c * 8;
            CP16(sb + doff,            (const void*)(A0 + goff));
            CP16(sb + MAT3 + doff,     (const void*)(A1 + goff));
            CP16(sb + 2 * MAT3 + doff, (const void*)(B0 + goff));
            CP16(sb + 3 * MAT3 + doff, (const void*)(B1 + goff));
        }
        CP_COMMIT();
    };

    issue(0);
    if (T > 1) issue(1);

    for (int t = 0; t < T; t++) {
        if (t + 1 < T) CP_WAIT1(); else CP_WAIT0();
        __syncthreads();

        unsigned sb = smem_base + (t & 1) * STG3;
        #pragma unroll
        for (int ks = 0; ks < 2; ks++) {
            unsigned bh[2][4], bl4[2][4];
            #pragma unroll
            for (int p = 0; p < 2; p++) {
                unsigned bd = sb + 2 * MAT3 + (unsigned)((wn * 32 + p * 16) * SROW3 + ks * 32) + b_off;
                ldsm_x4(bh[p], bd);
                ldsm_x4(bl4[p], bd + MAT3);
            }
            #pragma unroll
            for (int am = 0; am < 4; am++) {
                unsigned ah[4], al4[4];
                unsigned ad = sb + (unsigned)((wm * 64 + am * 16) * SROW3 + ks * 32) + a_off;
                ldsm_x4(ah, ad);
                ldsm_x4(al4, ad + MAT3);
                #pragma unroll
                for (int an = 0; an < 4; an++) {
                    const int p = an >> 1, q = (an & 1) * 2;
                    unsigned bfh[2] = { bh[p][q], bh[p][q + 1] };
                    unsigned bfl[2] = { bl4[p][q], bl4[p][q + 1] };
                    mma_f16(acc[am][an], ah, bfh);
                    mma_f16(acc[am][an], al4, bfh);
                    mma_f16(acc[am][an], ah, bfl);
                }
            }
        }
        __syncthreads();
        if (t + 2 < T) issue(t + 2);
    }

    #pragma unroll
    for (int am = 0; am < 4; am++) {
        int r0 = by * 128 + wm * 64 + am * 16 + gid;
        int r1 = r0 + 8;
        #pragma unroll
        for (int an = 0; an < 4; an++) {
            int n0 = bx * 128 + wn * 32 + an * 8 + 2 * tig;
            float bv0 = bias[n0], bv1 = bias[n0 + 1];
            size_t o0 = (size_t)r0 * N + n0;
            size_t o1 = (size_t)r1 * N + n0;
            float v0 = acc[am][an][0] + bv0;
            float v1 = acc[am][an][1] + bv1;
            float v2 = acc[am][an][2] + bv0;
            float v3 = acc[am][an][3] + bv1;
            unsigned hw, lw;
            split2h(v0, v1, hw, lw);
            *reinterpret_cast<unsigned*>(Ch + o0) = hw;
            *reinterpret_cast<unsigned*>(Cl + o0) = lw;
            split2h(v2, v3, hw, lw);
            *reinterpret_cast<unsigned*>(Ch + o1) = hw;
            *reinterpret_cast<unsigned*>(Cl + o1) = lw;
            if (pres && n0 >= DM) {      // K columns -> present[.,0,...]
                int local = n0 - DM;
                int hh = local / DH, dd = local % DH;
                int b0 = r0 >> 10, s0 = r0 & 1023;
                int b1 = r1 >> 10, s1 = r1 & 1023;
                size_t p0 = (((size_t)(b0 * 2) * NH + hh) * SEQ + s0) * DH + dd;
                size_t p1 = (((size_t)(b1 * 2) * NH + hh) * SEQ + s1) * DH + dd;
                *reinterpret_cast<float2*>(pres + p0) = make_float2(v0, v1);
                *reinterpret_cast<float2*>(pres + p1) = make_float2(v2, v3);
            }
        }
    }
}

// ---------------- GEMM v1: fp16 1-pass (A single, B single) -----------------
// OMODE: 0 = float out (+res), 2 = single fp16 out (+optional V-present)
#define STG1  (2*MAT3)
#define GEMM1_SMEM (2*STG1)

template<bool GELU, int OMODE>
__global__ __launch_bounds__(256, 2) void bgemm1_kernel(
    const __half* __restrict__ Ah, const __half* __restrict__ Bh,
    const float* __restrict__ bias, const float* __restrict__ res,
    float* __restrict__ C, __half* __restrict__ Ch,
    float* __restrict__ pres, int M, int N, int K)
{
    extern __shared__ unsigned char sm1[];
    const int tid = threadIdx.x;
    const int w = tid >> 5, l = tid & 31;
    const int wm = w & 1, wn = w >> 1;
    const int gid = l >> 2, tig = l & 3;
    const int bx = blockIdx.x, by = blockIdx.y;
    const int T = K >> 5;

    const unsigned smem_base = (unsigned)__cvta_generic_to_shared(sm1);

    const __half* A0 = Ah + (size_t)(by * 128) * K;
    const __half* B0 = Bh + (size_t)(bx * 128) * K;

    const int rl = l & 7, sel = l >> 3;
    const unsigned a_off = (unsigned)((rl + 8 * (sel & 1)) * SROW3 + 16 * (sel >> 1));
    const unsigned b_off = (unsigned)((rl + 8 * (sel >> 1)) * SROW3 + 16 * (sel & 1));

    float acc[4][4][4];
    #pragma unroll
    for (int i = 0; i < 4; i++)
        #pragma unroll
        for (int j = 0; j < 4; j++)
            #pragma unroll
            for (int c = 0; c < 4; c++) acc[i][j][c] = 0.f;

    auto issue = [&](int t) {
        unsigned sb = smem_base + (t & 1) * STG1;
        int k0 = t << 5;
        #pragma unroll
        for (int i = 0; i < 2; i++) {
            int chunk = tid + (i << 8);
            int r = chunk >> 2, c = chunk & 3;
            unsigned doff = (unsigned)(r * SROW3 + c * 16);
            size_t goff = (size_t)r * K + k0 + c * 8;
            CP16(sb + doff,        (const void*)(A0 + goff));
            CP16(sb + MAT3 + doff, (const void*)(B0 + goff));
        }
        CP_COMMIT();
    };

    issue(0);
    if (T > 1) issue(1);

    for (int t = 0; t < T; t++) {
        if (t + 1 < T) CP_WAIT1(); else CP_WAIT0();
        __syncthreads();

        unsigned sb = smem_base + (t & 1) * STG1;
        #pragma unroll
        for (int ks = 0; ks < 2; ks++) {
            unsigned bh[2][4];
            #pragma unroll
            for (int p = 0; p < 2; p++) {
                unsigned bd = sb + MAT3 + (unsigned)((wn * 32 + p * 16) * SROW3 + ks * 32) + b_off;
                ldsm_x4(bh[p], bd);
            }
            #pragma unroll
            for (int am = 0; am < 4; am++) {
                unsigned ah[4];
                unsigned ad = sb + (unsigned)((wm * 64 + am * 16) * SROW3 + ks * 32) + a_off;
                ldsm_x4(ah, ad);
                #pragma unroll
                for (int an = 0; an < 4; an++) {
                    const int p = an >> 1, q = (an & 1) * 2;
                    unsigned bfh[2] = { bh[p][q], bh[p][q + 1] };
                    mma_f16(acc[am][an], ah, bfh);
                }
            }
        }
        __syncthreads();
        if (t + 2 < T) issue(t + 2);
    }

    #pragma unroll
    for (int am = 0; am < 4; am++) {
        int r0 = by * 128 + wm * 64 + am * 16 + gid;
        int r1 = r0 + 8;
        #pragma unroll
        for (int an = 0; an < 4; an++) {
            int n0 = bx * 128 + wn * 32 + an * 8 + 2 * tig;
            float bv0 = bias[n0], bv1 = bias[n0 + 1];
            size_t o0 = (size_t)r0 * N + n0;
            size_t o1 = (size_t)r1 * N + n0;
            float v0 = acc[am][an][0] + bv0;
            float v1 = acc[am][an][1] + bv1;
            float v2 = acc[am][an][2] + bv0;
            float v3 = acc[am][an][3] + bv1;
            if (res) {
                v0 += res[o0]; v1 += res[o0 + 1];
                v2 += res[o1]; v3 += res[o1 + 1];
            }
            if (GELU) {
                v0 = gelu_tanh_f(v0); v1 = gelu_tanh_f(v1);
                v2 = gelu_tanh_f(v2); v3 = gelu_tanh_f(v3);
            }
            if (OMODE == 0) {
                *reinterpret_cast<float2*>(C + o0) = make_float2(v0, v1);
                *reinterpret_cast<float2*>(C + o1) = make_float2(v2, v3);
            } else {
                *reinterpret_cast<unsigned*>(Ch + o0) = packh(v0, v1);
                *reinterpret_cast<unsigned*>(Ch + o1) = packh(v2, v3);
                if (pres) {
                    int hh = n0 / DH, dd = n0 % DH;
                    int b0 = r0 >> 10, s0 = r0 & 1023;
                    int b1 = r1 >> 10, s1 = r1 & 1023;
                    size_t p0 = (((size_t)(b0 * 2 + 1) * NH + hh) * SEQ + s0) * DH + dd;
                    size_t p1 = (((size_t)(b1 * 2 + 1) * NH + hh) * SEQ + s1) * DH + dd;
                    *reinterpret_cast<float2*>(pres + p0) = make_float2(v0, v1);
                    *reinterpret_cast<float2*>(pres + p1) = make_float2(v2, v3);
                }
            }
        }
    }
}

// ---------------- attention v7: fp16, split-KV, PV 1-pass -------------------
#define A6_ST 100
#define A6_QH 0
#define A6_QL 12800
#define A6_KH 25600
#define A6_KL 32000
#define A6_VH 38400
#define ATT6_SMEM_BYTES (44800*4)

__global__ __launch_bounds__(256, 1) void attn_v7_kernel(
    const __half* __restrict__ qkh, const __half* __restrict__ qkl,
    const __half* __restrict__ vbuf,
    __half* __restrict__ atth)
{
    extern __shared__ unsigned smu[];
    const int type = blockIdx.x;
    const int bi = c_bi[type];
    const int ch = c_ch[type];
    const int h  = blockIdx.y;
    const int b  = blockIdx.z;
    const int tid = threadIdx.x;
    const int w = tid >> 5, l = tid & 31;
    const int gid = l >> 2, tig = l & 3;

    const int j0 = (ch == 1) ? bi : 0;
    const int j1 = (ch == 0) ? bi : 2 * bi + 2;

    const float scale = 13.856406460551018f;   // sqrt(192) (faithful bug)
    const unsigned sbase = (unsigned)__cvta_generic_to_shared(smu);

    const int kcol = DM + h * DH;
    const int vcol = h * DH;

    auto issue_k = [&](int j) {
        const size_t row0 = (size_t)(b * SEQ + j * 64);
        #pragma unroll
        for (int i = 0; i < 6; i++) {
            int c = tid + (i << 8);
            int r = c / 24, cc2 = c % 24;
            unsigned doff = (unsigned)((r * A6_ST + cc2 * 4) * 4);
            size_t gk = (row0 + r) * D2 + kcol + cc2 * 8;
            CP16(sbase + A6_KH * 4 + doff, (const void*)(qkh + gk));
            CP16(sbase + A6_KL * 4 + doff, (const void*)(qkl + gk));
        }
        CP_COMMIT();
    };
    auto issue_v = [&](int j) {
        const size_t row0 = (size_t)(b * SEQ + j * 64);
        #pragma unroll
        for (int i = 0; i < 6; i++) {
            int c = tid + (i << 8);
            int r = c / 24, cc2 = c % 24;
            unsigned doff = (unsigned)((r * A6_ST + cc2 * 4) * 4);
            size_t gv = (row0 + r) * DM + vcol + cc2 * 8;
            CP16(sbase + A6_VH * 4 + doff, (const void*)(vbuf + gv));
        }
        CP_COMMIT();
    };

    // preload Q, K(j0), V(j0)
    {
        const size_t row0 = (size_t)(b * SEQ + bi * 128);
        const int qcol = h * DH;
        #pragma unroll
        for (int i = 0; i < 12; i++) {
            int c = tid + (i << 8);
            int r = c / 24, cc2 = c % 24;
            unsigned doff = (unsigned)((r * A6_ST + cc2 * 4) * 4);
            size_t goff = (row0 + r) * D2 + qcol + cc2 * 8;
            CP16(sbase + A6_QH * 4 + doff, (const void*)(qkh + goff));
            CP16(sbase + A6_QL * 4 + doff, (const void*)(qkl + goff));
        }
        CP_COMMIT();
    }
    issue_k(j0);
    issue_v(j0);

    float m0 = -1e30f, m1 = -1e30f, l0 = 0.f, l1 = 0.f;
    float accO[24][4];
    #pragma unroll
    for (int i = 0; i < 24; i++)
        #pragma unroll
        for (int c = 0; c < 4; c++) accO[i][c] = 0.f;

    const int lm_rwi  = (l & 7) + ((l >> 3) & 1) * 8;
    const int lm_ncol = (l >> 4) * 8;
    const unsigned vh_base = sbase + A6_VH * 4;

    const int qg0 = bi * 128 + w * 16 + gid;
    const int qg1 = qg0 + 8;

    for (int j = j0; j < j1; j++) {
        CP_WAIT1();
        __syncthreads();

        const bool diag = (j >= 2 * bi);
        const bool wskip = diag && (64 * j >= bi * 128 + w * 16 + 16);

        const unsigned* Qh = smu + A6_QH;
        const unsigned* Ql = smu + A6_QL;
        const unsigned* Kh = smu + A6_KH;
        const unsigned* Kl = smu + A6_KL;

        unsigned pha[4][4];
        float corr0 = 1.f, corr1 = 1.f;

        if (!wskip) {
            float accS[8][4];
            #pragma unroll
            for (int i = 0; i < 8; i++)
                #pragma unroll
                for (int c = 0; c < 4; c++) accS[i][c] = 0.f;

            #pragma unroll
            for (int ks = 0; ks < 12; ks++) {
                int kp = ks * 8;
                unsigned ah[4], al[4];
                int a0 = (w * 16 + gid) * A6_ST + kp + tig;
                int a1 = a0 + 8 * A6_ST;
                ah[0] = Qh[a0]; ah[1] = Qh[a1]; ah[2] = Qh[a0 + 4]; ah[3] = Qh[a1 + 4];
                al[0] = Ql[a0]; al[1] = Ql[a1]; al[2] = Ql[a0 + 4]; al[3] = Ql[a1 + 4];
                #pragma unroll
                for (int nt = 0; nt < 8; nt++) {
                    int bb = (nt * 8 + gid) * A6_ST + kp + tig;
                    unsigned bh[2], bl2[2];
                    bh[0]  = Kh[bb]; bh[1]  = Kh[bb + 4];
                    bl2[0] = Kl[bb]; bl2[1] = Kl[bb + 4];
                    mma_f16(accS[nt], ah, bh);
                    mma_f16(accS[nt], al, bh);
                    mma_f16(accS[nt], ah, bl2);
                }
            }

            float mx0 = -1e30f, mx1 = -1e30f;
            #pragma unroll
            for (int nt = 0; nt < 8; nt++) {
                int kg = j * 64 + nt * 8 + 2 * tig;
                float v0 = accS[nt][0] * scale;
                float v1 = accS[nt][1] * scale;
                float v2 = accS[nt][2] * scale;
                float v3 = accS[nt][3] * scale;
                if (diag) {
                    if (kg     > qg0) v0 = -1e30f;
                    if (kg + 1 > qg0) v1 = -1e30f;
                    if (kg     > qg1) v2 = -1e30f;
                    if (kg + 1 > qg1) v3 = -1e30f;
                }
                accS[nt][0] = v0; accS[nt][1] = v1;
                accS[nt][2] = v2; accS[nt][3] = v3;
                mx0 = fmaxf(mx0, fmaxf(v0, v1));
                mx1 = fmaxf(mx1, fmaxf(v2, v3));
            }
            mx0 = fmaxf(mx0, __shfl_xor_sync(0xffffffffu, mx0, 1));
            mx0 = fmaxf(mx0, __shfl_xor_sync(0xffffffffu, mx0, 2));
            mx1 = fmaxf(mx1, __shfl_xor_sync(0xffffffffu, mx1, 1));
            mx1 = fmaxf(mx1, __shfl_xor_sync(0xffffffffu, mx1, 2));
            float mn0 = fmaxf(m0, mx0), mn1 = fmaxf(m1, mx1);
            corr0 = __expf(m0 - mn0); corr1 = __expf(m1 - mn1);

            float sum0 = 0.f, sum1 = 0.f;
            #pragma unroll
            for (int nt = 0; nt < 8; nt++) {
                float p0 = __expf(accS[nt][0] - mn0);
                float p1 = __expf(accS[nt][1] - mn0);
                float p2 = __expf(accS[nt][2] - mn1);
                float p3 = __expf(accS[nt][3] - mn1);
                sum0 += p0 + p1;
                sum1 += p2 + p3;
                const int ks = nt >> 1;
                const int s0 = (nt & 1) * 2;
                pha[ks][s0]     = packh(p0, p1);
                pha[ks][s0 + 1] = packh(p2, p3);
            }
            sum0 += __shfl_xor_sync(0xffffffffu, sum0, 1);
            sum0 += __shfl_xor_sync(0xffffffffu, sum0, 2);
            sum1 += __shfl_xor_sync(0xffffffffu, sum1, 1);
            sum1 += __shfl_xor_sync(0xffffffffu, sum1, 2);
            l0 = l0 * corr0 + sum0;  m0 = mn0;
            l1 = l1 * corr1 + sum1;  m1 = mn1;
        }

        CP_WAIT0();
        __syncthreads();
        if (j + 1 < j1) issue_k(j + 1);

        if (!wskip) {
            #pragma unroll
            for (int nt = 0; nt < 24; nt++) {
                accO[nt][0] *= corr0; accO[nt][1] *= corr0;
                accO[nt][2] *= corr1; accO[nt][3] *= corr1;
            }
            #pragma unroll
            for (int ks = 0; ks < 4; ks++) {
                unsigned rowoff = (unsigned)((ks * 16 + lm_rwi) * A6_ST) * 4u;
                #pragma unroll
                for (int g = 0; g < 12; g++) {
                    unsigned coloff = (unsigned)(g * 8 + lm_ncol / 2) * 4u;
                    unsigned bh0, bh1, bh2, bh3;
                    ldsm_x4_t(bh0, bh1, bh2, bh3, vh_base + rowoff + coloff);
                    unsigned bfh[2];
                    bfh[0] = bh0; bfh[1] = bh1;
                    mma_f16(accO[2 * g],     pha[ks], bfh);
                    bfh[0] = bh2; bfh[1] = bh3;
                    mma_f16(accO[2 * g + 1], pha[ks], bfh);
                }
            }
        }

        __syncthreads();
        if (j + 1 < j1) issue_v(j + 1);
    }

    if (ch < 0) {
        float li0 = 1.0f / l0, li1 = 1.0f / l1;
        int row0 = b * SEQ + bi * 128 + w * 16 + gid;
        #pragma unroll
        for (int nt = 0; nt < 24; nt++) {
            int col = h * DH + nt * 8 + 2 * tig;
            size_t o0 = (size_t)row0 * DM + col;
            size_t o1 = (size_t)(row0 + 8) * DM + col;
            *reinterpret_cast<unsigned*>(atth + o0) = packh(accO[nt][0] * li0, accO[nt][1] * li0);
            *reinterpret_cast<unsigned*>(atth + o1) = packh(accO[nt][2] * li1, accO[nt][3] * li1);
        }
    } else {
        const int pidx = ((b * NH + h) << 2) + (bi - 4);
        float* po = g_po + ((size_t)ch * 128 + pidx) * (128 * 192);
        const int r0 = w * 16 + gid, r1 = r0 + 8;
        #pragma unroll
        for (int nt = 0; nt < 24; nt++) {
            int col = nt * 8 + 2 * tig;
            *reinterpret_cast<float2*>(po + r0 * 192 + col) = make_float2(accO[nt][0], accO[nt][1]);
            *reinterpret_cast<float2*>(po + r1 * 192 + col) = make_float2(accO[nt][2], accO[nt][3]);
        }
        if (tig == 0) {
            int mlb = (ch * 128 + pidx) * 128;
            g_pm[mlb + r0] = m0; g_pl[mlb + r0] = l0;
            g_pm[mlb + r1] = m1; g_pl[mlb + r1] = l1;
        }
    }
}

// ---------------- split-KV combine ------------------------------------------
__global__ __launch_bounds__(256) void attn_combine_kernel(__half* __restrict__ atth)
{
    const int pidx = blockIdx.x;
    const int b  = pidx >> 4;
    const int h  = (pidx >> 2) & 3;
    const int bi = 4 + (pidx & 3);
    const int r  = threadIdx.x >> 1;
    const int c0 = (threadIdx.x & 1) * 96;

    const float* po0 = g_po + ((size_t)0 * 128 + pidx) * (128 * 192) + r * 192 + c0;
    const float* po1 = g_po + ((size_t)1 * 128 + pidx) * (128 * 192) + r * 192 + c0;
    const int mlb0 = (0 * 128 + pidx) * 128 + r;
    const int mlb1 = (1 * 128 + pidx) * 128 + r;
    float m0 = g_pm[mlb0], l0 = g_pl[mlb0];
    float m1 = g_pm[mlb1], l1 = g_pl[mlb1];
    float m = fmaxf(m0, m1);
    float e0 = __expf(m0 - m), e1 = __expf(m1 - m);
    float linv = 1.0f / (e0 * l0 + e1 * l1);

    size_t go = (size_t)(b * SEQ + bi * 128 + r) * DM + h * DH + c0;
    #pragma unroll
    for (int c = 0; c < 96; c += 2) {
        float v0 = (e0 * po0[c]     + e1 * po1[c])     * linv;
        float v1 = (e0 * po0[c + 1] + e1 * po1[c + 1]) * linv;
        *reinterpret_cast<unsigned*>(atth + go + c) = packh(v0, v1);
    }
}

// ---------------- launch -----------------------------------------------
extern "C" void kernel_launch(void* const* d_in, const int* in_sizes, int n_in,
                              void* d_out, int out_size)
{
    const float* x   = (const float*)d_in[0];
    const float* W1  = (const float*)d_in[2];
    const float* b1  = (const float*)d_in[3];
    const float* W3  = (const float*)d_in[4];
    const float* b3  = (const float*)d_in[5];
    const float* W2  = (const float*)d_in[6];
    const float* b2  = (const float*)d_in[7];
    const float* W4  = (const float*)d_in[8];
    const float* b4  = (const float*)d_in[9];
    const float* g1  = (const float*)d_in[10];
    const float* be1 = (const float*)d_in[11];
    const float* g2  = (const float*)d_in[12];
    const float* be2 = (const float*)d_in[13];
    float* out = (float*)d_out;

    float *x1;
    cudaGetSymbolAddress((void**)&x1, g_x1);
    __half *qkh, *qkl, *vh, *xnh, *xnl, *atth, *xn2h, *hh;
    __half *w1h, *w1l, *w3h, *w2h, *w4h;
    cudaGetSymbolAddress((void**)&qkh,  g_qkh);  cudaGetSymbolAddress((void**)&qkl,  g_qkl);
    cudaGetSymbolAddress((void**)&vh,   g_vh);
    cudaGetSymbolAddress((void**)&xnh,  g_xnh);  cudaGetSymbolAddress((void**)&xnl,  g_xnl);
    cudaGetSymbolAddress((void**)&atth, g_atth);
    cudaGetSymbolAddress((void**)&xn2h, g_xn2h);
    cudaGetSymbolAddress((void**)&hh,   g_hh);
    cudaGetSymbolAddress((void**)&w1h,  g_w1h);  cudaGetSymbolAddress((void**)&w1l,  g_w1l);
    cudaGetSymbolAddress((void**)&w3h,  g_w3h);
    cudaGetSymbolAddress((void**)&w2h,  g_w2h);
    cudaGetSymbolAddress((void**)&w4h,  g_w4h);

    cudaFuncSetAttribute(attn_v7_kernel,
                         cudaFuncAttributeMaxDynamicSharedMemorySize, ATT6_SMEM_BYTES);
    cudaFuncSetAttribute(bgemm3f_kernel,
                         cudaFuncAttributeMaxDynamicSharedMemorySize, GEMM3_SMEM);
    cudaFuncSetAttribute(bgemm1_kernel<false,0>,
                         cudaFuncAttributeMaxDynamicSharedMemorySize, GEMM1_SMEM);
    cudaFuncSetAttribute(bgemm1_kernel<true,2>,
                         cudaFuncAttributeMaxDynamicSharedMemorySize, GEMM1_SMEM);
    cudaFuncSetAttribute(bgemm1_kernel<false,2>,
                         cudaFuncAttributeMaxDynamicSharedMemorySize, GEMM1_SMEM);

    float* pres = out + XOUT_ELEMS;
    bool has_present = ((size_t)out_size >= XOUT_ELEMS + PRES_ELEMS);
    float* presp = has_present ? pres : nullptr;

    // 0) weight prep: W1 QK part split, W1 V part single, others single
    wsplit_h2_kernel<<<dim3(D2/32, DM/32), 256>>>(W1, w1h, w1l, DM, D3);
    // V columns of W1 (single): transpose rows [D2, D3)
    {
        // reuse wsplit_h2 with Tl=null over the V slice: blockIdx.x covers N slice
        // launch a separate grid mapping n0 offset D2
        wsplit_h2_kernel<<<dim3(DM/32, DM/32), 256>>>(W1 + D2, w1h + (size_t)D2 * DM, nullptr, DM, D3);
    }
    wsplit_h2_kernel<<<dim3(DM/32, DM/32), 256>>>(W3, w3h, nullptr, DM, DM);
    wsplit_h2_kernel<<<dim3(D4/32, DM/32), 256>>>(W2, w2h, nullptr, DM, D4);
    wsplit_h2_kernel<<<dim3(DM/32, D4/32), 256>>>(W4, w4h, nullptr, D4, DM);

    // 1) LN1 -> fp16 split
    ln_kernel<true><<<ROWS, 256>>>(x, g1, be1, xnh, xnl);

    // 2a) qk = xn @ W1[:, :2DM] (fp16 3-pass) -> split fp16 (+ K present)
    bgemm3f_kernel<<<dim3(D2/128, ROWS/128), 256, GEMM3_SMEM>>>(
        xnh, xnl, w1h, w1l, b1, qkh, qkl, presp, ROWS, D2, DM);

    // 2b) v = xn @ W1[:, 2DM:] (fp16 1-pass) -> single fp16 (+ V present)
    bgemm1_kernel<false,2><<<dim3(DM/128, ROWS/128), 256, GEMM1_SMEM>>>(
        xnh, w1h + (size_t)D2 * DM, b1 + D2, nullptr,
        nullptr, vh, presp, ROWS, DM, DM);

    // 3) attention: split-KV main + combine
    attn_v7_kernel<<<dim3(12, NH, BS), 256, ATT6_SMEM_BYTES>>>(qkh, qkl, vh, atth);
    attn_combine_kernel<<<128, 256>>>(atth);

    // 4) x1 = att @ W3 + b3 + x (fp16 1-pass, float out)
    bgemm1_kernel<false,0><<<dim3(DM/128, ROWS/128), 256, GEMM1_SMEM>>>(
        atth, w3h, b3, x, x1, nullptr, nullptr, ROWS, DM, DM);

    // 5) LN2 -> fp16 single
    ln_kernel<false><<<ROWS, 256>>>(x1, g2, be2, xn2h, nullptr);

    // 6) h = gelu(xn2 @ W2 + b2) -> fp16 single out
    bgemm1_kernel<true,2><<<dim3(D4/128, ROWS/128), 256, GEMM1_SMEM>>>(
        xn2h, w2h, b2, nullptr, nullptr, hh, nullptr, ROWS, D4, DM);

    // 7) out = h @ W4 + b4 + x1 (fp16 1-pass, float out)
    bgemm1_kernel<false,0><<<dim3(DM/128, ROWS/128), 256, GEMM1_SMEM>>>(
        hh, w4h, b4, x1, out, nullptr, nullptr, ROWS, DM, D4);
}

// round 14
// speedup vs baseline: 1.9394x; 1.0020x over previous
#include <cuda_runtime.h>
#include <cuda_bf16.h>
#include <cuda_fp16.h>
#include <math.h>

// ---------------- problem constants ----------------
#define BS   8
#define SEQ  1024
#define DM   768
#define NH   4
#define DH   192
#define ROWS (BS*SEQ)          // 8192
#define D3   (3*DM)            // 2304
#define D4   (4*DM)            // 3072
#define D2   (2*DM)            // 1536

#define XOUT_ELEMS   ((size_t)ROWS*DM)
#define PRES_ELEMS   ((size_t)BS*2*NH*SEQ*DH)

// ---------------- scratch (device globals) ---------------------------------
__device__ __align__(256) float g_x1 [ROWS*DM];

__device__ __align__(256) __half g_qkh[(size_t)ROWS*D2], g_qkl[(size_t)ROWS*D2];
__device__ __align__(256) __half g_vh [(size_t)ROWS*DM];
__device__ __align__(256) __half g_xnh [ROWS*DM],  g_xnl [ROWS*DM];
__device__ __align__(256) __half g_atth[ROWS*DM];
__device__ __align__(256) __half g_xn2h[ROWS*DM];
__device__ __align__(256) __half g_hh[(size_t)ROWS*D4];

// transposed weights: [N][K]
__device__ __align__(256) __half g_w1h[(size_t)D3*DM], g_w1l[(size_t)D2*DM];
__device__ __align__(256) __half g_w3h[(size_t)DM*DM];
__device__ __align__(256) __half g_w2h[(size_t)D4*DM];
__device__ __align__(256) __half g_w4h[(size_t)DM*D4];

// split-KV partials
__device__ __align__(256) float g_po[(size_t)2*128*128*192];
__device__ __align__(256) float g_pm[2*128*128];
__device__ __align__(256) float g_pl[2*128*128];

__device__ const int c_bi[12] = {7,6,3,5,7,2,4,6,5,1,4,0};
__device__ const int c_ch[12] = {1,1,-1,1,0,-1,1,0,0,-1,0,-1};

// ---------------- helpers ---------------------------------------------------
__device__ __forceinline__ void split2h(float x0, float x1, unsigned &hi, unsigned &lo) {
    __half h0 = __float2half_rn(x0);
    __half h1 = __float2half_rn(x1);
    __half l0 = __float2half_rn(x0 - __half2float(h0));
    __half l1 = __float2half_rn(x1 - __half2float(h1));
    hi = ((unsigned)__half_as_ushort(h1) << 16) | (unsigned)__half_as_ushort(h0);
    lo = ((unsigned)__half_as_ushort(l1) << 16) | (unsigned)__half_as_ushort(l0);
}

__device__ __forceinline__ unsigned packh(float x0, float x1) {
    __half h0 = __float2half_rn(x0);
    __half h1 = __float2half_rn(x1);
    return ((unsigned)__half_as_ushort(h1) << 16) | (unsigned)__half_as_ushort(h0);
}

// 2^x for a pair, computed in fp16x2 via one MUFU op; result stays packed fp16x2
__device__ __forceinline__ unsigned ex2h2(float x0, float x1) {
    unsigned hin = packh(x0, x1);
    unsigned r;
    asm("ex2.approx.f16x2 %0, %1;" : "=r"(r) : "r"(hin));
    return r;
}

__device__ __forceinline__ void mma_f16(float c[4], const unsigned a[4], const unsigned b[2]) {
    asm volatile(
        "mma.sync.aligned.m16n8k16.row.col.f32.f16.f16.f32 "
        "{%0,%1,%2,%3}, {%4,%5,%6,%7}, {%8,%9}, {%0,%1,%2,%3};\n"
        : "+f"(c[0]), "+f"(c[1]), "+f"(c[2]), "+f"(c[3])
        : "r"(a[0]), "r"(a[1]), "r"(a[2]), "r"(a[3]), "r"(b[0]), "r"(b[1]));
}

__device__ __forceinline__ void ldsm_x4(unsigned r[4], unsigned addr) {
    asm volatile("ldmatrix.sync.aligned.m8n8.x4.shared.b16 {%0,%1,%2,%3}, [%4];"
        : "=r"(r[0]), "=r"(r[1]), "=r"(r[2]), "=r"(r[3]) : "r"(addr));
}

__device__ __forceinline__ void ldsm_x4_t(unsigned &r0, unsigned &r1, unsigned &r2, unsigned &r3, unsigned saddr) {
    asm volatile("ldmatrix.sync.aligned.m8n8.x4.trans.shared.b16 {%0,%1,%2,%3}, [%4];"
        : "=r"(r0), "=r"(r1), "=r"(r2), "=r"(r3) : "r"(saddr));
}

#define CP16(dst, src) asm volatile("cp.async.cg.shared.global [%0], [%1], 16;\n" :: "r"(dst), "l"(src))
#define CP_COMMIT() asm volatile("cp.async.commit_group;\n" ::)
#define CP_WAIT0()  asm volatile("cp.async.wait_group 0;\n" ::)
#define CP_WAIT1()  asm volatile("cp.async.wait_group 1;\n" ::)

__device__ __forceinline__ float gelu_tanh_f(float x) {
    float x3 = x * x * x;
    float t  = tanhf(0.7978845608028654f * (x + 0.044715f * x3));
    return 0.5f * x * (1.0f + t);
}

// ---------------- weight transpose + split (fp16 hi/lo, lo optional) --------
__global__ __launch_bounds__(256) void wsplit_h2_kernel(
    const float* __restrict__ W, __half* __restrict__ Th,
    __half* __restrict__ Tl, int K, int N)
{
    __shared__ float t[32][33];
    int n0 = blockIdx.x * 32, k0 = blockIdx.y * 32;
    int tx = threadIdx.x & 31, ty = threadIdx.x >> 5;
    #pragma unroll
    for (int j = 0; j < 4; j++)
        t[ty + 8 * j][tx] = W[(size_t)(k0 + ty + 8 * j) * N + n0 + tx];
    __syncthreads();
    #pragma unroll
    for (int j = 0; j < 4; j++) {
        float v = t[tx][ty + 8 * j];
        __half hi = __float2half_rn(v);
        size_t o = (size_t)(n0 + ty + 8 * j) * K + k0 + tx;
        Th[o] = hi;
        if (Tl) Tl[o] = __float2half_rn(v - __half2float(hi));
    }
}

// ---------------- LayerNorm -> fp16 (optionally split) ----------------------
template<bool SPLIT>
__global__ __launch_bounds__(256) void ln_kernel(
    const float* __restrict__ x, const float* __restrict__ gamma,
    const float* __restrict__ beta, __half* __restrict__ oh, __half* __restrict__ ol)
{
    int row = blockIdx.x;
    int tid = threadIdx.x;
    const float* xr = x + (size_t)row * DM;
    float v0 = xr[tid], v1 = xr[tid + 256], v2 = xr[tid + 512];
    float s  = v0 + v1 + v2;
    float sq = v0*v0 + v1*v1 + v2*v2;
    #pragma unroll
    for (int o = 16; o > 0; o >>= 1) {
        s  += __shfl_xor_sync(0xffffffffu, s,  o);
        sq += __shfl_xor_sync(0xffffffffu, sq, o);
    }
    __shared__ float ss[8], ssq[8];
    __shared__ float mu_s, rs_s;
    int w = tid >> 5, l = tid & 31;
    if (l == 0) { ss[w] = s; ssq[w] = sq; }
    __syncthreads();
    if (tid == 0) {
        float S = 0.f, SQ = 0.f;
        #pragma unroll
        for (int i = 0; i < 8; i++) { S += ss[i]; SQ += ssq[i]; }
        float mu = S * (1.0f / DM);
        float var = SQ * (1.0f / DM) - mu * mu;
        mu_s = mu;
        rs_s = rsqrtf(var + 1e-3f);
    }
    __syncthreads();
    float mu = mu_s, rs = rs_s;
    size_t ro = (size_t)row * DM;
    #pragma unroll
    for (int q = 0; q < 3; q++) {
        int c = tid + q * 256;
        float v = (q == 0 ? v0 : (q == 1 ? v1 : v2));
        float y = (v - mu) * rs * gamma[c] + beta[c];
        __half hi = __float2half_rn(y);
        oh[ro + c] = hi;
        if (SPLIT) ol[ro + c] = __float2half_rn(y - __half2float(hi));
    }
}

// ---------------- GEMM f3: fp16 3-pass (A split, B split) — QK only ---------
#define SROW3 80
#define MAT3  (128*SROW3)
#define STG3  (4*MAT3)
#define GEMM3_SMEM (2*STG3)

__global__ __launch_bounds__(256, 2) void bgemm3f_kernel(
    const __half* __restrict__ Ah, const __half* __restrict__ Al,
    const __half* __restrict__ Bh, const __half* __restrict__ Bl,
    const float* __restrict__ bias,
    __half* __restrict__ Ch, __half* __restrict__ Cl,
    float* __restrict__ pres, int M, int N, int K)
{
    extern __shared__ unsigned char sm3[];
    const int tid = threadIdx.x;
    const int w = tid >> 5, l = tid & 31;
    const int wm = w & 1, wn = w >> 1;
    const int gid = l >> 2, tig = l & 3;
    const int bx = blockIdx.x, by = blockIdx.y;
    const int T = K >> 5;

    const unsigned smem_base = (unsigned)__cvta_generic_to_shared(sm3);

    const __half* A0 = Ah + (size_t)(by * 128) * K;
    const __half* A1 = Al + (size_t)(by * 128) * K;
    const __half* B0 = Bh + (size_t)(bx * 128) * K;
    const __half* B1 = Bl + (size_t)(bx * 128) * K;

    const int rl = l & 7, sel = l >> 3;
    const unsigned a_off = (unsigned)((rl + 8 * (sel & 1)) * SROW3 + 16 * (sel >> 1));
    const unsigned b_off = (unsigned)((rl + 8 * (sel >> 1)) * SROW3 + 16 * (sel & 1));

    float acc[4][4][4];
    #pragma unroll
    for (int i = 0; i < 4; i++)
        #pragma unroll
        for (int j = 0; j < 4; j++)
            #pragma unroll
            for (int c = 0; c < 4; c++) acc[i][j][c] = 0.f;

    auto issue = [&](int t) {
        unsigned sb = smem_base + (t & 1) * STG3;
        int k0 = t << 5;
        #pragma unroll
        for (int i = 0; i < 2; i++) {
            int chunk = tid + (i << 8);
            int r = chunk >> 2, c = chunk & 3;
            unsigned doff = (unsigned)(r * SROW3 + c * 16);
            size_t goff = (size_t)r * K + k0 + c * 8;
            CP16(sb + doff,            (const void*)(A0 + goff));
            CP16(sb + MAT3 + doff,     (const void*)(A1 + goff));
            CP16(sb + 2 * MAT3 + doff, (const void*)(B0 + goff));
            CP16(sb + 3 * MAT3 + doff, (const void*)(B1 + goff));
        }
        CP_COMMIT();
    };

    issue(0);
    if (T > 1) issue(1);

    for (int t = 0; t < T; t++) {
        if (t + 1 < T) CP_WAIT1(); else CP_WAIT0();
        __syncthreads();

        unsigned sb = smem_base + (t & 1) * STG3;
        #pragma unroll
        for (int ks = 0; ks < 2; ks++) {
            unsigned bh[2][4], bl4[2][4];
            #pragma unroll
            for (int p = 0; p < 2; p++) {
                unsigned bd = sb + 2 * MAT3 + (unsigned)((wn * 32 + p * 16) * SROW3 + ks * 32) + b_off;
                ldsm_x4(bh[p], bd);
                ldsm_x4(bl4[p], bd + MAT3);
            }
            #pragma unroll
            for (int am = 0; am < 4; am++) {
                unsigned ah[4], al4[4];
                unsigned ad = sb + (unsigned)((wm * 64 + am * 16) * SROW3 + ks * 32) + a_off;
                ldsm_x4(ah, ad);
                ldsm_x4(al4, ad + MAT3);
                #pragma unroll
                for (int an = 0; an < 4; an++) {
                    const int p = an >> 1, q = (an & 1) * 2;
                    unsigned bfh[2] = { bh[p][q], bh[p][q + 1] };
                    unsigned bfl[2] = { bl4[p][q], bl4[p][q + 1] };
                    mma_f16(acc[am][an], ah, bfh);
                    mma_f16(acc[am][an], al4, bfh);
                    mma_f16(acc[am][an], ah, bfl);
                }
            }
        }
        __syncthreads();
        if (t + 2 < T) issue(t + 2);
    }

    #pragma unroll
    for (int am = 0; am < 4; am++) {
        int r0 = by * 128 + wm * 64 + am * 16 + gid;
        int r1 = r0 + 8;
        #pragma unroll
        for (int an = 0; an < 4; an++) {
            int n0 = bx * 128 + wn * 32 + an * 8 + 2 * tig;
            float bv0 = bias[n0], bv1 = bias[n0 + 1];
            size_t o0 = (size_t)r0 * N + n0;
            size_t o1 = (size_t)r1 * N + n0;
            float v0 = acc[am][an][0] + bv0;
            float v1 = acc[am][an][1] + bv1;
            float v2 = acc[am][an][2] + bv0;
            float v3 = acc[am][an][3] + bv1;
            unsigned hw, lw;
            split2h(v0, v1, hw, lw);
            *reinterpret_cast<unsigned*>(Ch + o0) = hw;
            *reinterpret_cast<unsigned*>(Cl + o0) = lw;
            split2h(v2, v3, hw, lw);
            *reinterpret_cast<unsigned*>(Ch + o1) = hw;
            *reinterpret_cast<unsigned*>(Cl + o1) = lw;
            if (pres && n0 >= DM) {
                int local = n0 - DM;
                int hh = local / DH, dd = local % DH;
                int b0 = r0 >> 10, s0 = r0 & 1023;
                int b1 = r1 >> 10, s1 = r1 & 1023;
                size_t p0 = (((size_t)(b0 * 2) * NH + hh) * SEQ + s0) * DH + dd;
                size_t p1 = (((size_t)(b1 * 2) * NH + hh) * SEQ + s1) * DH + dd;
                *reinterpret_cast<float2*>(pres + p0) = make_float2(v0, v1);
                *reinterpret_cast<float2*>(pres + p1) = make_float2(v2, v3);
            }
        }
    }
}

// ---------------- GEMM v1: fp16 1-pass (A single, B single) -----------------
#define STG1  (2*MAT3)
#define GEMM1_SMEM (2*STG1)

template<bool GELU, int OMODE>   // 0 = float out (+res), 2 = fp16 out (+V-present)
__global__ __launch_bounds__(256, 2) void bgemm1_kernel(
    const __half* __restrict__ Ah, const __half* __restrict__ Bh,
    const float* __restrict__ bias, const float* __restrict__ res,
    float* __restrict__ C, __half* __restrict__ Ch,
    float* __restrict__ pres, int M, int N, int K)
{
    extern __shared__ unsigned char sm1[];
    const int tid = threadIdx.x;
    const int w = tid >> 5, l = tid & 31;
    const int wm = w & 1, wn = w >> 1;
    const int gid = l >> 2, tig = l & 3;
    const int bx = blockIdx.x, by = blockIdx.y;
    const int T = K >> 5;

    const unsigned smem_base = (unsigned)__cvta_generic_to_shared(sm1);

    const __half* A0 = Ah + (size_t)(by * 128) * K;
    const __half* B0 = Bh + (size_t)(bx * 128) * K;

    const int rl = l & 7, sel = l >> 3;
    const unsigned a_off = (unsigned)((rl + 8 * (sel & 1)) * SROW3 + 16 * (sel >> 1));
    const unsigned b_off = (unsigned)((rl + 8 * (sel >> 1)) * SROW3 + 16 * (sel & 1));

    float acc[4][4][4];
    #pragma unroll
    for (int i = 0; i < 4; i++)
        #pragma unroll
        for (int j = 0; j < 4; j++)
            #pragma unroll
            for (int c = 0; c < 4; c++) acc[i][j][c] = 0.f;

    auto issue = [&](int t) {
        unsigned sb = smem_base + (t & 1) * STG1;
        int k0 = t << 5;
        #pragma unroll
        for (int i = 0; i < 2; i++) {
            int chunk = tid + (i << 8);
            int r = chunk >> 2, c = chunk & 3;
            unsigned doff = (unsigned)(r * SROW3 + c * 16);
            size_t goff = (size_t)r * K + k0 + c * 8;
            CP16(sb + doff,        (const void*)(A0 + goff));
            CP16(sb + MAT3 + doff, (const void*)(B0 + goff));
        }
        CP_COMMIT();
    };

    issue(0);
    if (T > 1) issue(1);

    for (int t = 0; t < T; t++) {
        if (t + 1 < T) CP_WAIT1(); else CP_WAIT0();
        __syncthreads();

        unsigned sb = smem_base + (t & 1) * STG1;
        #pragma unroll
        for (int ks = 0; ks < 2; ks++) {
            unsigned bh[2][4];
            #pragma unroll
            for (int p = 0; p < 2; p++) {
                unsigned bd = sb + MAT3 + (unsigned)((wn * 32 + p * 16) * SROW3 + ks * 32) + b_off;
                ldsm_x4(bh[p], bd);
            }
            #pragma unroll
            for (int am = 0; am < 4; am++) {
                unsigned ah[4];
                unsigned ad = sb + (unsigned)((wm * 64 + am * 16) * SROW3 + ks * 32) + a_off;
                ldsm_x4(ah, ad);
                #pragma unroll
                for (int an = 0; an < 4; an++) {
                    const int p = an >> 1, q = (an & 1) * 2;
                    unsigned bfh[2] = { bh[p][q], bh[p][q + 1] };
                    mma_f16(acc[am][an], ah, bfh);
                }
            }
        }
        __syncthreads();
        if (t + 2 < T) issue(t + 2);
    }

    #pragma unroll
    for (int am = 0; am < 4; am++) {
        int r0 = by * 128 + wm * 64 + am * 16 + gid;
        int r1 = r0 + 8;
        #pragma unroll
        for (int an = 0; an < 4; an++) {
            int n0 = bx * 128 + wn * 32 + an * 8 + 2 * tig;
            float bv0 = bias[n0], bv1 = bias[n0 + 1];
            size_t o0 = (size_t)r0 * N + n0;
            size_t o1 = (size_t)r1 * N + n0;
            float v0 = acc[am][an][0] + bv0;
            float v1 = acc[am][an][1] + bv1;
            float v2 = acc[am][an][2] + bv0;
            float v3 = acc[am][an][3] + bv1;
            if (res) {
                v0 += res[o0]; v1 += res[o0 + 1];
                v2 += res[o1]; v3 += res[o1 + 1];
            }
            if (GELU) {
                v0 = gelu_tanh_f(v0); v1 = gelu_tanh_f(v1);
                v2 = gelu_tanh_f(v2); v3 = gelu_tanh_f(v3);
            }
            if (OMODE == 0) {
                *reinterpret_cast<float2*>(C + o0) = make_float2(v0, v1);
                *reinterpret_cast<float2*>(C + o1) = make_float2(v2, v3);
            } else {
                *reinterpret_cast<unsigned*>(Ch + o0) = packh(v0, v1);
                *reinterpret_cast<unsigned*>(Ch + o1) = packh(v2, v3);
                if (pres) {
                    int hh = n0 / DH, dd = n0 % DH;
                    int b0 = r0 >> 10, s0 = r0 & 1023;
                    int b1 = r1 >> 10, s1 = r1 & 1023;
                    size_t p0 = (((size_t)(b0 * 2 + 1) * NH + hh) * SEQ + s0) * DH + dd;
                    size_t p1 = (((size_t)(b1 * 2 + 1) * NH + hh) * SEQ + s1) * DH + dd;
                    *reinterpret_cast<float2*>(pres + p0) = make_float2(v0, v1);
                    *reinterpret_cast<float2*>(pres + p1) = make_float2(v2, v3);
                }
            }
        }
    }
}

// ---------------- attention v8: fp16, split-KV, ex2.f16x2 softmax -----------
#define A6_ST 100
#define A6_QH 0
#define A6_QL 12800
#define A6_KH 25600
#define A6_KL 32000
#define A6_VH 38400
#define ATT6_SMEM_BYTES (44800*4)

__global__ __launch_bounds__(256, 1) void attn_v8_kernel(
    const __half* __restrict__ qkh, const __half* __restrict__ qkl,
    const __half* __restrict__ vbuf,
    __half* __restrict__ atth)
{
    extern __shared__ unsigned smu[];
    const int type = blockIdx.x;
    const int bi = c_bi[type];
    const int ch = c_ch[type];
    const int h  = blockIdx.y;
    const int b  = blockIdx.z;
    const int tid = threadIdx.x;
    const int w = tid >> 5, l = tid & 31;
    const int gid = l >> 2, tig = l & 3;

    const int j0 = (ch == 1) ? bi : 0;
    const int j1 = (ch == 0) ? bi : 2 * bi + 2;

    // scale * log2(e): scores live in the log2 domain
    const float scale2 = 13.856406460551018f * 1.4426950408889634f;
    const unsigned sbase = (unsigned)__cvta_generic_to_shared(smu);

    const int kcol = DM + h * DH;
    const int vcol = h * DH;

    auto issue_k = [&](int j) {
        const size_t row0 = (size_t)(b * SEQ + j * 64);
        #pragma unroll
        for (int i = 0; i < 6; i++) {
            int c = tid + (i << 8);
            int r = c / 24, cc2 = c % 24;
            unsigned doff = (unsigned)((r * A6_ST + cc2 * 4) * 4);
            size_t gk = (row0 + r) * D2 + kcol + cc2 * 8;
            CP16(sbase + A6_KH * 4 + doff, (const void*)(qkh + gk));
            CP16(sbase + A6_KL * 4 + doff, (const void*)(qkl + gk));
        }
        CP_COMMIT();
    };
    auto issue_v = [&](int j) {
        const size_t row0 = (size_t)(b * SEQ + j * 64);
        #pragma unroll
        for (int i = 0; i < 6; i++) {
            int c = tid + (i << 8);
            int r = c / 24, cc2 = c % 24;
            unsigned doff = (unsigned)((r * A6_ST + cc2 * 4) * 4);
            size_t gv = (row0 + r) * DM + vcol + cc2 * 8;
            CP16(sbase + A6_VH * 4 + doff, (const void*)(vbuf + gv));
        }
        CP_COMMIT();
    };

    // preload Q, K(j0), V(j0)
    {
        const size_t row0 = (size_t)(b * SEQ + bi * 128);
        const int qcol = h * DH;
        #pragma unroll
        for (int i = 0; i < 12; i++) {
            int c = tid + (i << 8);
            int r = c / 24, cc2 = c % 24;
            unsigned doff = (unsigned)((r * A6_ST + cc2 * 4) * 4);
            size_t goff = (row0 + r) * D2 + qcol + cc2 * 8;
            CP16(sbase + A6_QH * 4 + doff, (const void*)(qkh + goff));
            CP16(sbase + A6_QL * 4 + doff, (const void*)(qkl + goff));
        }
        CP_COMMIT();
    }
    issue_k(j0);
    issue_v(j0);

    float m0 = -1e30f, m1 = -1e30f, l0 = 0.f, l1 = 0.f;   // m in log2 domain
    float accO[24][4];
    #pragma unroll
    for (int i = 0; i < 24; i++)
        #pragma unroll
        for (int c = 0; c < 4; c++) accO[i][c] = 0.f;

    const int lm_rwi  = (l & 7) + ((l >> 3) & 1) * 8;
    const int lm_ncol = (l >> 4) * 8;
    const unsigned vh_base = sbase + A6_VH * 4;

    const int qg0 = bi * 128 + w * 16 + gid;
    const int qg1 = qg0 + 8;

    for (int j = j0; j < j1; j++) {
        CP_WAIT1();
        __syncthreads();

        const bool diag = (j >= 2 * bi);
        const bool wskip = diag && (64 * j >= bi * 128 + w * 16 + 16);

        const unsigned* Qh = smu + A6_QH;
        const unsigned* Ql = smu + A6_QL;
        const unsigned* Kh = smu + A6_KH;
        const unsigned* Kl = smu + A6_KL;

        unsigned pha[4][4];
        float corr0 = 1.f, corr1 = 1.f;

        if (!wskip) {
            float accS[8][4];
            #pragma unroll
            for (int i = 0; i < 8; i++)
                #pragma unroll
                for (int c = 0; c < 4; c++) accS[i][c] = 0.f;

            #pragma unroll
            for (int ks = 0; ks < 12; ks++) {
                int kp = ks * 8;
                unsigned ah[4], al[4];
                int a0 = (w * 16 + gid) * A6_ST + kp + tig;
                int a1 = a0 + 8 * A6_ST;
                ah[0] = Qh[a0]; ah[1] = Qh[a1]; ah[2] = Qh[a0 + 4]; ah[3] = Qh[a1 + 4];
                al[0] = Ql[a0]; al[1] = Ql[a1]; al[2] = Ql[a0 + 4]; al[3] = Ql[a1 + 4];
                #pragma unroll
                for (int nt = 0; nt < 8; nt++) {
                    int bb = (nt * 8 + gid) * A6_ST + kp + tig;
                    unsigned bh[2], bl2[2];
                    bh[0]  = Kh[bb]; bh[1]  = Kh[bb + 4];
                    bl2[0] = Kl[bb]; bl2[1] = Kl[bb + 4];
                    mma_f16(accS[nt], ah, bh);
                    mma_f16(accS[nt], al, bh);
                    mma_f16(accS[nt], ah, bl2);
                }
            }

            float mx0 = -1e30f, mx1 = -1e30f;
            #pragma unroll
            for (int nt = 0; nt < 8; nt++) {
                int kg = j * 64 + nt * 8 + 2 * tig;
                float v0 = accS[nt][0] * scale2;
                float v1 = accS[nt][1] * scale2;
                float v2 = accS[nt][2] * scale2;
                float v3 = accS[nt][3] * scale2;
                if (diag) {
                    if (kg     > qg0) v0 = -1e30f;
                    if (kg + 1 > qg0) v1 = -1e30f;
                    if (kg     > qg1) v2 = -1e30f;
                    if (kg + 1 > qg1) v3 = -1e30f;
                }
                accS[nt][0] = v0; accS[nt][1] = v1;
                accS[nt][2] = v2; accS[nt][3] = v3;
                mx0 = fmaxf(mx0, fmaxf(v0, v1));
                mx1 = fmaxf(mx1, fmaxf(v2, v3));
            }
            mx0 = fmaxf(mx0, __shfl_xor_sync(0xffffffffu, mx0, 1));
            mx0 = fmaxf(mx0, __shfl_xor_sync(0xffffffffu, mx0, 2));
            mx1 = fmaxf(mx1, __shfl_xor_sync(0xffffffffu, mx1, 1));
            mx1 = fmaxf(mx1, __shfl_xor_sync(0xffffffffu, mx1, 2));
            float mn0 = fmaxf(m0, mx0), mn1 = fmaxf(m1, mx1);
            corr0 = exp2f(m0 - mn0); corr1 = exp2f(m1 - mn1);

            float sum0 = 0.f, sum1 = 0.f;
            #pragma unroll
            for (int nt = 0; nt < 8; nt++) {
                unsigned u01 = ex2h2(accS[nt][0] - mn0, accS[nt][1] - mn0);
                unsigned u23 = ex2h2(accS[nt][2] - mn1, accS[nt][3] - mn1);
                const int ks = nt >> 1;
                const int s0 = (nt & 1) * 2;
                pha[ks][s0]     = u01;
                pha[ks][s0 + 1] = u23;
                float2 f01 = __half22float2(*reinterpret_cast<__half2*>(&u01));
                float2 f23 = __half22float2(*reinterpret_cast<__half2*>(&u23));
                sum0 += f01.x + f01.y;
                sum1 += f23.x + f23.y;
            }
            sum0 += __shfl_xor_sync(0xffffffffu, sum0, 1);
            sum0 += __shfl_xor_sync(0xffffffffu, sum0, 2);
            sum1 += __shfl_xor_sync(0xffffffffu, sum1, 1);
            sum1 += __shfl_xor_sync(0xffffffffu, sum1, 2);
            l0 = l0 * corr0 + sum0;  m0 = mn0;
            l1 = l1 * corr1 + sum1;  m1 = mn1;
        }

        CP_WAIT0();
        __syncthreads();
        if (j + 1 < j1) issue_k(j + 1);

        if (!wskip) {
            #pragma unroll
            for (int nt = 0; nt < 24; nt++) {
                accO[nt][0] *= corr0; accO[nt][1] *= corr0;
                accO[nt][2] *= corr1; accO[nt][3] *= corr1;
            }
            #pragma unroll
            for (int ks = 0; ks < 4; ks++) {
                unsigned rowoff = (unsigned)((ks * 16 + lm_rwi) * A6_ST) * 4u;
                #pragma unroll
                for (int g = 0; g < 12; g++) {
                    unsigned coloff = (unsigned)(g * 8 + lm_ncol / 2) * 4u;
                    unsigned bh0, bh1, bh2, bh3;
                    ldsm_x4_t(bh0, bh1, bh2, bh3, vh_base + rowoff + coloff);
                    unsigned bfh[2];
                    bfh[0] = bh0; bfh[1] = bh1;
                    mma_f16(accO[2 * g],     pha[ks], bfh);
                    bfh[0] = bh2; bfh[1] = bh3;
                    mma_f16(accO[2 * g + 1], pha[ks], bfh);
                }
            }
        }

        __syncthreads();
        if (j + 1 < j1) issue_v(j + 1);
    }

    if (ch < 0) {
        float li0 = 1.0f / l0, li1 = 1.0f / l1;
        int row0 = b * SEQ + bi * 128 + w * 16 + gid;
        #pragma unroll
        for (int nt = 0; nt < 24; nt++) {
            int col = h * DH + nt * 8 + 2 * tig;
            size_t o0 = (size_t)row0 * DM + col;
            size_t o1 = (size_t)(row0 + 8) * DM + col;
            *reinterpret_cast<unsigned*>(atth + o0) = packh(accO[nt][0] * li0, accO[nt][1] * li0);
            *reinterpret_cast<unsigned*>(atth + o1) = packh(accO[nt][2] * li1, accO[nt][3] * li1);
        }
    } else {
        const int pidx = ((b * NH + h) << 2) + (bi - 4);
        float* po = g_po + ((size_t)ch * 128 + pidx) * (128 * 192);
        const int r0 = w * 16 + gid, r1 = r0 + 8;
        #pragma unroll
        for (int nt = 0; nt < 24; nt++) {
            int col = nt * 8 + 2 * tig;
            *reinterpret_cast<float2*>(po + r0 * 192 + col) = make_float2(accO[nt][0], accO[nt][1]);
            *reinterpret_cast<float2*>(po + r1 * 192 + col) = make_float2(accO[nt][2], accO[nt][3]);
        }
        if (tig == 0) {
            int mlb = (ch * 128 + pidx) * 128;
            g_pm[mlb + r0] = m0; g_pl[mlb + r0] = l0;
            g_pm[mlb + r1] = m1; g_pl[mlb + r1] = l1;
        }
    }
}

// ---------------- split-KV combine (m in log2 domain) ------------------------
__global__ __launch_bounds__(256) void attn_combine_kernel(__half* __restrict__ atth)
{
    const int pidx = blockIdx.x;
    const int b  = pidx >> 4;
    const int h  = (pidx >> 2) & 3;
    const int bi = 4 + (pidx & 3);
    const int r  = threadIdx.x >> 1;
    const int c0 = (threadIdx.x & 1) * 96;

    const float* po0 = g_po + ((size_t)0 * 128 + pidx) * (128 * 192) + r * 192 + c0;
    const float* po1 = g_po + ((size_t)1 * 128 + pidx) * (128 * 192) + r * 192 + c0;
    const int mlb0 = (0 * 128 + pidx) * 128 + r;
    const int mlb1 = (1 * 128 + pidx) * 128 + r;
    float m0 = g_pm[mlb0], l0 = g_pl[mlb0];
    float m1 = g_pm[mlb1], l1 = g_pl[mlb1];
    float m = fmaxf(m0, m1);
    float e0 = exp2f(m0 - m), e1 = exp2f(m1 - m);
    float linv = 1.0f / (e0 * l0 + e1 * l1);

    size_t go = (size_t)(b * SEQ + bi * 128 + r) * DM + h * DH + c0;
    #pragma unroll
    for (int c = 0; c < 96; c += 2) {
        float v0 = (e0 * po0[c]     + e1 * po1[c])     * linv;
        float v1 = (e0 * po0[c + 1] + e1 * po1[c + 1]) * linv;
        *reinterpret_cast<unsigned*>(atth + go + c) = packh(v0, v1);
    }
}

// ---------------- launch -----------------------------------------------
extern "C" void kernel_launch(void* const* d_in, const int* in_sizes, int n_in,
                              void* d_out, int out_size)
{
    const float* x   = (const float*)d_in[0];
    const float* W1  = (const float*)d_in[2];
    const float* b1  = (const float*)d_in[3];
    const float* W3  = (const float*)d_in[4];
    const float* b3  = (const float*)d_in[5];
    const float* W2  = (const float*)d_in[6];
    const float* b2  = (const float*)d_in[7];
    const float* W4  = (const float*)d_in[8];
    const float* b4  = (const float*)d_in[9];
    const float* g1  = (const float*)d_in[10];
    const float* be1 = (const float*)d_in[11];
    const float* g2  = (const float*)d_in[12];
    const float* be2 = (const float*)d_in[13];
    float* out = (float*)d_out;

    float *x1;
    cudaGetSymbolAddress((void**)&x1, g_x1);
    __half *qkh, *qkl, *vh, *xnh, *xnl, *atth, *xn2h, *hh;
    __half *w1h, *w1l, *w3h, *w2h, *w4h;
    cudaGetSymbolAddress((void**)&qkh,  g_qkh);  cudaGetSymbolAddress((void**)&qkl,  g_qkl);
    cudaGetSymbolAddress((void**)&vh,   g_vh);
    cudaGetSymbolAddress((void**)&xnh,  g_xnh);  cudaGetSymbolAddress((void**)&xnl,  g_xnl);
    cudaGetSymbolAddress((void**)&atth, g_atth);
    cudaGetSymbolAddress((void**)&xn2h, g_xn2h);
    cudaGetSymbolAddress((void**)&hh,   g_hh);
    cudaGetSymbolAddress((void**)&w1h,  g_w1h);  cudaGetSymbolAddress((void**)&w1l,  g_w1l);
    cudaGetSymbolAddress((void**)&w3h,  g_w3h);
    cudaGetSymbolAddress((void**)&w2h,  g_w2h);
    cudaGetSymbolAddress((void**)&w4h,  g_w4h);

    cudaFuncSetAttribute(attn_v8_kernel,
                         cudaFuncAttributeMaxDynamicSharedMemorySize, ATT6_SMEM_BYTES);
    cudaFuncSetAttribute(bgemm3f_kernel,
                         cudaFuncAttributeMaxDynamicSharedMemorySize, GEMM3_SMEM);
    cudaFuncSetAttribute(bgemm1_kernel<false,0>,
                         cudaFuncAttributeMaxDynamicSharedMemorySize, GEMM1_SMEM);
    cudaFuncSetAttribute(bgemm1_kernel<true,2>,
                         cudaFuncAttributeMaxDynamicSharedMemorySize, GEMM1_SMEM);
    cudaFuncSetAttribute(bgemm1_kernel<false,2>,
                         cudaFuncAttributeMaxDynamicSharedMemorySize, GEMM1_SMEM);

    float* pres = out + XOUT_ELEMS;
    bool has_present = ((size_t)out_size >= XOUT_ELEMS + PRES_ELEMS);
    float* presp = has_present ? pres : nullptr;

    // 0) weight prep
    wsplit_h2_kernel<<<dim3(D2/32, DM/32), 256>>>(W1, w1h, w1l, DM, D3);
    wsplit_h2_kernel<<<dim3(DM/32, DM/32), 256>>>(W1 + D2, w1h + (size_t)D2 * DM, nullptr, DM, D3);
    wsplit_h2_kernel<<<dim3(DM/32, DM/32), 256>>>(W3, w3h, nullptr, DM, DM);
    wsplit_h2_kernel<<<dim3(D4/32, DM/32), 256>>>(W2, w2h, nullptr, DM, D4);
    wsplit_h2_kernel<<<dim3(DM/32, D4/32), 256>>>(W4, w4h, nullptr, D4, DM);

    // 1) LN1 -> fp16 split
    ln_kernel<true><<<ROWS, 256>>>(x, g1, be1, xnh, xnl);

    // 2a) qk (fp16 3-pass) -> split fp16 (+ K present)
    bgemm3f_kernel<<<dim3(D2/128, ROWS/128), 256, GEMM3_SMEM>>>(
        xnh, xnl, w1h, w1l, b1, qkh, qkl, presp, ROWS, D2, DM);

    // 2b) v (fp16 1-pass) -> single fp16 (+ V present)
    bgemm1_kernel<false,2><<<dim3(DM/128, ROWS/128), 256, GEMM1_SMEM>>>(
        xnh, w1h + (size_t)D2 * DM, b1 + D2, nullptr,
        nullptr, vh, presp, ROWS, DM, DM);

    // 3) attention: split-KV main (ex2 softmax) + combine
    attn_v8_kernel<<<dim3(12, NH, BS), 256, ATT6_SMEM_BYTES>>>(qkh, qkl, vh, atth);
    attn_combine_kernel<<<128, 256>>>(atth);

    // 4) x1 = att @ W3 + b3 + x
    bgemm1_kernel<false,0><<<dim3(DM/128, ROWS/128), 256, GEMM1_SMEM>>>(
        atth, w3h, b3, x, x1, nullptr, nullptr, ROWS, DM, DM);

    // 5) LN2 -> fp16 single
    ln_kernel<false><<<ROWS, 256>>>(x1, g2, be2, xn2h, nullptr);

    // 6) h = gelu(xn2 @ W2 + b2) -> fp16 single
    bgemm1_kernel<true,2><<<dim3(D4/128, ROWS/128), 256, GEMM1_SMEM>>>(
        xn2h, w2h, b2, nullptr, nullptr, hh, nullptr, ROWS, D4, DM);

    // 7) out = h @ W4 + b4 + x1
    bgemm1_kernel<false,0><<<dim3(DM/128, ROWS/128), 256, GEMM1_SMEM>>>(
        hh, w4h, b4, x1, out, nullptr, nullptr, ROWS, DM, D4);
}

// round 15
// speedup vs baseline: 1.9414x; 1.0010x over previous
#include <cuda_runtime.h>
#include <cuda_bf16.h>
#include <cuda_fp16.h>
#include <math.h>

// ---------------- problem constants ----------------
#define BS   8
#define SEQ  1024
#define DM   768
#define NH   4
#define DH   192
#define ROWS (BS*SEQ)          // 8192
#define D3   (3*DM)            // 2304
#define D4   (4*DM)            // 3072
#define D2   (2*DM)            // 1536

#define XOUT_ELEMS   ((size_t)ROWS*DM)
#define PRES_ELEMS   ((size_t)BS*2*NH*SEQ*DH)

#define PERSIST_GRID 296       // 148 SMs x 2 CTA/SM

// ---------------- scratch (device globals) ---------------------------------
__device__ __align__(256) float g_x1 [ROWS*DM];

__device__ __align__(256) __half g_qkh[(size_t)ROWS*D2], g_qkl[(size_t)ROWS*D2];
__device__ __align__(256) __half g_vh [(size_t)ROWS*DM];
__device__ __align__(256) __half g_xnh [ROWS*DM],  g_xnl [ROWS*DM];
__device__ __align__(256) __half g_atth[ROWS*DM];
__device__ __align__(256) __half g_xn2h[ROWS*DM];
__device__ __align__(256) __half g_hh[(size_t)ROWS*D4];

// transposed weights: [N][K]
__device__ __align__(256) __half g_w1h[(size_t)D3*DM], g_w1l[(size_t)D2*DM];
__device__ __align__(256) __half g_w3h[(size_t)DM*DM];
__device__ __align__(256) __half g_w2h[(size_t)D4*DM];
__device__ __align__(256) __half g_w4h[(size_t)DM*D4];

// split-KV partials
__device__ __align__(256) float g_po[(size_t)2*128*128*192];
__device__ __align__(256) float g_pm[2*128*128];
__device__ __align__(256) float g_pl[2*128*128];

__device__ const int c_bi[12] = {7,6,3,5,7,2,4,6,5,1,4,0};
__device__ const int c_ch[12] = {1,1,-1,1,0,-1,1,0,0,-1,0,-1};

// ---------------- helpers ---------------------------------------------------
__device__ __forceinline__ void split2h(float x0, float x1, unsigned &hi, unsigned &lo) {
    __half h0 = __float2half_rn(x0);
    __half h1 = __float2half_rn(x1);
    __half l0 = __float2half_rn(x0 - __half2float(h0));
    __half l1 = __float2half_rn(x1 - __half2float(h1));
    hi = ((unsigned)__half_as_ushort(h1) << 16) | (unsigned)__half_as_ushort(h0);
    lo = ((unsigned)__half_as_ushort(l1) << 16) | (unsigned)__half_as_ushort(l0);
}

__device__ __forceinline__ unsigned packh(float x0, float x1) {
    __half h0 = __float2half_rn(x0);
    __half h1 = __float2half_rn(x1);
    return ((unsigned)__half_as_ushort(h1) << 16) | (unsigned)__half_as_ushort(h0);
}

__device__ __forceinline__ unsigned ex2h2(float x0, float x1) {
    unsigned hin = packh(x0, x1);
    unsigned r;
    asm("ex2.approx.f16x2 %0, %1;" : "=r"(r) : "r"(hin));
    return r;
}

__device__ __forceinline__ void mma_f16(float c[4], const unsigned a[4], const unsigned b[2]) {
    asm volatile(
        "mma.sync.aligned.m16n8k16.row.col.f32.f16.f16.f32 "
        "{%0,%1,%2,%3}, {%4,%5,%6,%7}, {%8,%9}, {%0,%1,%2,%3};\n"
        : "+f"(c[0]), "+f"(c[1]), "+f"(c[2]), "+f"(c[3])
        : "r"(a[0]), "r"(a[1]), "r"(a[2]), "r"(a[3]), "r"(b[0]), "r"(b[1]));
}

__device__ __forceinline__ void ldsm_x4(unsigned r[4], unsigned addr) {
    asm volatile("ldmatrix.sync.aligned.m8n8.x4.shared.b16 {%0,%1,%2,%3}, [%4];"
        : "=r"(r[0]), "=r"(r[1]), "=r"(r[2]), "=r"(r[3]) : "r"(addr));
}

__device__ __forceinline__ void ldsm_x4_t(unsigned &r0, unsigned &r1, unsigned &r2, unsigned &r3, unsigned saddr) {
    asm volatile("ldmatrix.sync.aligned.m8n8.x4.trans.shared.b16 {%0,%1,%2,%3}, [%4];"
        : "=r"(r0), "=r"(r1), "=r"(r2), "=r"(r3) : "r"(saddr));
}

#define CP16(dst, src) asm volatile("cp.async.cg.shared.global [%0], [%1], 16;\n" :: "r"(dst), "l"(src))
#define CP_COMMIT() asm volatile("cp.async.commit_group;\n" ::)
#define CP_WAIT0()  asm volatile("cp.async.wait_group 0;\n" ::)
#define CP_WAIT1()  asm volatile("cp.async.wait_group 1;\n" ::)

__device__ __forceinline__ float gelu_tanh_f(float x) {
    float x3 = x * x * x;
    float t  = tanhf(0.7978845608028654f * (x + 0.044715f * x3));
    return 0.5f * x * (1.0f + t);
}

// ---------------- weight transpose + split (fp16 hi/lo, lo optional) --------
__global__ __launch_bounds__(256) void wsplit_h2_kernel(
    const float* __restrict__ W, __half* __restrict__ Th,
    __half* __restrict__ Tl, int K, int N)
{
    __shared__ float t[32][33];
    int n0 = blockIdx.x * 32, k0 = blockIdx.y * 32;
    int tx = threadIdx.x & 31, ty = threadIdx.x >> 5;
    #pragma unroll
    for (int j = 0; j < 4; j++)
        t[ty + 8 * j][tx] = W[(size_t)(k0 + ty + 8 * j) * N + n0 + tx];
    __syncthreads();
    #pragma unroll
    for (int j = 0; j < 4; j++) {
        float v = t[tx][ty + 8 * j];
        __half hi = __float2half_rn(v);
        size_t o = (size_t)(n0 + ty + 8 * j) * K + k0 + tx;
        Th[o] = hi;
        if (Tl) Tl[o] = __float2half_rn(v - __half2float(hi));
    }
}

// ---------------- LayerNorm -> fp16 (optionally split) ----------------------
template<bool SPLIT>
__global__ __launch_bounds__(256) void ln_kernel(
    const float* __restrict__ x, const float* __restrict__ gamma,
    const float* __restrict__ beta, __half* __restrict__ oh, __half* __restrict__ ol)
{
    int row = blockIdx.x;
    int tid = threadIdx.x;
    const float* xr = x + (size_t)row * DM;
    float v0 = xr[tid], v1 = xr[tid + 256], v2 = xr[tid + 512];
    float s  = v0 + v1 + v2;
    float sq = v0*v0 + v1*v1 + v2*v2;
    #pragma unroll
    for (int o = 16; o > 0; o >>= 1) {
        s  += __shfl_xor_sync(0xffffffffu, s,  o);
        sq += __shfl_xor_sync(0xffffffffu, sq, o);
    }
    __shared__ float ss[8], ssq[8];
    __shared__ float mu_s, rs_s;
    int w = tid >> 5, l = tid & 31;
    if (l == 0) { ss[w] = s; ssq[w] = sq; }
    __syncthreads();
    if (tid == 0) {
        float S = 0.f, SQ = 0.f;
        #pragma unroll
        for (int i = 0; i < 8; i++) { S += ss[i]; SQ += ssq[i]; }
        float mu = S * (1.0f / DM);
        float var = SQ * (1.0f / DM) - mu * mu;
        mu_s = mu;
        rs_s = rsqrtf(var + 1e-3f);
    }
    __syncthreads();
    float mu = mu_s, rs = rs_s;
    size_t ro = (size_t)row * DM;
    #pragma unroll
    for (int q = 0; q < 3; q++) {
        int c = tid + q * 256;
        float v = (q == 0 ? v0 : (q == 1 ? v1 : v2));
        float y = (v - mu) * rs * gamma[c] + beta[c];
        __half hi = __float2half_rn(y);
        oh[ro + c] = hi;
        if (SPLIT) ol[ro + c] = __float2half_rn(y - __half2float(hi));
    }
}

// ---------------- GEMM f3: fp16 3-pass (A split, B split), persistent -------
#define SROW3 80
#define MAT3  (128*SROW3)
#define STG3  (4*MAT3)
#define GEMM3_SMEM (2*STG3)

__global__ __launch_bounds__(256, 2) void bgemm3f_kernel(
    const __half* __restrict__ Ah, const __half* __restrict__ Al,
    const __half* __restrict__ Bh, const __half* __restrict__ Bl,
    const float* __restrict__ bias,
    __half* __restrict__ Ch, __half* __restrict__ Cl,
    float* __restrict__ pres, int M, int N, int K)
{
    extern __shared__ unsigned char sm3[];
    const int tid = threadIdx.x;
    const int w = tid >> 5, l = tid & 31;
    const int wm = w & 1, wn = w >> 1;
    const int gid = l >> 2, tig = l & 3;
    const int T = K >> 5;
    const int nbx = N >> 7;
    const int ntile = (M >> 7) * nbx;

    const unsigned smem_base = (unsigned)__cvta_generic_to_shared(sm3);
    const int rl = l & 7, sel = l >> 3;
    const unsigned a_off = (unsigned)((rl + 8 * (sel & 1)) * SROW3 + 16 * (sel >> 1));
    const unsigned b_off = (unsigned)((rl + 8 * (sel >> 1)) * SROW3 + 16 * (sel & 1));

    for (int tile = blockIdx.x; tile < ntile; tile += gridDim.x) {
        const int by = tile / nbx, bx = tile % nbx;
        const __half* A0 = Ah + (size_t)(by * 128) * K;
        const __half* A1 = Al + (size_t)(by * 128) * K;
        const __half* B0 = Bh + (size_t)(bx * 128) * K;
        const __half* B1 = Bl + (size_t)(bx * 128) * K;

        float acc[4][4][4];
        #pragma unroll
        for (int i = 0; i < 4; i++)
            #pragma unroll
            for (int j = 0; j < 4; j++)
                #pragma unroll
                for (int c = 0; c < 4; c++) acc[i][j][c] = 0.f;

        auto issue = [&](int t) {
            unsigned sb = smem_base + (t & 1) * STG3;
            int k0 = t << 5;
            #pragma unroll
            for (int i = 0; i < 2; i++) {
                int chunk = tid + (i << 8);
                int r = chunk >> 2, c = chunk & 3;
                unsigned doff = (unsigned)(r * SROW3 + c * 16);
                size_t goff = (size_t)r * K + k0 + c * 8;
                CP16(sb + doff,            (const void*)(A0 + goff));
                CP16(sb + MAT3 + doff,     (const void*)(A1 + goff));
                CP16(sb + 2 * MAT3 + doff, (const void*)(B0 + goff));
                CP16(sb + 3 * MAT3 + doff, (const void*)(B1 + goff));
            }
            CP_COMMIT();
        };

        __syncthreads();          // protect smem reuse across tiles
        issue(0);
        issue(1);

        for (int t = 0; t < T; t++) {
            if (t + 1 < T) CP_WAIT1(); else CP_WAIT0();
            __syncthreads();

            unsigned sb = smem_base + (t & 1) * STG3;
            #pragma unroll
            for (int ks = 0; ks < 2; ks++) {
                unsigned bh[2][4], bl4[2][4];
                #pragma unroll
                for (int p = 0; p < 2; p++) {
                    unsigned bd = sb + 2 * MAT3 + (unsigned)((wn * 32 + p * 16) * SROW3 + ks * 32) + b_off;
                    ldsm_x4(bh[p], bd);
                    ldsm_x4(bl4[p], bd + MAT3);
                }
                #pragma unroll
                for (int am = 0; am < 4; am++) {
                    unsigned ah[4], al4[4];
                    unsigned ad = sb + (unsigned)((wm * 64 + am * 16) * SROW3 + ks * 32) + a_off;
                    ldsm_x4(ah, ad);
                    ldsm_x4(al4, ad + MAT3);
                    #pragma unroll
                    for (int an = 0; an < 4; an++) {
                        const int p = an >> 1, q = (an & 1) * 2;
                        unsigned bfh[2] = { bh[p][q], bh[p][q + 1] };
                        unsigned bfl[2] = { bl4[p][q], bl4[p][q + 1] };
                        mma_f16(acc[am][an], ah, bfh);
                        mma_f16(acc[am][an], al4, bfh);
                        mma_f16(acc[am][an], ah, bfl);
                    }
                }
            }
            __syncthreads();
            if (t + 2 < T) issue(t + 2);
        }

        #pragma unroll
        for (int am = 0; am < 4; am++) {
            int r0 = by * 128 + wm * 64 + am * 16 + gid;
            int r1 = r0 + 8;
            #pragma unroll
            for (int an = 0; an < 4; an++) {
                int n0 = bx * 128 + wn * 32 + an * 8 + 2 * tig;
                float bv0 = bias[n0], bv1 = bias[n0 + 1];
                size_t o0 = (size_t)r0 * N + n0;
                size_t o1 = (size_t)r1 * N + n0;
                float v0 = acc[am][an][0] + bv0;
                float v1 = acc[am][an][1] + bv1;
                float v2 = acc[am][an][2] + bv0;
                float v3 = acc[am][an][3] + bv1;
                unsigned hw, lw;
                split2h(v0, v1, hw, lw);
                *reinterpret_cast<unsigned*>(Ch + o0) = hw;
                *reinterpret_cast<unsigned*>(Cl + o0) = lw;
                split2h(v2, v3, hw, lw);
                *reinterpret_cast<unsigned*>(Ch + o1) = hw;
                *reinterpret_cast<unsigned*>(Cl + o1) = lw;
                if (pres && n0 >= DM) {
                    int local = n0 - DM;
                    int hh = local / DH, dd = local % DH;
                    int b0 = r0 >> 10, s0 = r0 & 1023;
                    int b1 = r1 >> 10, s1 = r1 & 1023;
                    size_t p0 = (((size_t)(b0 * 2) * NH + hh) * SEQ + s0) * DH + dd;
                    size_t p1 = (((size_t)(b1 * 2) * NH + hh) * SEQ + s1) * DH + dd;
                    *reinterpret_cast<float2*>(pres + p0) = make_float2(v0, v1);
                    *reinterpret_cast<float2*>(pres + p1) = make_float2(v2, v3);
                }
            }
        }
    }
}

// ---------------- GEMM v1: fp16 1-pass (A single, B single), persistent -----
#define STG1  (2*MAT3)
#define GEMM1_SMEM (2*STG1)

template<bool GELU, int OMODE>   // 0 = float out (+res), 2 = fp16 out (+V-present)
__global__ __launch_bounds__(256, 2) void bgemm1_kernel(
    const __half* __restrict__ Ah, const __half* __restrict__ Bh,
    const float* __restrict__ bias, const float* __restrict__ res,
    float* __restrict__ C, __half* __restrict__ Ch,
    float* __restrict__ pres, int M, int N, int K)
{
    extern __shared__ unsigned char sm1[];
    const int tid = threadIdx.x;
    const int w = tid >> 5, l = tid & 31;
    const int wm = w & 1, wn = w >> 1;
    const int gid = l >> 2, tig = l & 3;
    const int T = K >> 5;
    const int nbx = N >> 7;
    const int ntile = (M >> 7) * nbx;

    const unsigned smem_base = (unsigned)__cvta_generic_to_shared(sm1);
    const int rl = l & 7, sel = l >> 3;
    const unsigned a_off = (unsigned)((rl + 8 * (sel & 1)) * SROW3 + 16 * (sel >> 1));
    const unsigned b_off = (unsigned)((rl + 8 * (sel >> 1)) * SROW3 + 16 * (sel & 1));

    for (int tile = blockIdx.x; tile < ntile; tile += gridDim.x) {
        const int by = tile / nbx, bx = tile % nbx;
        const __half* A0 = Ah + (size_t)(by * 128) * K;
        const __half* B0 = Bh + (size_t)(bx * 128) * K;

        float acc[4][4][4];
        #pragma unroll
        for (int i = 0; i < 4; i++)
            #pragma unroll
            for (int j = 0; j < 4; j++)
                #pragma unroll
                for (int c = 0; c < 4; c++) acc[i][j][c] = 0.f;

        auto issue = [&](int t) {
            unsigned sb = smem_base + (t & 1) * STG1;
            int k0 = t << 5;
            #pragma unroll
            for (int i = 0; i < 2; i++) {
                int chunk = tid + (i << 8);
                int r = chunk >> 2, c = chunk & 3;
                unsigned doff = (unsigned)(r * SROW3 + c * 16);
                size_t goff = (size_t)r * K + k0 + c * 8;
                CP16(sb + doff,        (const void*)(A0 + goff));
                CP16(sb + MAT3 + doff, (const void*)(B0 + goff));
            }
            CP_COMMIT();
        };

        __syncthreads();          // protect smem reuse across tiles
        issue(0);
        issue(1);

        for (int t = 0; t < T; t++) {
            if (t + 1 < T) CP_WAIT1(); else CP_WAIT0();
            __syncthreads();

            unsigned sb = smem_base + (t & 1) * STG1;
            #pragma unroll
            for (int ks = 0; ks < 2; ks++) {
                unsigned bh[2][4];
                #pragma unroll
                for (int p = 0; p < 2; p++) {
                    unsigned bd = sb + MAT3 + (unsigned)((wn * 32 + p * 16) * SROW3 + ks * 32) + b_off;
                    ldsm_x4(bh[p], bd);
                }
                #pragma unroll
                for (int am = 0; am < 4; am++) {
                    unsigned ah[4];
                    unsigned ad = sb + (unsigned)((wm * 64 + am * 16) * SROW3 + ks * 32) + a_off;
                    ldsm_x4(ah, ad);
                    #pragma unroll
                    for (int an = 0; an < 4; an++) {
                        const int p = an >> 1, q = (an & 1) * 2;
                        unsigned bfh[2] = { bh[p][q], bh[p][q + 1] };
                        mma_f16(acc[am][an], ah, bfh);
                    }
                }
            }
            __syncthreads();
            if (t + 2 < T) issue(t + 2);
        }

        #pragma unroll
        for (int am = 0; am < 4; am++) {
            int r0 = by * 128 + wm * 64 + am * 16 + gid;
            int r1 = r0 + 8;
            #pragma unroll
            for (int an = 0; an < 4; an++) {
                int n0 = bx * 128 + wn * 32 + an * 8 + 2 * tig;
                float bv0 = bias[n0], bv1 = bias[n0 + 1];
                size_t o0 = (size_t)r0 * N + n0;
                size_t o1 = (size_t)r1 * N + n0;
                float v0 = acc[am][an][0] + bv0;
                float v1 = acc[am][an][1] + bv1;
                float v2 = acc[am][an][2] + bv0;
                float v3 = acc[am][an][3] + bv1;
                if (res) {
                    v0 += res[o0]; v1 += res[o0 + 1];
                    v2 += res[o1]; v3 += res[o1 + 1];
                }
                if (GELU) {
                    v0 = gelu_tanh_f(v0); v1 = gelu_tanh_f(v1);
                    v2 = gelu_tanh_f(v2); v3 = gelu_tanh_f(v3);
                }
                if (OMODE == 0) {
                    *reinterpret_cast<float2*>(C + o0) = make_float2(v0, v1);
                    *reinterpret_cast<float2*>(C + o1) = make_float2(v2, v3);
                } else {
                    *reinterpret_cast<unsigned*>(Ch + o0) = packh(v0, v1);
                    *reinterpret_cast<unsigned*>(Ch + o1) = packh(v2, v3);
                    if (pres) {
                        int hh = n0 / DH, dd = n0 % DH;
                        int b0 = r0 >> 10, s0 = r0 & 1023;
                        int b1 = r1 >> 10, s1 = r1 & 1023;
                        size_t p0 = (((size_t)(b0 * 2 + 1) * NH + hh) * SEQ + s0) * DH + dd;
                        size_t p1 = (((size_t)(b1 * 2 + 1) * NH + hh) * SEQ + s1) * DH + dd;
                        *reinterpret_cast<float2*>(pres + p0) = make_float2(v0, v1);
                        *reinterpret_cast<float2*>(pres + p1) = make_float2(v2, v3);
                    }
                }
            }
        }
    }
}

// ---------------- attention v8: fp16, split-KV, ex2.f16x2 softmax -----------
#define A6_ST 100
#define A6_QH 0
#define A6_QL 12800
#define A6_KH 25600
#define A6_KL 32000
#define A6_VH 38400
#define ATT6_SMEM_BYTES (44800*4)

__global__ __launch_bounds__(256, 1) void attn_v8_kernel(
    const __half* __restrict__ qkh, const __half* __restrict__ qkl,
    const __half* __restrict__ vbuf,
    __half* __restrict__ atth)
{
    extern __shared__ unsigned smu[];
    const int type = blockIdx.x;
    const int bi = c_bi[type];
    const int ch = c_ch[type];
    const int h  = blockIdx.y;
    const int b  = blockIdx.z;
    const int tid = threadIdx.x;
    const int w = tid >> 5, l = tid & 31;
    const int gid = l >> 2, tig = l & 3;

    const int j0 = (ch == 1) ? bi : 0;
    const int j1 = (ch == 0) ? bi : 2 * bi + 2;

    const float scale2 = 13.856406460551018f * 1.4426950408889634f;
    const unsigned sbase = (unsigned)__cvta_generic_to_shared(smu);

    const int kcol = DM + h * DH;
    const int vcol = h * DH;

    auto issue_k = [&](int j) {
        const size_t row0 = (size_t)(b * SEQ + j * 64);
        #pragma unroll
        for (int i = 0; i < 6; i++) {
            int c = tid + (i << 8);
            int r = c / 24, cc2 = c % 24;
            unsigned doff = (unsigned)((r * A6_ST + cc2 * 4) * 4);
            size_t gk = (row0 + r) * D2 + kcol + cc2 * 8;
            CP16(sbase + A6_KH * 4 + doff, (const void*)(qkh + gk));
            CP16(sbase + A6_KL * 4 + doff, (const void*)(qkl + gk));
        }
        CP_COMMIT();
    };
    auto issue_v = [&](int j) {
        const size_t row0 = (size_t)(b * SEQ + j * 64);
        #pragma unroll
        for (int i = 0; i < 6; i++) {
            int c = tid + (i << 8);
            int r = c / 24, cc2 = c % 24;
            unsigned doff = (unsigned)((r * A6_ST + cc2 * 4) * 4);
            size_t gv = (row0 + r) * DM + vcol + cc2 * 8;
            CP16(sbase + A6_VH * 4 + doff, (const void*)(vbuf + gv));
        }
        CP_COMMIT();
    };

    {
        const size_t row0 = (size_t)(b * SEQ + bi * 128);
        const int qcol = h * DH;
        #pragma unroll
        for (int i = 0; i < 12; i++) {
            int c = tid + (i << 8);
            int r = c / 24, cc2 = c % 24;
            unsigned doff = (unsigned)((r * A6_ST + cc2 * 4) * 4);
            size_t goff = (row0 + r) * D2 + qcol + cc2 * 8;
            CP16(sbase + A6_QH * 4 + doff, (const void*)(qkh + goff));
            CP16(sbase + A6_QL * 4 + doff, (const void*)(qkl + goff));
        }
        CP_COMMIT();
    }
    issue_k(j0);
    issue_v(j0);

    float m0 = -1e30f, m1 = -1e30f, l0 = 0.f, l1 = 0.f;
    float accO[24][4];
    #pragma unroll
    for (int i = 0; i < 24; i++)
        #pragma unroll
        for (int c = 0; c < 4; c++) accO[i][c] = 0.f;

    const int lm_rwi  = (l & 7) + ((l >> 3) & 1) * 8;
    const int lm_ncol = (l >> 4) * 8;
    const unsigned vh_base = sbase + A6_VH * 4;

    const int qg0 = bi * 128 + w * 16 + gid;
    const int qg1 = qg0 + 8;

    for (int j = j0; j < j1; j++) {
        CP_WAIT1();
        __syncthreads();

        const bool diag = (j >= 2 * bi);
        const bool wskip = diag && (64 * j >= bi * 128 + w * 16 + 16);

        const unsigned* Qh = smu + A6_QH;
        const unsigned* Ql = smu + A6_QL;
        const unsigned* Kh = smu + A6_KH;
        const unsigned* Kl = smu + A6_KL;

        unsigned pha[4][4];
        float corr0 = 1.f, corr1 = 1.f;

        if (!wskip) {
            float accS[8][4];
            #pragma unroll
            for (int i = 0; i < 8; i++)
                #pragma unroll
                for (int c = 0; c < 4; c++) accS[i][c] = 0.f;

            #pragma unroll
            for (int ks = 0; ks < 12; ks++) {
                int kp = ks * 8;
                unsigned ah[4], al[4];
                int a0 = (w * 16 + gid) * A6_ST + kp + tig;
                int a1 = a0 + 8 * A6_ST;
                ah[0] = Qh[a0]; ah[1] = Qh[a1]; ah[2] = Qh[a0 + 4]; ah[3] = Qh[a1 + 4];
                al[0] = Ql[a0]; al[1] = Ql[a1]; al[2] = Ql[a0 + 4]; al[3] = Ql[a1 + 4];
                #pragma unroll
                for (int nt = 0; nt < 8; nt++) {
                    int bb = (nt * 8 + gid) * A6_ST + kp + tig;
                    unsigned bh[2], bl2[2];
                    bh[0]  = Kh[bb]; bh[1]  = Kh[bb + 4];
                    bl2[0] = Kl[bb]; bl2[1] = Kl[bb + 4];
                    mma_f16(accS[nt], ah, bh);
                    mma_f16(accS[nt], al, bh);
                    mma_f16(accS[nt], ah, bl2);
                }
            }

            float mx0 = -1e30f, mx1 = -1e30f;
            #pragma unroll
            for (int nt = 0; nt < 8; nt++) {
                int kg = j * 64 + nt * 8 + 2 * tig;
                float v0 = accS[nt][0] * scale2;
                float v1 = accS[nt][1] * scale2;
                float v2 = accS[nt][2] * scale2;
                float v3 = accS[nt][3] * scale2;
                if (diag) {
                    if (kg     > qg0) v0 = -1e30f;
                    if (kg + 1 > qg0) v1 = -1e30f;
                    if (kg     > qg1) v2 = -1e30f;
                    if (kg + 1 > qg1) v3 = -1e30f;
                }
                accS[nt][0] = v0; accS[nt][1] = v1;
                accS[nt][2] = v2; accS[nt][3] = v3;
                mx0 = fmaxf(mx0, fmaxf(v0, v1));
                mx1 = fmaxf(mx1, fmaxf(v2, v3));
            }
            mx0 = fmaxf(mx0, __shfl_xor_sync(0xffffffffu, mx0, 1));
            mx0 = fmaxf(mx0, __shfl_xor_sync(0xffffffffu, mx0, 2));
            mx1 = fmaxf(mx1, __shfl_xor_sync(0xffffffffu, mx1, 1));
            mx1 = fmaxf(mx1, __shfl_xor_sync(0xffffffffu, mx1, 2));
            float mn0 = fmaxf(m0, mx0), mn1 = fmaxf(m1, mx1);
            corr0 = exp2f(m0 - mn0); corr1 = exp2f(m1 - mn1);

            float sum0 = 0.f, sum1 = 0.f;
            #pragma unroll
            for (int nt = 0; nt < 8; nt++) {
                unsigned u01 = ex2h2(accS[nt][0] - mn0, accS[nt][1] - mn0);
                unsigned u23 = ex2h2(accS[nt][2] - mn1, accS[nt][3] - mn1);
                const int ks = nt >> 1;
                const int s0 = (nt & 1) * 2;
                pha[ks][s0]     = u01;
                pha[ks][s0 + 1] = u23;
                float2 f01 = __half22float2(*reinterpret_cast<__half2*>(&u01));
                float2 f23 = __half22float2(*reinterpret_cast<__half2*>(&u23));
                sum0 += f01.x + f01.y;
                sum1 += f23.x + f23.y;
            }
            sum0 += __shfl_xor_sync(0xffffffffu, sum0, 1);
            sum0 += __shfl_xor_sync(0xffffffffu, sum0, 2);
            sum1 += __shfl_xor_sync(0xffffffffu, sum1, 1);
            sum1 += __shfl_xor_sync(0xffffffffu, sum1, 2);
            l0 = l0 * corr0 + sum0;  m0 = mn0;
            l1 = l1 * corr1 + sum1;  m1 = mn1;
        }

        CP_WAIT0();
        __syncthreads();
        if (j + 1 < j1) issue_k(j + 1);

        if (!wskip) {
            #pragma unroll
            for (int nt = 0; nt < 24; nt++) {
                accO[nt][0] *= corr0; accO[nt][1] *= corr0;
                accO[nt][2] *= corr1; accO[nt][3] *= corr1;
            }
            #pragma unroll
            for (int ks = 0; ks < 4; ks++) {
                unsigned rowoff = (unsigned)((ks * 16 + lm_rwi) * A6_ST) * 4u;
                #pragma unroll
                for (int g = 0; g < 12; g++) {
                    unsigned coloff = (unsigned)(g * 8 + lm_ncol / 2) * 4u;
                    unsigned bh0, bh1, bh2, bh3;
                    ldsm_x4_t(bh0, bh1, bh2, bh3, vh_base + rowoff + coloff);
                    unsigned bfh[2];
                    bfh[0] = bh0; bfh[1] = bh1;
                    mma_f16(accO[2 * g],     pha[ks], bfh);
                    bfh[0] = bh2; bfh[1] = bh3;
                    mma_f16(accO[2 * g + 1], pha[ks], bfh);
                }
            }
        }

        __syncthreads();
        if (j + 1 < j1) issue_v(j + 1);
    }

    if (ch < 0) {
        float li0 = 1.0f / l0, li1 = 1.0f / l1;
        int row0 = b * SEQ + bi * 128 + w * 16 + gid;
        #pragma unroll
        for (int nt = 0; nt < 24; nt++) {
            int col = h * DH + nt * 8 + 2 * tig;
            size_t o0 = (size_t)row0 * DM + col;
            size_t o1 = (size_t)(row0 + 8) * DM + col;
            *reinterpret_cast<unsigned*>(atth + o0) = packh(accO[nt][0] * li0, accO[nt][1] * li0);
            *reinterpret_cast<unsigned*>(atth + o1) = packh(accO[nt][2] * li1, accO[nt][3] * li1);
        }
    } else {
        const int pidx = ((b * NH + h) << 2) + (bi - 4);
        float* po = g_po + ((size_t)ch * 128 + pidx) * (128 * 192);
        const int r0 = w * 16 + gid, r1 = r0 + 8;
        #pragma unroll
        for (int nt = 0; nt < 24; nt++) {
            int col = nt * 8 + 2 * tig;
            *reinterpret_cast<float2*>(po + r0 * 192 + col) = make_float2(accO[nt][0], accO[nt][1]);
            *reinterpret_cast<float2*>(po + r1 * 192 + col) = make_float2(accO[nt][2], accO[nt][3]);
        }
        if (tig == 0) {
            int mlb = (ch * 128 + pidx) * 128;
            g_pm[mlb + r0] = m0; g_pl[mlb + r0] = l0;
            g_pm[mlb + r1] = m1; g_pl[mlb + r1] = l1;
        }
    }
}

// ---------------- split-KV combine (m in log2 domain) ------------------------
__global__ __launch_bounds__(256) void attn_combine_kernel(__half* __restrict__ atth)
{
    const int pidx = blockIdx.x;
    const int b  = pidx >> 4;
    const int h  = (pidx >> 2) & 3;
    const int bi = 4 + (pidx & 3);
    const int r  = threadIdx.x >> 1;
    const int c0 = (threadIdx.x & 1) * 96;

    const float* po0 = g_po + ((size_t)0 * 128 + pidx) * (128 * 192) + r * 192 + c0;
    const float* po1 = g_po + ((size_t)1 * 128 + pidx) * (128 * 192) + r * 192 + c0;
    const int mlb0 = (0 * 128 + pidx) * 128 + r;
    const int mlb1 = (1 * 128 + pidx) * 128 + r;
    float m0 = g_pm[mlb0], l0 = g_pl[mlb0];
    float m1 = g_pm[mlb1], l1 = g_pl[mlb1];
    float m = fmaxf(m0, m1);
    float e0 = exp2f(m0 - m), e1 = exp2f(m1 - m);
    float linv = 1.0f / (e0 * l0 + e1 * l1);

    size_t go = (size_t)(b * SEQ + bi * 128 + r) * DM + h * DH + c0;
    #pragma unroll
    for (int c = 0; c < 96; c += 2) {
        float v0 = (e0 * po0[c]     + e1 * po1[c])     * linv;
        float v1 = (e0 * po0[c + 1] + e1 * po1[c + 1]) * linv;
        *reinterpret_cast<unsigned*>(atth + go + c) = packh(v0, v1);
    }
}

// ---------------- launch -----------------------------------------------
extern "C" void kernel_launch(void* const* d_in, const int* in_sizes, int n_in,
                              void* d_out, int out_size)
{
    const float* x   = (const float*)d_in[0];
    const float* W1  = (const float*)d_in[2];
    const float* b1  = (const float*)d_in[3];
    const float* W3  = (const float*)d_in[4];
    const float* b3  = (const float*)d_in[5];
    const float* W2  = (const float*)d_in[6];
    const float* b2  = (const float*)d_in[7];
    const float* W4  = (const float*)d_in[8];
    const float* b4  = (const float*)d_in[9];
    const float* g1  = (const float*)d_in[10];
    const float* be1 = (const float*)d_in[11];
    const float* g2  = (const float*)d_in[12];
    const float* be2 = (const float*)d_in[13];
    float* out = (float*)d_out;

    float *x1;
    cudaGetSymbolAddress((void**)&x1, g_x1);
    __half *qkh, *qkl, *vh, *xnh, *xnl, *atth, *xn2h, *hh;
    __half *w1h, *w1l, *w3h, *w2h, *w4h;
    cudaGetSymbolAddress((void**)&qkh,  g_qkh);  cudaGetSymbolAddress((void**)&qkl,  g_qkl);
    cudaGetSymbolAddress((void**)&vh,   g_vh);
    cudaGetSymbolAddress((void**)&xnh,  g_xnh);  cudaGetSymbolAddress((void**)&xnl,  g_xnl);
    cudaGetSymbolAddress((void**)&atth, g_atth);
    cudaGetSymbolAddress((void**)&xn2h, g_xn2h);
    cudaGetSymbolAddress((void**)&hh,   g_hh);
    cudaGetSymbolAddress((void**)&w1h,  g_w1h);  cudaGetSymbolAddress((void**)&w1l,  g_w1l);
    cudaGetSymbolAddress((void**)&w3h,  g_w3h);
    cudaGetSymbolAddress((void**)&w2h,  g_w2h);
    cudaGetSymbolAddress((void**)&w4h,  g_w4h);

    cudaFuncSetAttribute(attn_v8_kernel,
                         cudaFuncAttributeMaxDynamicSharedMemorySize, ATT6_SMEM_BYTES);
    cudaFuncSetAttribute(bgemm3f_kernel,
                         cudaFuncAttributeMaxDynamicSharedMemorySize, GEMM3_SMEM);
    cudaFuncSetAttribute(bgemm1_kernel<false,0>,
                         cudaFuncAttributeMaxDynamicSharedMemorySize, GEMM1_SMEM);
    cudaFuncSetAttribute(bgemm1_kernel<true,2>,
                         cudaFuncAttributeMaxDynamicSharedMemorySize, GEMM1_SMEM);
    cudaFuncSetAttribute(bgemm1_kernel<false,2>,
                         cudaFuncAttributeMaxDynamicSharedMemorySize, GEMM1_SMEM);

    float* pres = out + XOUT_ELEMS;
    bool has_present = ((size_t)out_size >= XOUT_ELEMS + PRES_ELEMS);
    float* presp = has_present ? pres : nullptr;

    // 0) weight prep
    wsplit_h2_kernel<<<dim3(D2/32, DM/32), 256>>>(W1, w1h, w1l, DM, D3);
    wsplit_h2_kernel<<<dim3(DM/32, DM/32), 256>>>(W1 + D2, w1h + (size_t)D2 * DM, nullptr, DM, D3);
    wsplit_h2_kernel<<<dim3(DM/32, DM/32), 256>>>(W3, w3h, nullptr, DM, DM);
    wsplit_h2_kernel<<<dim3(D4/32, DM/32), 256>>>(W2, w2h, nullptr, DM, D4);
    wsplit_h2_kernel<<<dim3(DM/32, D4/32), 256>>>(W4, w4h, nullptr, D4, DM);

    // 1) LN1 -> fp16 split
    ln_kernel<true><<<ROWS, 256>>>(x, g1, be1, xnh, xnl);

    // 2a) qk (fp16 3-pass, persistent) -> split fp16 (+ K present)
    bgemm3f_kernel<<<PERSIST_GRID, 256, GEMM3_SMEM>>>(
        xnh, xnl, w1h, w1l, b1, qkh, qkl, presp, ROWS, D2, DM);

    // 2b) v (fp16 1-pass, persistent) -> single fp16 (+ V present)
    bgemm1_kernel<false,2><<<PERSIST_GRID, 256, GEMM1_SMEM>>>(
        xnh, w1h + (size_t)D2 * DM, b1 + D2, nullptr,
        nullptr, vh, presp, ROWS, DM, DM);

    // 3) attention: split-KV main (ex2 softmax) + combine
    attn_v8_kernel<<<dim3(12, NH, BS), 256, ATT6_SMEM_BYTES>>>(qkh, qkl, vh, atth);
    attn_combine_kernel<<<128, 256>>>(atth);

    // 4) x1 = att @ W3 + b3 + x
    bgemm1_kernel<false,0><<<PERSIST_GRID, 256, GEMM1_SMEM>>>(
        atth, w3h, b3, x, x1, nullptr, nullptr, ROWS, DM, DM);

    // 5) LN2 -> fp16 single
    ln_kernel<false><<<ROWS, 256>>>(x1, g2, be2, xn2h, nullptr);

    // 6) h = gelu(xn2 @ W2 + b2) -> fp16 single
    bgemm1_kernel<true,2><<<PERSIST_GRID, 256, GEMM1_SMEM>>>(
        xn2h, w2h, b2, nullptr, nullptr, hh, nullptr, ROWS, D4, DM);

    // 7) out = h @ W4 + b4 + x1
    bgemm1_kernel<false,0><<<PERSIST_GRID, 256, GEMM1_SMEM>>>(
        hh, w4h, b4, x1, out, nullptr, nullptr, ROWS, DM, D4);
}

// round 16
// speedup vs baseline: 1.9415x; 1.0000x over previous
#include <cuda_runtime.h>
#include <cuda_bf16.h>
#include <cuda_fp16.h>
#include <math.h>

// ---------------- problem constants ----------------
#define BS   8
#define SEQ  1024
#define DM   768
#define NH   4
#define DH   192
#define ROWS (BS*SEQ)          // 8192
#define D3   (3*DM)            // 2304
#define D4   (4*DM)            // 3072
#define D2   (2*DM)            // 1536

#define XOUT_ELEMS   ((size_t)ROWS*DM)
#define PRES_ELEMS   ((size_t)BS*2*NH*SEQ*DH)

#define PERSIST_GRID 296       // 148 SMs x 2 CTA/SM

// ---------------- scratch (device globals) ---------------------------------
__device__ __align__(256) float g_x1 [ROWS*DM];

__device__ __align__(256) __half g_qkh[(size_t)ROWS*D2], g_qkl[(size_t)ROWS*D2];
__device__ __align__(256) __half g_vh [(size_t)ROWS*DM];
__device__ __align__(256) __half g_xnh [ROWS*DM],  g_xnl [ROWS*DM];
__device__ __align__(256) __half g_atth[ROWS*DM];
__device__ __align__(256) __half g_xn2h[ROWS*DM];
__device__ __align__(256) __half g_hh[(size_t)ROWS*D4];

// transposed weights: [N][K]
__device__ __align__(256) __half g_w1h[(size_t)D3*DM], g_w1l[(size_t)D2*DM];
__device__ __align__(256) __half g_w3h[(size_t)DM*DM];
__device__ __align__(256) __half g_w2h[(size_t)D4*DM];
__device__ __align__(256) __half g_w4h[(size_t)DM*D4];

// split-KV partials
__device__ __align__(256) float g_po[(size_t)2*128*128*192];
__device__ __align__(256) float g_pm[2*128*128];
__device__ __align__(256) float g_pl[2*128*128];

__device__ const int c_bi[12] = {7,6,3,5,7,2,4,6,5,1,4,0};
__device__ const int c_ch[12] = {1,1,-1,1,0,-1,1,0,0,-1,0,-1};

// ---------------- helpers ---------------------------------------------------
__device__ __forceinline__ void split2h(float x0, float x1, unsigned &hi, unsigned &lo) {
    __half h0 = __float2half_rn(x0);
    __half h1 = __float2half_rn(x1);
    __half l0 = __float2half_rn(x0 - __half2float(h0));
    __half l1 = __float2half_rn(x1 - __half2float(h1));
    hi = ((unsigned)__half_as_ushort(h1) << 16) | (unsigned)__half_as_ushort(h0);
    lo = ((unsigned)__half_as_ushort(l1) << 16) | (unsigned)__half_as_ushort(l0);
}

__device__ __forceinline__ unsigned packh(float x0, float x1) {
    __half h0 = __float2half_rn(x0);
    __half h1 = __float2half_rn(x1);
    return ((unsigned)__half_as_ushort(h1) << 16) | (unsigned)__half_as_ushort(h0);
}

__device__ __forceinline__ unsigned ex2h2(float x0, float x1) {
    unsigned hin = packh(x0, x1);
    unsigned r;
    asm("ex2.approx.f16x2 %0, %1;" : "=r"(r) : "r"(hin));
    return r;
}

__device__ __forceinline__ void mma_f16(float c[4], const unsigned a[4], const unsigned b[2]) {
    asm volatile(
        "mma.sync.aligned.m16n8k16.row.col.f32.f16.f16.f32 "
        "{%0,%1,%2,%3}, {%4,%5,%6,%7}, {%8,%9}, {%0,%1,%2,%3};\n"
        : "+f"(c[0]), "+f"(c[1]), "+f"(c[2]), "+f"(c[3])
        : "r"(a[0]), "r"(a[1]), "r"(a[2]), "r"(a[3]), "r"(b[0]), "r"(b[1]));
}

__device__ __forceinline__ void ldsm_x4(unsigned r[4], unsigned addr) {
    asm volatile("ldmatrix.sync.aligned.m8n8.x4.shared.b16 {%0,%1,%2,%3}, [%4];"
        : "=r"(r[0]), "=r"(r[1]), "=r"(r[2]), "=r"(r[3]) : "r"(addr));
}

__device__ __forceinline__ void ldsm_x4_t(unsigned &r0, unsigned &r1, unsigned &r2, unsigned &r3, unsigned saddr) {
    asm volatile("ldmatrix.sync.aligned.m8n8.x4.trans.shared.b16 {%0,%1,%2,%3}, [%4];"
        : "=r"(r0), "=r"(r1), "=r"(r2), "=r"(r3) : "r"(saddr));
}

#define CP16(dst, src) asm volatile("cp.async.cg.shared.global [%0], [%1], 16;\n" :: "r"(dst), "l"(src))
#define CP_COMMIT() asm volatile("cp.async.commit_group;\n" ::)
#define CP_WAIT0()  asm volatile("cp.async.wait_group 0;\n" ::)
#define CP_WAIT1()  asm volatile("cp.async.wait_group 1;\n" ::)
#define CP_WAIT2()  asm volatile("cp.async.wait_group 2;\n" ::)

__device__ __forceinline__ float gelu_tanh_f(float x) {
    float x3 = x * x * x;
    float t  = tanhf(0.7978845608028654f * (x + 0.044715f * x3));
    return 0.5f * x * (1.0f + t);
}

// ---------------- fused prep: all weight transposes + LN1 in one launch -----
// jobs by blockIdx.x range:
//   [0,1152)      W1 QK split  (48 ntiles x 24 ktiles)
//   [1152,1728)   W1 V single  (24 x 24)
//   [1728,2304)   W3 single    (24 x 24)
//   [2304,4608)   W2 single    (96 x 24)
//   [4608,6912)   W4 single    (24 x 96)
//   [6912,15104)  LN1 rows (8192)
#define PREP_GRID 15104

__device__ __forceinline__ void wsplit_body(
    const float* __restrict__ W, __half* __restrict__ Th, __half* __restrict__ Tl,
    int K, int Nsrc, int idx, int nb, float t[32][33])
{
    int n0 = (idx % nb) * 32, k0 = (idx / nb) * 32;
    int tx = threadIdx.x & 31, ty = threadIdx.x >> 5;
    #pragma unroll
    for (int j = 0; j < 4; j++)
        t[ty + 8 * j][tx] = W[(size_t)(k0 + ty + 8 * j) * Nsrc + n0 + tx];
    __syncthreads();
    #pragma unroll
    for (int j = 0; j < 4; j++) {
        float v = t[tx][ty + 8 * j];
        __half hi = __float2half_rn(v);
        size_t o = (size_t)(n0 + ty + 8 * j) * K + k0 + tx;
        Th[o] = hi;
        if (Tl) Tl[o] = __float2half_rn(v - __half2float(hi));
    }
}

__global__ __launch_bounds__(256) void prep_kernel(
    const float* __restrict__ W1, const float* __restrict__ W3,
    const float* __restrict__ W2, const float* __restrict__ W4,
    const float* __restrict__ x, const float* __restrict__ gamma,
    const float* __restrict__ beta)
{
    __shared__ float t[32][33];
    __shared__ float ss[8], ssq[8];
    __shared__ float mu_s, rs_s;
    const int bid = blockIdx.x;
    const int tid = threadIdx.x;

    if (bid < 1152) {
        wsplit_body(W1, g_w1h, g_w1l, DM, D3, bid, 48, t);
    } else if (bid < 1728) {
        wsplit_body(W1 + D2, g_w1h + (size_t)D2 * DM, nullptr, DM, D3, bid - 1152, 24, t);
    } else if (bid < 2304) {
        wsplit_body(W3, g_w3h, nullptr, DM, DM, bid - 1728, 24, t);
    } else if (bid < 4608) {
        wsplit_body(W2, g_w2h, nullptr, DM, D4, bid - 2304, 96, t);
    } else if (bid < 6912) {
        wsplit_body(W4, g_w4h, nullptr, D4, DM, bid - 4608, 24, t);
    } else {
        // LN1 -> fp16 split
        const int row = bid - 6912;
        const float* xr = x + (size_t)row * DM;
        float v0 = xr[tid], v1 = xr[tid + 256], v2 = xr[tid + 512];
        float s  = v0 + v1 + v2;
        float sq = v0*v0 + v1*v1 + v2*v2;
        #pragma unroll
        for (int o = 16; o > 0; o >>= 1) {
            s  += __shfl_xor_sync(0xffffffffu, s,  o);
            sq += __shfl_xor_sync(0xffffffffu, sq, o);
        }
        int w = tid >> 5, l = tid & 31;
        if (l == 0) { ss[w] = s; ssq[w] = sq; }
        __syncthreads();
        if (tid == 0) {
            float S = 0.f, SQ = 0.f;
            #pragma unroll
            for (int i = 0; i < 8; i++) { S += ss[i]; SQ += ssq[i]; }
            float mu = S * (1.0f / DM);
            float var = SQ * (1.0f / DM) - mu * mu;
            mu_s = mu;
            rs_s = rsqrtf(var + 1e-3f);
        }
        __syncthreads();
        float mu = mu_s, rs = rs_s;
        size_t ro = (size_t)row * DM;
        #pragma unroll
        for (int q = 0; q < 3; q++) {
            int c = tid + q * 256;
            float v = (q == 0 ? v0 : (q == 1 ? v1 : v2));
            float y = (v - mu) * rs * gamma[c] + beta[c];
            __half hi = __float2half_rn(y);
            g_xnh[ro + c] = hi;
            g_xnl[ro + c] = __float2half_rn(y - __half2float(hi));
        }
    }
}

// ---------------- LayerNorm -> fp16 single (LN2) -----------------------------
__global__ __launch_bounds__(256) void ln2_kernel(
    const float* __restrict__ x, const float* __restrict__ gamma,
    const float* __restrict__ beta, __half* __restrict__ oh)
{
    int row = blockIdx.x;
    int tid = threadIdx.x;
    const float* xr = x + (size_t)row * DM;
    float v0 = xr[tid], v1 = xr[tid + 256], v2 = xr[tid + 512];
    float s  = v0 + v1 + v2;
    float sq = v0*v0 + v1*v1 + v2*v2;
    #pragma unroll
    for (int o = 16; o > 0; o >>= 1) {
        s  += __shfl_xor_sync(0xffffffffu, s,  o);
        sq += __shfl_xor_sync(0xffffffffu, sq, o);
    }
    __shared__ float ss[8], ssq[8];
    __shared__ float mu_s, rs_s;
    int w = tid >> 5, l = tid & 31;
    if (l == 0) { ss[w] = s; ssq[w] = sq; }
    __syncthreads();
    if (tid == 0) {
        float S = 0.f, SQ = 0.f;
        #pragma unroll
        for (int i = 0; i < 8; i++) { S += ss[i]; SQ += ssq[i]; }
        float mu = S * (1.0f / DM);
        float var = SQ * (1.0f / DM) - mu * mu;
        mu_s = mu;
        rs_s = rsqrtf(var + 1e-3f);
    }
    __syncthreads();
    float mu = mu_s, rs = rs_s;
    size_t ro = (size_t)row * DM;
    #pragma unroll
    for (int q = 0; q < 3; q++) {
        int c = tid + q * 256;
        float v = (q == 0 ? v0 : (q == 1 ? v1 : v2));
        float y = (v - mu) * rs * gamma[c] + beta[c];
        oh[ro + c] = __float2half_rn(y);
    }
}

// ---------------- GEMM f3: fp16 3-pass (A split, B split), persistent -------
#define SROW3 80
#define MAT3  (128*SROW3)
#define STG3  (4*MAT3)
#define GEMM3_SMEM (2*STG3)

__global__ __launch_bounds__(256, 2) void bgemm3f_kernel(
    const __half* __restrict__ Ah, const __half* __restrict__ Al,
    const __half* __restrict__ Bh, const __half* __restrict__ Bl,
    const float* __restrict__ bias,
    __half* __restrict__ Ch, __half* __restrict__ Cl,
    float* __restrict__ pres, int M, int N, int K)
{
    extern __shared__ unsigned char sm3[];
    const int tid = threadIdx.x;
    const int w = tid >> 5, l = tid & 31;
    const int wm = w & 1, wn = w >> 1;
    const int gid = l >> 2, tig = l & 3;
    const int T = K >> 5;
    const int nbx = N >> 7;
    const int ntile = (M >> 7) * nbx;

    const unsigned smem_base = (unsigned)__cvta_generic_to_shared(sm3);
    const int rl = l & 7, sel = l >> 3;
    const unsigned a_off = (unsigned)((rl + 8 * (sel & 1)) * SROW3 + 16 * (sel >> 1));
    const unsigned b_off = (unsigned)((rl + 8 * (sel >> 1)) * SROW3 + 16 * (sel & 1));

    for (int tile = blockIdx.x; tile < ntile; tile += gridDim.x) {
        const int by = tile / nbx, bx = tile % nbx;
        const __half* A0 = Ah + (size_t)(by * 128) * K;
        const __half* A1 = Al + (size_t)(by * 128) * K;
        const __half* B0 = Bh + (size_t)(bx * 128) * K;
        const __half* B1 = Bl + (size_t)(bx * 128) * K;

        float acc[4][4][4];
        #pragma unroll
        for (int i = 0; i < 4; i++)
            #pragma unroll
            for (int j = 0; j < 4; j++)
                #pragma unroll
                for (int c = 0; c < 4; c++) acc[i][j][c] = 0.f;

        auto issue = [&](int t) {
            unsigned sb = smem_base + (t & 1) * STG3;
            int k0 = t << 5;
            #pragma unroll
            for (int i = 0; i < 2; i++) {
                int chunk = tid + (i << 8);
                int r = chunk >> 2, c = chunk & 3;
                unsigned doff = (unsigned)(r * SROW3 + c * 16);
                size_t goff = (size_t)r * K + k0 + c * 8;
                CP16(sb + doff,            (const void*)(A0 + goff));
                CP16(sb + MAT3 + doff,     (const void*)(A1 + goff));
                CP16(sb + 2 * MAT3 + doff, (const void*)(B0 + goff));
                CP16(sb + 3 * MAT3 + doff, (const void*)(B1 + goff));
            }
            CP_COMMIT();
        };

        __syncthreads();
        issue(0);
        issue(1);

        for (int t = 0; t < T; t++) {
            if (t + 1 < T) CP_WAIT1(); else CP_WAIT0();
            __syncthreads();

            unsigned sb = smem_base + (t & 1) * STG3;
            #pragma unroll
            for (int ks = 0; ks < 2; ks++) {
                unsigned bh[2][4], bl4[2][4];
                #pragma unroll
                for (int p = 0; p < 2; p++) {
                    unsigned bd = sb + 2 * MAT3 + (unsigned)((wn * 32 + p * 16) * SROW3 + ks * 32) + b_off;
                    ldsm_x4(bh[p], bd);
                    ldsm_x4(bl4[p], bd + MAT3);
                }
                #pragma unroll
                for (int am = 0; am < 4; am++) {
                    unsigned ah[4], al4[4];
                    unsigned ad = sb + (unsigned)((wm * 64 + am * 16) * SROW3 + ks * 32) + a_off;
                    ldsm_x4(ah, ad);
                    ldsm_x4(al4, ad + MAT3);
                    #pragma unroll
                    for (int an = 0; an < 4; an++) {
                        const int p = an >> 1, q = (an & 1) * 2;
                        unsigned bfh[2] = { bh[p][q], bh[p][q + 1] };
                        unsigned bfl[2] = { bl4[p][q], bl4[p][q + 1] };
                        mma_f16(acc[am][an], ah, bfh);
                        mma_f16(acc[am][an], al4, bfh);
                        mma_f16(acc[am][an], ah, bfl);
                    }
                }
            }
            __syncthreads();
            if (t + 2 < T) issue(t + 2);
        }

        #pragma unroll
        for (int am = 0; am < 4; am++) {
            int r0 = by * 128 + wm * 64 + am * 16 + gid;
            int r1 = r0 + 8;
            #pragma unroll
            for (int an = 0; an < 4; an++) {
                int n0 = bx * 128 + wn * 32 + an * 8 + 2 * tig;
                float bv0 = bias[n0], bv1 = bias[n0 + 1];
                size_t o0 = (size_t)r0 * N + n0;
                size_t o1 = (size_t)r1 * N + n0;
                float v0 = acc[am][an][0] + bv0;
                float v1 = acc[am][an][1] + bv1;
                float v2 = acc[am][an][2] + bv0;
                float v3 = acc[am][an][3] + bv1;
                unsigned hw, lw;
                split2h(v0, v1, hw, lw);
                *reinterpret_cast<unsigned*>(Ch + o0) = hw;
                *reinterpret_cast<unsigned*>(Cl + o0) = lw;
                split2h(v2, v3, hw, lw);
                *reinterpret_cast<unsigned*>(Ch + o1) = hw;
                *reinterpret_cast<unsigned*>(Cl + o1) = lw;
                if (pres && n0 >= DM) {
                    int local = n0 - DM;
                    int hh = local / DH, dd = local % DH;
                    int b0 = r0 >> 10, s0 = r0 & 1023;
                    int b1 = r1 >> 10, s1 = r1 & 1023;
                    size_t p0 = (((size_t)(b0 * 2) * NH + hh) * SEQ + s0) * DH + dd;
                    size_t p1 = (((size_t)(b1 * 2) * NH + hh) * SEQ + s1) * DH + dd;
                    *reinterpret_cast<float2*>(pres + p0) = make_float2(v0, v1);
                    *reinterpret_cast<float2*>(pres + p1) = make_float2(v2, v3);
                }
            }
        }
    }
}

// ---------------- GEMM v1: fp16 1-pass, persistent, 3-stage -----------------
#define STG1  (2*MAT3)
#define GEMM1_SMEM (3*STG1)

template<bool GELU, int OMODE>   // 0 = float out (+res), 2 = fp16 out (+V-present)
__global__ __launch_bounds__(256, 2) void bgemm1_kernel(
    const __half* __restrict__ Ah, const __half* __restrict__ Bh,
    const float* __restrict__ bias, const float* __restrict__ res,
    float* __restrict__ C, __half* __restrict__ Ch,
    float* __restrict__ pres, int M, int N, int K)
{
    extern __shared__ unsigned char sm1[];
    const int tid = threadIdx.x;
    const int w = tid >> 5, l = tid & 31;
    const int wm = w & 1, wn = w >> 1;
    const int gid = l >> 2, tig = l & 3;
    const int T = K >> 5;
    const int nbx = N >> 7;
    const int ntile = (M >> 7) * nbx;

    const unsigned smem_base = (unsigned)__cvta_generic_to_shared(sm1);
    const int rl = l & 7, sel = l >> 3;
    const unsigned a_off = (unsigned)((rl + 8 * (sel & 1)) * SROW3 + 16 * (sel >> 1));
    const unsigned b_off = (unsigned)((rl + 8 * (sel >> 1)) * SROW3 + 16 * (sel & 1));

    for (int tile = blockIdx.x; tile < ntile; tile += gridDim.x) {
        const int by = tile / nbx, bx = tile % nbx;
        const __half* A0 = Ah + (size_t)(by * 128) * K;
        const __half* B0 = Bh + (size_t)(bx * 128) * K;

        float acc[4][4][4];
        #pragma unroll
        for (int i = 0; i < 4; i++)
            #pragma unroll
            for (int j = 0; j < 4; j++)
                #pragma unroll
                for (int c = 0; c < 4; c++) acc[i][j][c] = 0.f;

        auto issue = [&](int t) {
            int buf = t % 3;
            unsigned sb = smem_base + buf * STG1;
            int k0 = t << 5;
            #pragma unroll
            for (int i = 0; i < 2; i++) {
                int chunk = tid + (i << 8);
                int r = chunk >> 2, c = chunk & 3;
                unsigned doff = (unsigned)(r * SROW3 + c * 16);
                size_t goff = (size_t)r * K + k0 + c * 8;
                CP16(sb + doff,        (const void*)(A0 + goff));
                CP16(sb + MAT3 + doff, (const void*)(B0 + goff));
            }
            CP_COMMIT();
        };

        __syncthreads();           // protect smem reuse across tiles
        issue(0);
        issue(1);
        issue(2);

        for (int t = 0; t < T; t++) {
            if (t + 2 < T)      CP_WAIT2();
            else if (t + 1 < T) CP_WAIT1();
            else                CP_WAIT0();
            __syncthreads();

            unsigned sb = smem_base + (t % 3) * STG1;
            #pragma unroll
            for (int ks = 0; ks < 2; ks++) {
                unsigned bh[2][4];
                #pragma unroll
                for (int p = 0; p < 2; p++) {
                    unsigned bd = sb + MAT3 + (unsigned)((wn * 32 + p * 16) * SROW3 + ks * 32) + b_off;
                    ldsm_x4(bh[p], bd);
                }
                #pragma unroll
                for (int am = 0; am < 4; am++) {
                    unsigned ah[4];
                    unsigned ad = sb + (unsigned)((wm * 64 + am * 16) * SROW3 + ks * 32) + a_off;
                    ldsm_x4(ah, ad);
                    #pragma unroll
                    for (int an = 0; an < 4; an++) {
                        const int p = an >> 1, q = (an & 1) * 2;
                        unsigned bfh[2] = { bh[p][q], bh[p][q + 1] };
                        mma_f16(acc[am][an], ah, bfh);
                    }
                }
            }
            __syncthreads();
            if (t + 3 < T) issue(t + 3);
        }

        #pragma unroll
        for (int am = 0; am < 4; am++) {
            int r0 = by * 128 + wm * 64 + am * 16 + gid;
            int r1 = r0 + 8;
            #pragma unroll
            for (int an = 0; an < 4; an++) {
                int n0 = bx * 128 + wn * 32 + an * 8 + 2 * tig;
                float bv0 = bias[n0], bv1 = bias[n0 + 1];
                size_t o0 = (size_t)r0 * N + n0;
                size_t o1 = (size_t)r1 * N + n0;
                float v0 = acc[am][an][0] + bv0;
                float v1 = acc[am][an][1] + bv1;
                float v2 = acc[am][an][2] + bv0;
                float v3 = acc[am][an][3] + bv1;
                if (res) {
                    v0 += res[o0]; v1 += res[o0 + 1];
                    v2 += res[o1]; v3 += res[o1 + 1];
                }
                if (GELU) {
                    v0 = gelu_tanh_f(v0); v1 = gelu_tanh_f(v1);
                    v2 = gelu_tanh_f(v2); v3 = gelu_tanh_f(v3);
                }
                if (OMODE == 0) {
                    *reinterpret_cast<float2*>(C + o0) = make_float2(v0, v1);
                    *reinterpret_cast<float2*>(C + o1) = make_float2(v2, v3);
                } else {
                    *reinterpret_cast<unsigned*>(Ch + o0) = packh(v0, v1);
                    *reinterpret_cast<unsigned*>(Ch + o1) = packh(v2, v3);
                    if (pres) {
                        int hh = n0 / DH, dd = n0 % DH;
                        int b0 = r0 >> 10, s0 = r0 & 1023;
                        int b1 = r1 >> 10, s1 = r1 & 1023;
                        size_t p0 = (((size_t)(b0 * 2 + 1) * NH + hh) * SEQ + s0) * DH + dd;
                        size_t p1 = (((size_t)(b1 * 2 + 1) * NH + hh) * SEQ + s1) * DH + dd;
                        *reinterpret_cast<float2*>(pres + p0) = make_float2(v0, v1);
                        *reinterpret_cast<float2*>(pres + p1) = make_float2(v2, v3);
                    }
                }
            }
        }
    }
}

// ---------------- attention v8: fp16, split-KV, ex2.f16x2 softmax -----------
#define A6_ST 100
#define A6_QH 0
#define A6_QL 12800
#define A6_KH 25600
#define A6_KL 32000
#define A6_VH 38400
#define ATT6_SMEM_BYTES (44800*4)

__global__ __launch_bounds__(256, 1) void attn_v8_kernel(
    const __half* __restrict__ qkh, const __half* __restrict__ qkl,
    const __half* __restrict__ vbuf,
    __half* __restrict__ atth)
{
    extern __shared__ unsigned smu[];
    const int type = blockIdx.x;
    const int bi = c_bi[type];
    const int ch = c_ch[type];
    const int h  = blockIdx.y;
    const int b  = blockIdx.z;
    const int tid = threadIdx.x;
    const int w = tid >> 5, l = tid & 31;
    const int gid = l >> 2, tig = l & 3;

    const int j0 = (ch == 1) ? bi : 0;
    const int j1 = (ch == 0) ? bi : 2 * bi + 2;

    const float scale2 = 13.856406460551018f * 1.4426950408889634f;
    const unsigned sbase = (unsigned)__cvta_generic_to_shared(smu);

    const int kcol = DM + h * DH;
    const int vcol = h * DH;

    auto issue_k = [&](int j) {
        const size_t row0 = (size_t)(b * SEQ + j * 64);
        #pragma unroll
        for (int i = 0; i < 6; i++) {
            int c = tid + (i << 8);
            int r = c / 24, cc2 = c % 24;
            unsigned doff = (unsigned)((r * A6_ST + cc2 * 4) * 4);
            size_t gk = (row0 + r) * D2 + kcol + cc2 * 8;
            CP16(sbase + A6_KH * 4 + doff, (const void*)(qkh + gk));
            CP16(sbase + A6_KL * 4 + doff, (const void*)(qkl + gk));
        }
        CP_COMMIT();
    };
    auto issue_v = [&](int j) {
        const size_t row0 = (size_t)(b * SEQ + j * 64);
        #pragma unroll
        for (int i = 0; i < 6; i++) {
            int c = tid + (i << 8);
            int r = c / 24, cc2 = c % 24;
            unsigned doff = (unsigned)((r * A6_ST + cc2 * 4) * 4);
            size_t gv = (row0 + r) * DM + vcol + cc2 * 8;
            CP16(sbase + A6_VH * 4 + doff, (const void*)(vbuf + gv));
        }
        CP_COMMIT();
    };

    {
        const size_t row0 = (size_t)(b * SEQ + bi * 128);
        const int qcol = h * DH;
        #pragma unroll
        for (int i = 0; i < 12; i++) {
            int c = tid + (i << 8);
            int r = c / 24, cc2 = c % 24;
            unsigned doff = (unsigned)((r * A6_ST + cc2 * 4) * 4);
            size_t goff = (row0 + r) * D2 + qcol + cc2 * 8;
            CP16(sbase + A6_QH * 4 + doff, (const void*)(qkh + goff));
            CP16(sbase + A6_QL * 4 + doff, (const void*)(qkl + goff));
        }
        CP_COMMIT();
    }
    issue_k(j0);
    issue_v(j0);

    float m0 = -1e30f, m1 = -1e30f, l0 = 0.f, l1 = 0.f;
    float accO[24][4];
    #pragma unroll
    for (int i = 0; i < 24; i++)
        #pragma unroll
        for (int c = 0; c < 4; c++) accO[i][c] = 0.f;

    const int lm_rwi  = (l & 7) + ((l >> 3) & 1) * 8;
    const int lm_ncol = (l >> 4) * 8;
    const unsigned vh_base = sbase + A6_VH * 4;

    const int qg0 = bi * 128 + w * 16 + gid;
    const int qg1 = qg0 + 8;

    for (int j = j0; j < j1; j++) {
        CP_WAIT1();
        __syncthreads();

        const bool diag = (j >= 2 * bi);
        const bool wskip = diag && (64 * j >= bi * 128 + w * 16 + 16);

        const unsigned* Qh = smu + A6_QH;
        const unsigned* Ql = smu + A6_QL;
        const unsigned* Kh = smu + A6_KH;
        const unsigned* Kl = smu + A6_KL;

        unsigned pha[4][4];
        float corr0 = 1.f, corr1 = 1.f;

        if (!wskip) {
            float accS[8][4];
            #pragma unroll
            for (int i = 0; i < 8; i++)
                #pragma unroll
                for (int c = 0; c < 4; c++) accS[i][c] = 0.f;

            #pragma unroll
            for (int ks = 0; ks < 12; ks++) {
                int kp = ks * 8;
                unsigned ah[4], al[4];
                int a0 = (w * 16 + gid) * A6_ST + kp + tig;
                int a1 = a0 + 8 * A6_ST;
                ah[0] = Qh[a0]; ah[1] = Qh[a1]; ah[2] = Qh[a0 + 4]; ah[3] = Qh[a1 + 4];
                al[0] = Ql[a0]; al[1] = Ql[a1]; al[2] = Ql[a0 + 4]; al[3] = Ql[a1 + 4];
                #pragma unroll
                for (int nt = 0; nt < 8; nt++) {
                    int bb = (nt * 8 + gid) * A6_ST + kp + tig;
                    unsigned bh[2], bl2[2];
                    bh[0]  = Kh[bb]; bh[1]  = Kh[bb + 4];
                    bl2[0] = Kl[bb]; bl2[1] = Kl[bb + 4];
                    mma_f16(accS[nt], ah, bh);
                    mma_f16(accS[nt], al, bh);
                    mma_f16(accS[nt], ah, bl2);
                }
            }

            float mx0 = -1e30f, mx1 = -1e30f;
            #pragma unroll
            for (int nt = 0; nt < 8; nt++) {
                int kg = j * 64 + nt * 8 + 2 * tig;
                float v0 = accS[nt][0] * scale2;
                float v1 = accS[nt][1] * scale2;
                float v2 = accS[nt][2] * scale2;
                float v3 = accS[nt][3] * scale2;
                if (diag) {
                    if (kg     > qg0) v0 = -1e30f;
                    if (kg + 1 > qg0) v1 = -1e30f;
                    if (kg     > qg1) v2 = -1e30f;
                    if (kg + 1 > qg1) v3 = -1e30f;
                }
                accS[nt][0] = v0; accS[nt][1] = v1;
                accS[nt][2] = v2; accS[nt][3] = v3;
                mx0 = fmaxf(mx0, fmaxf(v0, v1));
                mx1 = fmaxf(mx1, fmaxf(v2, v3));
            }
            mx0 = fmaxf(mx0, __shfl_xor_sync(0xffffffffu, mx0, 1));
            mx0 = fmaxf(mx0, __shfl_xor_sync(0xffffffffu, mx0, 2));
            mx1 = fmaxf(mx1, __shfl_xor_sync(0xffffffffu, mx1, 1));
            mx1 = fmaxf(mx1, __shfl_xor_sync(0xffffffffu, mx1, 2));
            float mn0 = fmaxf(m0, mx0), mn1 = fmaxf(m1, mx1);
            corr0 = exp2f(m0 - mn0); corr1 = exp2f(m1 - mn1);

            float sum0 = 0.f, sum1 = 0.f;
            #pragma unroll
            for (int nt = 0; nt < 8; nt++) {
                unsigned u01 = ex2h2(accS[nt][0] - mn0, accS[nt][1] - mn0);
                unsigned u23 = ex2h2(accS[nt][2] - mn1, accS[nt][3] - mn1);
                const int ks = nt >> 1;
                const int s0 = (nt & 1) * 2;
                pha[ks][s0]     = u01;
                pha[ks][s0 + 1] = u23;
                float2 f01 = __half22float2(*reinterpret_cast<__half2*>(&u01));
                float2 f23 = __half22float2(*reinterpret_cast<__half2*>(&u23));
                sum0 += f01.x + f01.y;
                sum1 += f23.x + f23.y;
            }
            sum0 += __shfl_xor_sync(0xffffffffu, sum0, 1);
            sum0 += __shfl_xor_sync(0xffffffffu, sum0, 2);
            sum1 += __shfl_xor_sync(0xffffffffu, sum1, 1);
            sum1 += __shfl_xor_sync(0xffffffffu, sum1, 2);
            l0 = l0 * corr0 + sum0;  m0 = mn0;
            l1 = l1 * corr1 + sum1;  m1 = mn1;
        }

        CP_WAIT0();
        __syncthreads();
        if (j + 1 < j1) issue_k(j + 1);

        if (!wskip) {
            #pragma unroll
            for (int nt = 0; nt < 24; nt++) {
                accO[nt][0] *= corr0; accO[nt][1] *= corr0;
                accO[nt][2] *= corr1; accO[nt][3] *= corr1;
            }
            #pragma unroll
            for (int ks = 0; ks < 4; ks++) {
                unsigned rowoff = (unsigned)((ks * 16 + lm_rwi) * A6_ST) * 4u;
                #pragma unroll
                for (int g = 0; g < 12; g++) {
                    unsigned coloff = (unsigned)(g * 8 + lm_ncol / 2) * 4u;
                    unsigned bh0, bh1, bh2, bh3;
                    ldsm_x4_t(bh0, bh1, bh2, bh3, vh_base + rowoff + coloff);
                    unsigned bfh[2];
                    bfh[0] = bh0; bfh[1] = bh1;
                    mma_f16(accO[2 * g],     pha[ks], bfh);
                    bfh[0] = bh2; bfh[1] = bh3;
                    mma_f16(accO[2 * g + 1], pha[ks], bfh);
                }
            }
        }

        __syncthreads();
        if (j + 1 < j1) issue_v(j + 1);
    }

    if (ch < 0) {
        float li0 = 1.0f / l0, li1 = 1.0f / l1;
        int row0 = b * SEQ + bi * 128 + w * 16 + gid;
        #pragma unroll
        for (int nt = 0; nt < 24; nt++) {
            int col = h * DH + nt * 8 + 2 * tig;
            size_t o0 = (size_t)row0 * DM + col;
            size_t o1 = (size_t)(row0 + 8) * DM + col;
            *reinterpret_cast<unsigned*>(atth + o0) = packh(accO[nt][0] * li0, accO[nt][1] * li0);
            *reinterpret_cast<unsigned*>(atth + o1) = packh(accO[nt][2] * li1, accO[nt][3] * li1);
        }
    } else {
        const int pidx = ((b * NH + h) << 2) + (bi - 4);
        float* po = g_po + ((size_t)ch * 128 + pidx) * (128 * 192);
        const int r0 = w * 16 + gid, r1 = r0 + 8;
        #pragma unroll
        for (int nt = 0; nt < 24; nt++) {
            int col = nt * 8 + 2 * tig;
            *reinterpret_cast<float2*>(po + r0 * 192 + col) = make_float2(accO[nt][0], accO[nt][1]);
            *reinterpret_cast<float2*>(po + r1 * 192 + col) = make_float2(accO[nt][2], accO[nt][3]);
        }
        if (tig == 0) {
            int mlb = (ch * 128 + pidx) * 128;
            g_pm[mlb + r0] = m0; g_pl[mlb + r0] = l0;
            g_pm[mlb + r1] = m1; g_pl[mlb + r1] = l1;
        }
    }
}

// ---------------- split-KV combine (m in log2 domain) ------------------------
__global__ __launch_bounds__(256) void attn_combine_kernel(__half* __restrict__ atth)
{
    const int pidx = blockIdx.x;
    const int b  = pidx >> 4;
    const int h  = (pidx >> 2) & 3;
    const int bi = 4 + (pidx & 3);
    const int r  = threadIdx.x >> 1;
    const int c0 = (threadIdx.x & 1) * 96;

    const float* po0 = g_po + ((size_t)0 * 128 + pidx) * (128 * 192) + r * 192 + c0;
    const float* po1 = g_po + ((size_t)1 * 128 + pidx) * (128 * 192) + r * 192 + c0;
    const int mlb0 = (0 * 128 + pidx) * 128 + r;
    const int mlb1 = (1 * 128 + pidx) * 128 + r;
    float m0 = g_pm[mlb0], l0 = g_pl[mlb0];
    float m1 = g_pm[mlb1], l1 = g_pl[mlb1];
    float m = fmaxf(m0, m1);
    float e0 = exp2f(m0 - m), e1 = exp2f(m1 - m);
    float linv = 1.0f / (e0 * l0 + e1 * l1);

    size_t go = (size_t)(b * SEQ + bi * 128 + r) * DM + h * DH + c0;
    #pragma unroll
    for (int c = 0; c < 96; c += 2) {
        float v0 = (e0 * po0[c]     + e1 * po1[c])     * linv;
        float v1 = (e0 * po0[c + 1] + e1 * po1[c + 1]) * linv;
        *reinterpret_cast<unsigned*>(atth + go + c) = packh(v0, v1);
    }
}

// ---------------- launch -----------------------------------------------
extern "C" void kernel_launch(void* const* d_in, const int* in_sizes, int n_in,
                              void* d_out, int out_size)
{
    const float* x   = (const float*)d_in[0];
    const float* W1  = (const float*)d_in[2];
    const float* b1  = (const float*)d_in[3];
    const float* W3  = (const float*)d_in[4];
    const float* b3  = (const float*)d_in[5];
    const float* W2  = (const float*)d_in[6];
    const float* b2  = (const float*)d_in[7];
    const float* W4  = (const float*)d_in[8];
    const float* b4  = (const float*)d_in[9];
    const float* g1  = (const float*)d_in[10];
    const float* be1 = (const float*)d_in[11];
    const float* g2  = (const float*)d_in[12];
    const float* be2 = (const float*)d_in[13];
    float* out = (float*)d_out;

    float *x1;
    cudaGetSymbolAddress((void**)&x1, g_x1);
    __half *qkh, *qkl, *vh, *xnh, *xnl, *atth, *xn2h, *hh;
    __half *w1h, *w1l, *w3h, *w2h, *w4h;
    cudaGetSymbolAddress((void**)&qkh,  g_qkh);  cudaGetSymbolAddress((void**)&qkl,  g_qkl);
    cudaGetSymbolAddress((void**)&vh,   g_vh);
    cudaGetSymbolAddress((void**)&xnh,  g_xnh);  cudaGetSymbolAddress((void**)&xnl,  g_xnl);
    cudaGetSymbolAddress((void**)&atth, g_atth);
    cudaGetSymbolAddress((void**)&xn2h, g_xn2h);
    cudaGetSymbolAddress((void**)&hh,   g_hh);
    cudaGetSymbolAddress((void**)&w1h,  g_w1h);  cudaGetSymbolAddress((void**)&w1l,  g_w1l);
    cudaGetSymbolAddress((void**)&w3h,  g_w3h);
    cudaGetSymbolAddress((void**)&w2h,  g_w2h);
    cudaGetSymbolAddress((void**)&w4h,  g_w4h);

    cudaFuncSetAttribute(attn_v8_kernel,
                         cudaFuncAttributeMaxDynamicSharedMemorySize, ATT6_SMEM_BYTES);
    cudaFuncSetAttribute(bgemm3f_kernel,
                         cudaFuncAttributeMaxDynamicSharedMemorySize, GEMM3_SMEM);
    cudaFuncSetAttribute(bgemm1_kernel<false,0>,
                         cudaFuncAttributeMaxDynamicSharedMemorySize, GEMM1_SMEM);
    cudaFuncSetAttribute(bgemm1_kernel<true,2>,
                         cudaFuncAttributeMaxDynamicSharedMemorySize, GEMM1_SMEM);
    cudaFuncSetAttribute(bgemm1_kernel<false,2>,
                         cudaFuncAttributeMaxDynamicSharedMemorySize, GEMM1_SMEM);

    float* pres = out + XOUT_ELEMS;
    bool has_present = ((size_t)out_size >= XOUT_ELEMS + PRES_ELEMS);
    float* presp = has_present ? pres : nullptr;

    // 0+1) fused prep: all weight transposes + LN1 in one launch
    prep_kernel<<<PREP_GRID, 256>>>(W1, W3, W2, W4, x, g1, be1);

    // 2a) qk (fp16 3-pass, persistent) -> split fp16 (+ K present)
    bgemm3f_kernel<<<PERSIST_GRID, 256, GEMM3_SMEM>>>(
        xnh, xnl, w1h, w1l, b1, qkh, qkl, presp, ROWS, D2, DM);

    // 2b) v (fp16 1-pass, persistent) -> single fp16 (+ V present)
    bgemm1_kernel<false,2><<<PERSIST_GRID, 256, GEMM1_SMEM>>>(
        xnh, w1h + (size_t)D2 * DM, b1 + D2, nullptr,
        nullptr, vh, presp, ROWS, DM, DM);

    // 3) attention: split-KV main (ex2 softmax) + combine
    attn_v8_kernel<<<dim3(12, NH, BS), 256, ATT6_SMEM_BYTES>>>(qkh, qkl, vh, atth);
    attn_combine_kernel<<<128, 256>>>(atth);

    // 4) x1 = att @ W3 + b3 + x
    bgemm1_kernel<false,0><<<PERSIST_GRID, 256, GEMM1_SMEM>>>(
        atth, w3h, b3, x, x1, nullptr, nullptr, ROWS, DM, DM);

    // 5) LN2 -> fp16 single
    ln2_kernel<<<ROWS, 256>>>(x1, g2, be2, xn2h);

    // 6) h = gelu(xn2 @ W2 + b2) -> fp16 single
    bgemm1_kernel<true,2><<<PERSIST_GRID, 256, GEMM1_SMEM>>>(
        xn2h, w2h, b2, nullptr, nullptr, hh, nullptr, ROWS, D4, DM);

    // 7) out = h @ W4 + b4 + x1
    bgemm1_kernel<false,0><<<PERSIST_GRID, 256, GEMM1_SMEM>>>(
        hh, w4h, b4, x1, out, nullptr, nullptr, ROWS, DM, D4);
}

// round 17
// speedup vs baseline: 2.0015x; 1.0309x over previous
#include <cuda_runtime.h>
#include <cuda_bf16.h>
#include <cuda_fp16.h>
#include <math.h>

// ---------------- problem constants ----------------
#define BS   8
#define SEQ  1024
#define DM   768
#define NH   4
#define DH   192
#define ROWS (BS*SEQ)          // 8192
#define D3   (3*DM)            // 2304
#define D4   (4*DM)            // 3072
#define D2   (2*DM)            // 1536

#define XOUT_ELEMS   ((size_t)ROWS*DM)
#define PRES_ELEMS   ((size_t)BS*2*NH*SEQ*DH)

#define PERSIST_GRID 296       // 148 SMs x 2 CTA/SM

// ---------------- scratch (device globals) ---------------------------------
__device__ __align__(256) float g_x1 [ROWS*DM];

__device__ __align__(256) __half g_qkh[(size_t)ROWS*D2], g_qkl[(size_t)ROWS*D2];
__device__ __align__(256) __half g_vh [(size_t)ROWS*DM];
__device__ __align__(256) __half g_xnh [ROWS*DM],  g_xnl [ROWS*DM];
__device__ __align__(256) __half g_atth[ROWS*DM];
__device__ __align__(256) __half g_xn2h[ROWS*DM];
__device__ __align__(256) __half g_hh[(size_t)ROWS*D4];

// transposed weights: [N][K]
__device__ __align__(256) __half g_w1h[(size_t)D3*DM], g_w1l[(size_t)D2*DM];
__device__ __align__(256) __half g_w3h[(size_t)DM*DM];
__device__ __align__(256) __half g_w2h[(size_t)D4*DM];
__device__ __align__(256) __half g_w4h[(size_t)DM*D4];

// split-KV partials
__device__ __align__(256) float g_po[(size_t)2*128*128*192];
__device__ __align__(256) float g_pm[2*128*128];
__device__ __align__(256) float g_pl[2*128*128];

__device__ const int c_bi[12] = {7,6,3,5,7,2,4,6,5,1,4,0};
__device__ const int c_ch[12] = {1,1,-1,1,0,-1,1,0,0,-1,0,-1};

// ---------------- helpers ---------------------------------------------------
__device__ __forceinline__ void split2h(float x0, float x1, unsigned &hi, unsigned &lo) {
    __half h0 = __float2half_rn(x0);
    __half h1 = __float2half_rn(x1);
    __half l0 = __float2half_rn(x0 - __half2float(h0));
    __half l1 = __float2half_rn(x1 - __half2float(h1));
    hi = ((unsigned)__half_as_ushort(h1) << 16) | (unsigned)__half_as_ushort(h0);
    lo = ((unsigned)__half_as_ushort(l1) << 16) | (unsigned)__half_as_ushort(l0);
}

__device__ __forceinline__ unsigned packh(float x0, float x1) {
    __half h0 = __float2half_rn(x0);
    __half h1 = __float2half_rn(x1);
    return ((unsigned)__half_as_ushort(h1) << 16) | (unsigned)__half_as_ushort(h0);
}

__device__ __forceinline__ unsigned ex2h2(float x0, float x1) {
    unsigned hin = packh(x0, x1);
    unsigned r;
    asm("ex2.approx.f16x2 %0, %1;" : "=r"(r) : "r"(hin));
    return r;
}

__device__ __forceinline__ void mma_f16(float c[4], const unsigned a[4], const unsigned b[2]) {
    asm volatile(
        "mma.sync.aligned.m16n8k16.row.col.f32.f16.f16.f32 "
        "{%0,%1,%2,%3}, {%4,%5,%6,%7}, {%8,%9}, {%0,%1,%2,%3};\n"
        : "+f"(c[0]), "+f"(c[1]), "+f"(c[2]), "+f"(c[3])
        : "r"(a[0]), "r"(a[1]), "r"(a[2]), "r"(a[3]), "r"(b[0]), "r"(b[1]));
}

__device__ __forceinline__ void ldsm_x4(unsigned r[4], unsigned addr) {
    asm volatile("ldmatrix.sync.aligned.m8n8.x4.shared.b16 {%0,%1,%2,%3}, [%4];"
        : "=r"(r[0]), "=r"(r[1]), "=r"(r[2]), "=r"(r[3]) : "r"(addr));
}

__device__ __forceinline__ void ldsm_x4_t(unsigned &r0, unsigned &r1, unsigned &r2, unsigned &r3, unsigned saddr) {
    asm volatile("ldmatrix.sync.aligned.m8n8.x4.trans.shared.b16 {%0,%1,%2,%3}, [%4];"
        : "=r"(r0), "=r"(r1), "=r"(r2), "=r"(r3) : "r"(saddr));
}

#define CP16(dst, src) asm volatile("cp.async.cg.shared.global [%0], [%1], 16;\n" :: "r"(dst), "l"(src))
#define CP_COMMIT() asm volatile("cp.async.commit_group;\n" ::)
#define CP_WAIT0()  asm volatile("cp.async.wait_group 0;\n" ::)
#define CP_WAIT1()  asm volatile("cp.async.wait_group 1;\n" ::)

__device__ __forceinline__ float gelu_tanh_f(float x) {
    float x3 = x * x * x;
    float t  = tanhf(0.7978845608028654f * (x + 0.044715f * x3));
    return 0.5f * x * (1.0f + t);
}

// ---------------- fused prep: all weight transposes + LN1 -------------------
#define PREP_GRID 15104

__device__ __forceinline__ void wsplit_body(
    const float* __restrict__ W, __half* __restrict__ Th, __half* __restrict__ Tl,
    int K, int Nsrc, int idx, int nb, float t[32][33])
{
    int n0 = (idx % nb) * 32, k0 = (idx / nb) * 32;
    int tx = threadIdx.x & 31, ty = threadIdx.x >> 5;
    #pragma unroll
    for (int j = 0; j < 4; j++)
        t[ty + 8 * j][tx] = W[(size_t)(k0 + ty + 8 * j) * Nsrc + n0 + tx];
    __syncthreads();
    #pragma unroll
    for (int j = 0; j < 4; j++) {
        float v = t[tx][ty + 8 * j];
        __half hi = __float2half_rn(v);
        size_t o = (size_t)(n0 + ty + 8 * j) * K + k0 + tx;
        Th[o] = hi;
        if (Tl) Tl[o] = __float2half_rn(v - __half2float(hi));
    }
}

__global__ __launch_bounds__(256) void prep_kernel(
    const float* __restrict__ W1, const float* __restrict__ W3,
    const float* __restrict__ W2, const float* __restrict__ W4,
    const float* __restrict__ x, const float* __restrict__ gamma,
    const float* __restrict__ beta)
{
    __shared__ float t[32][33];
    __shared__ float ss[8], ssq[8];
    __shared__ float mu_s, rs_s;
    const int bid = blockIdx.x;
    const int tid = threadIdx.x;

    if (bid < 1152) {
        wsplit_body(W1, g_w1h, g_w1l, DM, D3, bid, 48, t);
    } else if (bid < 1728) {
        wsplit_body(W1 + D2, g_w1h + (size_t)D2 * DM, nullptr, DM, D3, bid - 1152, 24, t);
    } else if (bid < 2304) {
        wsplit_body(W3, g_w3h, nullptr, DM, DM, bid - 1728, 24, t);
    } else if (bid < 4608) {
        wsplit_body(W2, g_w2h, nullptr, DM, D4, bid - 2304, 96, t);
    } else if (bid < 6912) {
        wsplit_body(W4, g_w4h, nullptr, D4, DM, bid - 4608, 24, t);
    } else {
        const int row = bid - 6912;
        const float* xr = x + (size_t)row * DM;
        float v0 = xr[tid], v1 = xr[tid + 256], v2 = xr[tid + 512];
        float s  = v0 + v1 + v2;
        float sq = v0*v0 + v1*v1 + v2*v2;
        #pragma unroll
        for (int o = 16; o > 0; o >>= 1) {
            s  += __shfl_xor_sync(0xffffffffu, s,  o);
            sq += __shfl_xor_sync(0xffffffffu, sq, o);
        }
        int w = tid >> 5, l = tid & 31;
        if (l == 0) { ss[w] = s; ssq[w] = sq; }
        __syncthreads();
        if (tid == 0) {
            float S = 0.f, SQ = 0.f;
            #pragma unroll
            for (int i = 0; i < 8; i++) { S += ss[i]; SQ += ssq[i]; }
            float mu = S * (1.0f / DM);
            float var = SQ * (1.0f / DM) - mu * mu;
            mu_s = mu;
            rs_s = rsqrtf(var + 1e-3f);
        }
        __syncthreads();
        float mu = mu_s, rs = rs_s;
        size_t ro = (size_t)row * DM;
        #pragma unroll
        for (int q = 0; q < 3; q++) {
            int c = tid + q * 256;
            float v = (q == 0 ? v0 : (q == 1 ? v1 : v2));
            float y = (v - mu) * rs * gamma[c] + beta[c];
            __half hi = __float2half_rn(y);
            g_xnh[ro + c] = hi;
            g_xnl[ro + c] = __float2half_rn(y - __half2float(hi));
        }
    }
}

// ---------------- LayerNorm -> fp16 single (LN2) -----------------------------
__global__ __launch_bounds__(256) void ln2_kernel(
    const float* __restrict__ x, const float* __restrict__ gamma,
    const float* __restrict__ beta, __half* __restrict__ oh)
{
    int row = blockIdx.x;
    int tid = threadIdx.x;
    const float* xr = x + (size_t)row * DM;
    float v0 = xr[tid], v1 = xr[tid + 256], v2 = xr[tid + 512];
    float s  = v0 + v1 + v2;
    float sq = v0*v0 + v1*v1 + v2*v2;
    #pragma unroll
    for (int o = 16; o > 0; o >>= 1) {
        s  += __shfl_xor_sync(0xffffffffu, s,  o);
        sq += __shfl_xor_sync(0xffffffffu, sq, o);
    }
    __shared__ float ss[8], ssq[8];
    __shared__ float mu_s, rs_s;
    int w = tid >> 5, l = tid & 31;
    if (l == 0) { ss[w] = s; ssq[w] = sq; }
    __syncthreads();
    if (tid == 0) {
        float S = 0.f, SQ = 0.f;
        #pragma unroll
        for (int i = 0; i < 8; i++) { S += ss[i]; SQ += ssq[i]; }
        float mu = S * (1.0f / DM);
        float var = SQ * (1.0f / DM) - mu * mu;
        mu_s = mu;
        rs_s = rsqrtf(var + 1e-3f);
    }
    __syncthreads();
    float mu = mu_s, rs = rs_s;
    size_t ro = (size_t)row * DM;
    #pragma unroll
    for (int q = 0; q < 3; q++) {
        int c = tid + q * 256;
        float v = (q == 0 ? v0 : (q == 1 ? v1 : v2));
        float y = (v - mu) * rs * gamma[c] + beta[c];
        oh[ro + c] = __float2half_rn(y);
    }
}

// ---------------- GEMM f3: fp16 3-pass (A split, B split), persistent -------
#define SROW3 80
#define MAT3  (128*SROW3)
#define STG3  (4*MAT3)
#define GEMM3_SMEM (2*STG3)

__global__ __launch_bounds__(256, 2) void bgemm3f_kernel(
    const __half* __restrict__ Ah, const __half* __restrict__ Al,
    const __half* __restrict__ Bh, const __half* __restrict__ Bl,
    const float* __restrict__ bias,
    __half* __restrict__ Ch, __half* __restrict__ Cl,
    float* __restrict__ pres, int M, int N, int K)
{
    extern __shared__ unsigned char sm3[];
    const int tid = threadIdx.x;
    const int w = tid >> 5, l = tid & 31;
    const int wm = w & 1, wn = w >> 1;
    const int gid = l >> 2, tig = l & 3;
    const int T = K >> 5;
    const int nbx = N >> 7;
    const int ntile = (M >> 7) * nbx;

    const unsigned smem_base = (unsigned)__cvta_generic_to_shared(sm3);
    const int rl = l & 7, sel = l >> 3;
    const unsigned a_off = (unsigned)((rl + 8 * (sel & 1)) * SROW3 + 16 * (sel >> 1));
    const unsigned b_off = (unsigned)((rl + 8 * (sel >> 1)) * SROW3 + 16 * (sel & 1));

    for (int tile = blockIdx.x; tile < ntile; tile += gridDim.x) {
        const int by = tile / nbx, bx = tile % nbx;
        const __half* A0 = Ah + (size_t)(by * 128) * K;
        const __half* A1 = Al + (size_t)(by * 128) * K;
        const __half* B0 = Bh + (size_t)(bx * 128) * K;
        const __half* B1 = Bl + (size_t)(bx * 128) * K;

        float acc[4][4][4];
        #pragma unroll
        for (int i = 0; i < 4; i++)
            #pragma unroll
            for (int j = 0; j < 4; j++)
                #pragma unroll
                for (int c = 0; c < 4; c++) acc[i][j][c] = 0.f;

        auto issue = [&](int t) {
            unsigned sb = smem_base + (t & 1) * STG3;
            int k0 = t << 5;
            #pragma unroll
            for (int i = 0; i < 2; i++) {
                int chunk = tid + (i << 8);
                int r = chunk >> 2, c = chunk & 3;
                unsigned doff = (unsigned)(r * SROW3 + c * 16);
                size_t goff = (size_t)r * K + k0 + c * 8;
                CP16(sb + doff,            (const void*)(A0 + goff));
                CP16(sb + MAT3 + doff,     (const void*)(A1 + goff));
                CP16(sb + 2 * MAT3 + doff, (const void*)(B0 + goff));
                CP16(sb + 3 * MAT3 + doff, (const void*)(B1 + goff));
            }
            CP_COMMIT();
        };

        __syncthreads();
        issue(0);
        issue(1);

        for (int t = 0; t < T; t++) {
            if (t + 1 < T) CP_WAIT1(); else CP_WAIT0();
            __syncthreads();

            unsigned sb = smem_base + (t & 1) * STG3;
            #pragma unroll
            for (int ks = 0; ks < 2; ks++) {
                unsigned bh[2][4], bl4[2][4];
                #pragma unroll
                for (int p = 0; p < 2; p++) {
                    unsigned bd = sb + 2 * MAT3 + (unsigned)((wn * 32 + p * 16) * SROW3 + ks * 32) + b_off;
                    ldsm_x4(bh[p], bd);
                    ldsm_x4(bl4[p], bd + MAT3);
                }
                #pragma unroll
                for (int am = 0; am < 4; am++) {
                    unsigned ah[4], al4[4];
                    unsigned ad = sb + (unsigned)((wm * 64 + am * 16) * SROW3 + ks * 32) + a_off;
                    ldsm_x4(ah, ad);
                    ldsm_x4(al4, ad + MAT3);
                    #pragma unroll
                    for (int an = 0; an < 4; an++) {
                        const int p = an >> 1, q = (an & 1) * 2;
                        unsigned bfh[2] = { bh[p][q], bh[p][q + 1] };
                        unsigned bfl[2] = { bl4[p][q], bl4[p][q + 1] };
                        mma_f16(acc[am][an], ah, bfh);
                        mma_f16(acc[am][an], al4, bfh);
                        mma_f16(acc[am][an], ah, bfl);
                    }
                }
            }
            __syncthreads();
            if (t + 2 < T) issue(t + 2);
        }

        #pragma unroll
        for (int am = 0; am < 4; am++) {
            int r0 = by * 128 + wm * 64 + am * 16 + gid;
            int r1 = r0 + 8;
            #pragma unroll
            for (int an = 0; an < 4; an++) {
                int n0 = bx * 128 + wn * 32 + an * 8 + 2 * tig;
                float bv0 = bias[n0], bv1 = bias[n0 + 1];
                size_t o0 = (size_t)r0 * N + n0;
                size_t o1 = (size_t)r1 * N + n0;
                float v0 = acc[am][an][0] + bv0;
                float v1 = acc[am][an][1] + bv1;
                float v2 = acc[am][an][2] + bv0;
                float v3 = acc[am][an][3] + bv1;
                unsigned hw, lw;
                split2h(v0, v1, hw, lw);
                *reinterpret_cast<unsigned*>(Ch + o0) = hw;
                *reinterpret_cast<unsigned*>(Cl + o0) = lw;
                split2h(v2, v3, hw, lw);
                *reinterpret_cast<unsigned*>(Ch + o1) = hw;
                *reinterpret_cast<unsigned*>(Cl + o1) = lw;
                if (pres && n0 >= DM) {
                    int local = n0 - DM;
                    int hh = local / DH, dd = local % DH;
                    int b0 = r0 >> 10, s0 = r0 & 1023;
                    int b1 = r1 >> 10, s1 = r1 & 1023;
                    size_t p0 = (((size_t)(b0 * 2) * NH + hh) * SEQ + s0) * DH + dd;
                    size_t p1 = (((size_t)(b1 * 2) * NH + hh) * SEQ + s1) * DH + dd;
                    *reinterpret_cast<float2*>(pres + p0) = make_float2(v0, v1);
                    *reinterpret_cast<float2*>(pres + p1) = make_float2(v2, v3);
                }
            }
        }
    }
}

// ---------------- GEMM v1: fp16 1-pass, persistent, 3-buffer single-sync ----
#define STG1  (2*MAT3)
#define GEMM1_SMEM (3*STG1)

template<bool GELU, int OMODE>   // 0 = float out (+res), 2 = fp16 out (+V-present)
__global__ __launch_bounds__(256, 2) void bgemm1_kernel(
    const __half* __restrict__ Ah, const __half* __restrict__ Bh,
    const float* __restrict__ bias, const float* __restrict__ res,
    float* __restrict__ C, __half* __restrict__ Ch,
    float* __restrict__ pres, int M, int N, int K)
{
    extern __shared__ unsigned char sm1[];
    const int tid = threadIdx.x;
    const int w = tid >> 5, l = tid & 31;
    const int wm = w & 1, wn = w >> 1;
    const int gid = l >> 2, tig = l & 3;
    const int T = K >> 5;
    const int nbx = N >> 7;
    const int ntile = (M >> 7) * nbx;

    const unsigned smem_base = (unsigned)__cvta_generic_to_shared(sm1);
    const int rl = l & 7, sel = l >> 3;
    const unsigned a_off = (unsigned)((rl + 8 * (sel & 1)) * SROW3 + 16 * (sel >> 1));
    const unsigned b_off = (unsigned)((rl + 8 * (sel >> 1)) * SROW3 + 16 * (sel & 1));

    for (int tile = blockIdx.x; tile < ntile; tile += gridDim.x) {
        const int by = tile / nbx, bx = tile % nbx;
        const __half* A0 = Ah + (size_t)(by * 128) * K;
        const __half* B0 = Bh + (size_t)(bx * 128) * K;

        float acc[4][4][4];
        #pragma unroll
        for (int i = 0; i < 4; i++)
            #pragma unroll
            for (int j = 0; j < 4; j++)
                #pragma unroll
                for (int c = 0; c < 4; c++) acc[i][j][c] = 0.f;

        auto issue = [&](int t) {
            int buf = t % 3;
            unsigned sb = smem_base + buf * STG1;
            int k0 = t << 5;
            #pragma unroll
            for (int i = 0; i < 2; i++) {
                int chunk = tid + (i << 8);
                int r = chunk >> 2, c = chunk & 3;
                unsigned doff = (unsigned)(r * SROW3 + c * 16);
                size_t goff = (size_t)r * K + k0 + c * 8;
                CP16(sb + doff,        (const void*)(A0 + goff));
                CP16(sb + MAT3 + doff, (const void*)(B0 + goff));
            }
            CP_COMMIT();
        };

        // Safe without cross-tile sync: buffers 0 and 1 were last computed
        // >= 2 iteration-syncs ago (all warps provably done with them).
        issue(0);
        issue(1);

        for (int t = 0; t < T; t++) {
            if (t + 1 < T) CP_WAIT1(); else CP_WAIT0();
            __syncthreads();            // ensures compute(t-1) done on all warps
            if (t + 2 < T) issue(t + 2);  // buffer (t+2)%3 == (t-1)%3, now free

            unsigned sb = smem_base + (t % 3) * STG1;
            #pragma unroll
            for (int ks = 0; ks < 2; ks++) {
                unsigned bh[2][4];
                #pragma unroll
                for (int p = 0; p < 2; p++) {
                    unsigned bd = sb + MAT3 + (unsigned)((wn * 32 + p * 16) * SROW3 + ks * 32) + b_off;
                    ldsm_x4(bh[p], bd);
                }
                #pragma unroll
                for (int am = 0; am < 4; am++) {
                    unsigned ah[4];
                    unsigned ad = sb + (unsigned)((wm * 64 + am * 16) * SROW3 + ks * 32) + a_off;
                    ldsm_x4(ah, ad);
                    #pragma unroll
                    for (int an = 0; an < 4; an++) {
                        const int p = an >> 1, q = (an & 1) * 2;
                        unsigned bfh[2] = { bh[p][q], bh[p][q + 1] };
                        mma_f16(acc[am][an], ah, bfh);
                    }
                }
            }
        }

        #pragma unroll
        for (int am = 0; am < 4; am++) {
            int r0 = by * 128 + wm * 64 + am * 16 + gid;
            int r1 = r0 + 8;
            #pragma unroll
            for (int an = 0; an < 4; an++) {
                int n0 = bx * 128 + wn * 32 + an * 8 + 2 * tig;
                float bv0 = bias[n0], bv1 = bias[n0 + 1];
                size_t o0 = (size_t)r0 * N + n0;
                size_t o1 = (size_t)r1 * N + n0;
                float v0 = acc[am][an][0] + bv0;
                float v1 = acc[am][an][1] + bv1;
                float v2 = acc[am][an][2] + bv0;
                float v3 = acc[am][an][3] + bv1;
                if (res) {
                    v0 += res[o0]; v1 += res[o0 + 1];
                    v2 += res[o1]; v3 += res[o1 + 1];
                }
                if (GELU) {
                    v0 = gelu_tanh_f(v0); v1 = gelu_tanh_f(v1);
                    v2 = gelu_tanh_f(v2); v3 = gelu_tanh_f(v3);
                }
                if (OMODE == 0) {
                    *reinterpret_cast<float2*>(C + o0) = make_float2(v0, v1);
                    *reinterpret_cast<float2*>(C + o1) = make_float2(v2, v3);
                } else {
                    *reinterpret_cast<unsigned*>(Ch + o0) = packh(v0, v1);
                    *reinterpret_cast<unsigned*>(Ch + o1) = packh(v2, v3);
                    if (pres) {
                        int hh = n0 / DH, dd = n0 % DH;
                        int b0 = r0 >> 10, s0 = r0 & 1023;
                        int b1 = r1 >> 10, s1 = r1 & 1023;
                        size_t p0 = (((size_t)(b0 * 2 + 1) * NH + hh) * SEQ + s0) * DH + dd;
                        size_t p1 = (((size_t)(b1 * 2 + 1) * NH + hh) * SEQ + s1) * DH + dd;
                        *reinterpret_cast<float2*>(pres + p0) = make_float2(v0, v1);
                        *reinterpret_cast<float2*>(pres + p1) = make_float2(v2, v3);
                    }
                }
            }
        }
    }
}

// ---------------- attention v8: fp16, split-KV, ex2.f16x2 softmax -----------
#define A6_ST 100
#define A6_QH 0
#define A6_QL 12800
#define A6_KH 25600
#define A6_KL 32000
#define A6_VH 38400
#define ATT6_SMEM_BYTES (44800*4)

__global__ __launch_bounds__(256, 1) void attn_v8_kernel(
    const __half* __restrict__ qkh, const __half* __restrict__ qkl,
    const __half* __restrict__ vbuf,
    __half* __restrict__ atth)
{
    extern __shared__ unsigned smu[];
    const int type = blockIdx.x;
    const int bi = c_bi[type];
    const int ch = c_ch[type];
    const int h  = blockIdx.y;
    const int b  = blockIdx.z;
    const int tid = threadIdx.x;
    const int w = tid >> 5, l = tid & 31;
    const int gid = l >> 2, tig = l & 3;

    const int j0 = (ch == 1) ? bi : 0;
    const int j1 = (ch == 0) ? bi : 2 * bi + 2;

    const float scale2 = 13.856406460551018f * 1.4426950408889634f;
    const unsigned sbase = (unsigned)__cvta_generic_to_shared(smu);

    const int kcol = DM + h * DH;
    const int vcol = h * DH;

    auto issue_k = [&](int j) {
        const size_t row0 = (size_t)(b * SEQ + j * 64);
        #pragma unroll
        for (int i = 0; i < 6; i++) {
            int c = tid + (i << 8);
            int r = c / 24, cc2 = c % 24;
            unsigned doff = (unsigned)((r * A6_ST + cc2 * 4) * 4);
            size_t gk = (row0 + r) * D2 + kcol + cc2 * 8;
            CP16(sbase + A6_KH * 4 + doff, (const void*)(qkh + gk));
            CP16(sbase + A6_KL * 4 + doff, (const void*)(qkl + gk));
        }
        CP_COMMIT();
    };
    auto issue_v = [&](int j) {
        const size_t row0 = (size_t)(b * SEQ + j * 64);
        #pragma unroll
        for (int i = 0; i < 6; i++) {
            int c = tid + (i << 8);
            int r = c / 24, cc2 = c % 24;
            unsigned doff = (unsigned)((r * A6_ST + cc2 * 4) * 4);
            size_t gv = (row0 + r) * DM + vcol + cc2 * 8;
            CP16(sbase + A6_VH * 4 + doff, (const void*)(vbuf + gv));
        }
        CP_COMMIT();
    };

    {
        const size_t row0 = (size_t)(b * SEQ + bi * 128);
        const int qcol = h * DH;
        #pragma unroll
        for (int i = 0; i < 12; i++) {
            int c = tid + (i << 8);
            int r = c / 24, cc2 = c % 24;
            unsigned doff = (unsigned)((r * A6_ST + cc2 * 4) * 4);
            size_t goff = (row0 + r) * D2 + qcol + cc2 * 8;
            CP16(sbase + A6_QH * 4 + doff, (const void*)(qkh + goff));
            CP16(sbase + A6_QL * 4 + doff, (const void*)(qkl + goff));
        }
        CP_COMMIT();
    }
    issue_k(j0);
    issue_v(j0);

    float m0 = -1e30f, m1 = -1e30f, l0 = 0.f, l1 = 0.f;
    float accO[24][4];
    #pragma unroll
    for (int i = 0; i < 24; i++)
        #pragma unroll
        for (int c = 0; c < 4; c++) accO[i][c] = 0.f;

    const int lm_rwi  = (l & 7) + ((l >> 3) & 1) * 8;
    const int lm_ncol = (l >> 4) * 8;
    const unsigned vh_base = sbase + A6_VH * 4;

    const int qg0 = bi * 128 + w * 16 + gid;
    const int qg1 = qg0 + 8;

    for (int j = j0; j < j1; j++) {
        CP_WAIT1();
        __syncthreads();

        const bool diag = (j >= 2 * bi);
        const bool wskip = diag && (64 * j >= bi * 128 + w * 16 + 16);

        const unsigned* Qh = smu + A6_QH;
        const unsigned* Ql = smu + A6_QL;
        const unsigned* Kh = smu + A6_KH;
        const unsigned* Kl = smu + A6_KL;

        unsigned pha[4][4];
        float corr0 = 1.f, corr1 = 1.f;

        if (!wskip) {
            float accS[8][4];
            #pragma unroll
            for (int i = 0; i < 8; i++)
                #pragma unroll
                for (int c = 0; c < 4; c++) accS[i][c] = 0.f;

            #pragma unroll
            for (int ks = 0; ks < 12; ks++) {
                int kp = ks * 8;
                unsigned ah[4], al[4];
                int a0 = (w * 16 + gid) * A6_ST + kp + tig;
                int a1 = a0 + 8 * A6_ST;
                ah[0] = Qh[a0]; ah[1] = Qh[a1]; ah[2] = Qh[a0 + 4]; ah[3] = Qh[a1 + 4];
                al[0] = Ql[a0]; al[1] = Ql[a1]; al[2] = Ql[a0 + 4]; al[3] = Ql[a1 + 4];
                #pragma unroll
                for (int nt = 0; nt < 8; nt++) {
                    int bb = (nt * 8 + gid) * A6_ST + kp + tig;
                    unsigned bh[2], bl2[2];
                    bh[0]  = Kh[bb]; bh[1]  = Kh[bb + 4];
                    bl2[0] = Kl[bb]; bl2[1] = Kl[bb + 4];
                    mma_f16(accS[nt], ah, bh);
                    mma_f16(accS[nt], al, bh);
                    mma_f16(accS[nt], ah, bl2);
                }
            }

            float mx0 = -1e30f, mx1 = -1e30f;
            #pragma unroll
            for (int nt = 0; nt < 8; nt++) {
                int kg = j * 64 + nt * 8 + 2 * tig;
                float v0 = accS[nt][0] * scale2;
                float v1 = accS[nt][1] * scale2;
                float v2 = accS[nt][2] * scale2;
                float v3 = accS[nt][3] * scale2;
                if (diag) {
                    if (kg     > qg0) v0 = -1e30f;
                    if (kg + 1 > qg0) v1 = -1e30f;
                    if (kg     > qg1) v2 = -1e30f;
                    if (kg + 1 > qg1) v3 = -1e30f;
                }
                accS[nt][0] = v0; accS[nt][1] = v1;
                accS[nt][2] = v2; accS[nt][3] = v3;
                mx0 = fmaxf(mx0, fmaxf(v0, v1));
                mx1 = fmaxf(mx1, fmaxf(v2, v3));
            }
            mx0 = fmaxf(mx0, __shfl_xor_sync(0xffffffffu, mx0, 1));
            mx0 = fmaxf(mx0, __shfl_xor_sync(0xffffffffu, mx0, 2));
            mx1 = fmaxf(mx1, __shfl_xor_sync(0xffffffffu, mx1, 1));
            mx1 = fmaxf(mx1, __shfl_xor_sync(0xffffffffu, mx1, 2));
            float mn0 = fmaxf(m0, mx0), mn1 = fmaxf(m1, mx1);
            corr0 = exp2f(m0 - mn0); corr1 = exp2f(m1 - mn1);

            float sum0 = 0.f, sum1 = 0.f;
            #pragma unroll
            for (int nt = 0; nt < 8; nt++) {
                unsigned u01 = ex2h2(accS[nt][0] - mn0, accS[nt][1] - mn0);
                unsigned u23 = ex2h2(accS[nt][2] - mn1, accS[nt][3] - mn1);
                const int ks = nt >> 1;
                const int s0 = (nt & 1) * 2;
                pha[ks][s0]     = u01;
                pha[ks][s0 + 1] = u23;
                float2 f01 = __half22float2(*reinterpret_cast<__half2*>(&u01));
                float2 f23 = __half22float2(*reinterpret_cast<__half2*>(&u23));
                sum0 += f01.x + f01.y;
                sum1 += f23.x + f23.y;
            }
            sum0 += __shfl_xor_sync(0xffffffffu, sum0, 1);
            sum0 += __shfl_xor_sync(0xffffffffu, sum0, 2);
            sum1 += __shfl_xor_sync(0xffffffffu, sum1, 1);
            sum1 += __shfl_xor_sync(0xffffffffu, sum1, 2);
            l0 = l0 * corr0 + sum0;  m0 = mn0;
            l1 = l1 * corr1 + sum1;  m1 = mn1;
        }

        CP_WAIT0();
        __syncthreads();
        if (j + 1 < j1) issue_k(j + 1);

        if (!wskip) {
            #pragma unroll
            for (int nt = 0; nt < 24; nt++) {
                accO[nt][0] *= corr0; accO[nt][1] *= corr0;
                accO[nt][2] *= corr1; accO[nt][3] *= corr1;
            }
            #pragma unroll
            for (int ks = 0; ks < 4; ks++) {
                unsigned rowoff = (unsigned)((ks * 16 + lm_rwi) * A6_ST) * 4u;
                #pragma unroll
                for (int g = 0; g < 12; g++) {
                    unsigned coloff = (unsigned)(g * 8 + lm_ncol / 2) * 4u;
                    unsigned bh0, bh1, bh2, bh3;
                    ldsm_x4_t(bh0, bh1, bh2, bh3, vh_base + rowoff + coloff);
                    unsigned bfh[2];
                    bfh[0] = bh0; bfh[1] = bh1;
                    mma_f16(accO[2 * g],     pha[ks], bfh);
                    bfh[0] = bh2; bfh[1] = bh3;
                    mma_f16(accO[2 * g + 1], pha[ks], bfh);
                }
            }
        }

        __syncthreads();
        if (j + 1 < j1) issue_v(j + 1);
    }

    if (ch < 0) {
        float li0 = 1.0f / l0, li1 = 1.0f / l1;
        int row0 = b * SEQ + bi * 128 + w * 16 + gid;
        #pragma unroll
        for (int nt = 0; nt < 24; nt++) {
            int col = h * DH + nt * 8 + 2 * tig;
            size_t o0 = (size_t)row0 * DM + col;
            size_t o1 = (size_t)(row0 + 8) * DM + col;
            *reinterpret_cast<unsigned*>(atth + o0) = packh(accO[nt][0] * li0, accO[nt][1] * li0);
            *reinterpret_cast<unsigned*>(atth + o1) = packh(accO[nt][2] * li1, accO[nt][3] * li1);
        }
    } else {
        const int pidx = ((b * NH + h) << 2) + (bi - 4);
        float* po = g_po + ((size_t)ch * 128 + pidx) * (128 * 192);
        const int r0 = w * 16 + gid, r1 = r0 + 8;
        #pragma unroll
        for (int nt = 0; nt < 24; nt++) {
            int col = nt * 8 + 2 * tig;
            *reinterpret_cast<float2*>(po + r0 * 192 + col) = make_float2(accO[nt][0], accO[nt][1]);
            *reinterpret_cast<float2*>(po + r1 * 192 + col) = make_float2(accO[nt][2], accO[nt][3]);
        }
        if (tig == 0) {
            int mlb = (ch * 128 + pidx) * 128;
            g_pm[mlb + r0] = m0; g_pl[mlb + r0] = l0;
            g_pm[mlb + r1] = m1; g_pl[mlb + r1] = l1;
        }
    }
}

// ---------------- split-KV combine (m in log2 domain) ------------------------
__global__ __launch_bounds__(256) void attn_combine_kernel(__half* __restrict__ atth)
{
    const int pidx = blockIdx.x;
    const int b  = pidx >> 4;
    const int h  = (pidx >> 2) & 3;
    const int bi = 4 + (pidx & 3);
    const int r  = threadIdx.x >> 1;
    const int c0 = (threadIdx.x & 1) * 96;

    const float* po0 = g_po + ((size_t)0 * 128 + pidx) * (128 * 192) + r * 192 + c0;
    const float* po1 = g_po + ((size_t)1 * 128 + pidx) * (128 * 192) + r * 192 + c0;
    const int mlb0 = (0 * 128 + pidx) * 128 + r;
    const int mlb1 = (1 * 128 + pidx) * 128 + r;
    float m0 = g_pm[mlb0], l0 = g_pl[mlb0];
    float m1 = g_pm[mlb1], l1 = g_pl[mlb1];
    float m = fmaxf(m0, m1);
    float e0 = exp2f(m0 - m), e1 = exp2f(m1 - m);
    float linv = 1.0f / (e0 * l0 + e1 * l1);

    size_t go = (size_t)(b * SEQ + bi * 128 + r) * DM + h * DH + c0;
    #pragma unroll
    for (int c = 0; c < 96; c += 2) {
        float v0 = (e0 * po0[c]     + e1 * po1[c])     * linv;
        float v1 = (e0 * po0[c + 1] + e1 * po1[c + 1]) * linv;
        *reinterpret_cast<unsigned*>(atth + go + c) = packh(v0, v1);
    }
}

// ---------------- launch -----------------------------------------------
extern "C" void kernel_launch(void* const* d_in, const int* in_sizes, int n_in,
                              void* d_out, int out_size)
{
    const float* x   = (const float*)d_in[0];
    const float* W1  = (const float*)d_in[2];
    const float* b1  = (const float*)d_in[3];
    const float* W3  = (const float*)d_in[4];
    const float* b3  = (const float*)d_in[5];
    const float* W2  = (const float*)d_in[6];
    const float* b2  = (const float*)d_in[7];
    const float* W4  = (const float*)d_in[8];
    const float* b4  = (const float*)d_in[9];
    const float* g1  = (const float*)d_in[10];
    const float* be1 = (const float*)d_in[11];
    const float* g2  = (const float*)d_in[12];
    const float* be2 = (const float*)d_in[13];
    float* out = (float*)d_out;

    float *x1;
    cudaGetSymbolAddress((void**)&x1, g_x1);
    __half *qkh, *qkl, *vh, *xnh, *xnl, *atth, *xn2h, *hh;
    __half *w1h, *w1l, *w3h, *w2h, *w4h;
    cudaGetSymbolAddress((void**)&qkh,  g_qkh);  cudaGetSymbolAddress((void**)&qkl,  g_qkl);
    cudaGetSymbolAddress((void**)&vh,   g_vh);
    cudaGetSymbolAddress((void**)&xnh,  g_xnh);  cudaGetSymbolAddress((void**)&xnl,  g_xnl);
    cudaGetSymbolAddress((void**)&atth, g_atth);
    cudaGetSymbolAddress((void**)&xn2h, g_xn2h);
    cudaGetSymbolAddress((void**)&hh,   g_hh);
    cudaGetSymbolAddress((void**)&w1h,  g_w1h);  cudaGetSymbolAddress((void**)&w1l,  g_w1l);
    cudaGetSymbolAddress((void**)&w3h,  g_w3h);
    cudaGetSymbolAddress((void**)&w2h,  g_w2h);
    cudaGetSymbolAddress((void**)&w4h,  g_w4h);

    cudaFuncSetAttribute(attn_v8_kernel,
                         cudaFuncAttributeMaxDynamicSharedMemorySize, ATT6_SMEM_BYTES);
    cudaFuncSetAttribute(bgemm3f_kernel,
                         cudaFuncAttributeMaxDynamicSharedMemorySize, GEMM3_SMEM);
    cudaFuncSetAttribute(bgemm1_kernel<false,0>,
                         cudaFuncAttributeMaxDynamicSharedMemorySize, GEMM1_SMEM);
    cudaFuncSetAttribute(bgemm1_kernel<true,2>,
                         cudaFuncAttributeMaxDynamicSharedMemorySize, GEMM1_SMEM);
    cudaFuncSetAttribute(bgemm1_kernel<false,2>,
                         cudaFuncAttributeMaxDynamicSharedMemorySize, GEMM1_SMEM);

    float* pres = out + XOUT_ELEMS;
    bool has_present = ((size_t)out_size >= XOUT_ELEMS + PRES_ELEMS);
    float* presp = has_present ? pres : nullptr;

    // 0+1) fused prep
    prep_kernel<<<PREP_GRID, 256>>>(W1, W3, W2, W4, x, g1, be1);

    // 2a) qk (fp16 3-pass, persistent) -> split fp16 (+ K present)
    bgemm3f_kernel<<<PERSIST_GRID, 256, GEMM3_SMEM>>>(
        xnh, xnl, w1h, w1l, b1, qkh, qkl, presp, ROWS, D2, DM);

    // 2b) v (fp16 1-pass, persistent, single-sync) -> fp16 (+ V present)
    bgemm1_kernel<false,2><<<PERSIST_GRID, 256, GEMM1_SMEM>>>(
        xnh, w1h + (size_t)D2 * DM, b1 + D2, nullptr,
        nullptr, vh, presp, ROWS, DM, DM);

    // 3) attention: split-KV main + combine
    attn_v8_kernel<<<dim3(12, NH, BS), 256, ATT6_SMEM_BYTES>>>(qkh, qkl, vh, atth);
    attn_combine_kernel<<<128, 256>>>(atth);

    // 4) x1 = att @ W3 + b3 + x
    bgemm1_kernel<false,0><<<PERSIST_GRID, 256, GEMM1_SMEM>>>(
        atth, w3h, b3, x, x1, nullptr, nullptr, ROWS, DM, DM);

    // 5) LN2 -> fp16 single
    ln2_kernel<<<ROWS, 256>>>(x1, g2, be2, xn2h);

    // 6) h = gelu(xn2 @ W2 + b2) -> fp16 single
    bgemm1_kernel<true,2><<<PERSIST_GRID, 256, GEMM1_SMEM>>>(
        xn2h, w2h, b2, nullptr, nullptr, hh, nullptr, ROWS, D4, DM);

    // 7) out = h @ W4 + b4 + x1
    bgemm1_kernel<false,0><<<PERSIST_GRID, 256, GEMM1_SMEM>>>(
        hh, w4h, b4, x1, out, nullptr, nullptr, ROWS, DM, D4);
}